// round 1
// baseline (speedup 1.0000x reference)
#include <cuda_runtime.h>
#include <math.h>

typedef unsigned long long ULL;

// ---------------- problem constants ----------------
#define BATCH   128
#define KDIM    49152      // 6144 * 8
#define NDIM    2048       // 256 * 8
#define KSPLIT  16
#define KCHUNK  (KDIM / KSPLIT)   // 3072

// ---------------- scratch (device globals; no allocation allowed) ----------
__device__ float g_xT[BATCH * KDIM];              // 25.2 MB transposed activations
__device__ float g_part[KSPLIT * BATCH * NDIM];   // 16 MB split-K partials
__device__ float g_W12[NDIM * 2];                 // collapsed li1_w @ li2_w
__device__ float g_ob[2];                         // collapsed output bias

// ---------------- packed f32x2 helpers (Blackwell FFMA2 path) ----------------
__device__ __forceinline__ ULL dup2(float b) {
    ULL r; asm("mov.b64 %0, {%1, %1};" : "=l"(r) : "f"(b)); return r;
}
__device__ __forceinline__ ULL pack2(float x, float y) {
    ULL r; asm("mov.b64 %0, {%1, %2};" : "=l"(r) : "f"(x), "f"(y)); return r;
}
__device__ __forceinline__ void fma2(ULL &c, ULL a, ULL b) {
    asm("fma.rn.f32x2 %0, %1, %2, %0;" : "+l"(c) : "l"(a), "l"(b));
}
__device__ __forceinline__ void unpack2(ULL c, float &lo, float &hi) {
    asm("mov.b64 {%0, %1}, %2;" : "=f"(lo), "=f"(hi) : "l"(c));
}

// ---------------- kernel 1: transpose x (B,8,6144) -> xT (B, 49152) ----------
// xT[b][i*8+j] = x[b][j][i]
__global__ void k_transpose(const float* __restrict__ x) {
    int idx = blockIdx.x * 256 + threadIdx.x;           // exact grid, no bounds
    int b = idx / KDIM;
    int o = idx - b * KDIM;
    g_xT[idx] = x[b * KDIM + (o & 7) * 6144 + (o >> 3)];
}

// ---------------- kernel 2: W12 = li1_w @ li2_w (2048x2), ob = li1_b@li2_w+li2_b
__global__ void k_w12(const float* __restrict__ li1_w, const float* __restrict__ li1_b,
                      const float* __restrict__ li2_w, const float* __restrict__ li2_b) {
    int j = blockIdx.x;            // 0..2048 (2048 = bias row)
    int t = threadIdx.x;
    __shared__ float red0[256];
    __shared__ float red1[256];
    const float* row = (j < NDIM) ? (li1_w + (size_t)j * 1000) : li1_b;
    float a0 = 0.f, a1 = 0.f;
    for (int p = t; p < 1000; p += 256) {
        float w = row[p];
        a0 += w * li2_w[2 * p];
        a1 += w * li2_w[2 * p + 1];
    }
    red0[t] = a0; red1[t] = a1;
    __syncthreads();
    for (int s = 128; s > 0; s >>= 1) {
        if (t < s) { red0[t] += red0[t + s]; red1[t] += red1[t + s]; }
        __syncthreads();
    }
    if (t == 0) {
        if (j < NDIM) { g_W12[2 * j] = red0[0]; g_W12[2 * j + 1] = red1[0]; }
        else          { g_ob[0] = red0[0] + li2_b[0]; g_ob[1] = red1[0] + li2_b[1]; }
    }
}

// ---------------- kernel 3: split-K GEMM  h_part = xT @ fc_w ----------------
// BM=128 (all of M), BN=64, BK=16. 128 threads, each owns 8(m, as 4 f32x2 pairs) x 8(n).
__global__ void __launch_bounds__(128) k_gemm(const float* __restrict__ fc_w) {
    __shared__ __align__(16) float As[16 * 132];   // [k][m], padded
    __shared__ __align__(16) float Bs[16 * 68];    // [k][n], padded

    int tid = threadIdx.x;
    int tx = tid & 7;          // n-group (0..7)
    int ty = tid >> 3;         // m-group (0..15)
    int nbase = blockIdx.x * 64;
    int s = blockIdx.y;
    int k0 = s * KCHUNK;

    ULL acc[4][8];
#pragma unroll
    for (int p = 0; p < 4; p++)
#pragma unroll
        for (int j = 0; j < 8; j++) acc[p][j] = 0ULL;

    for (int kt = 0; kt < KCHUNK / 16; ++kt) {
        int kb = k0 + kt * 16;
        // A tile: 128 x 16, transposed into As[k][m]
#pragma unroll
        for (int i = 0; i < 4; i++) {
            int idx = tid + i * 128;
            int row = idx >> 2, kq = idx & 3;
            float4 v = *reinterpret_cast<const float4*>(g_xT + row * KDIM + kb + kq * 4);
            As[(kq * 4 + 0) * 132 + row] = v.x;
            As[(kq * 4 + 1) * 132 + row] = v.y;
            As[(kq * 4 + 2) * 132 + row] = v.z;
            As[(kq * 4 + 3) * 132 + row] = v.w;
        }
        // B tile: 16 x 64
#pragma unroll
        for (int i = 0; i < 2; i++) {
            int idx = tid + i * 128;
            int row = idx >> 4, nq = idx & 15;
            float4 v = *reinterpret_cast<const float4*>(fc_w + (size_t)(kb + row) * NDIM + nbase + nq * 4);
            *reinterpret_cast<float4*>(Bs + row * 68 + nq * 4) = v;
        }
        __syncthreads();
#pragma unroll
        for (int kk = 0; kk < 16; kk++) {
            float4 a0 = *reinterpret_cast<const float4*>(As + kk * 132 + ty * 8);
            float4 a1 = *reinterpret_cast<const float4*>(As + kk * 132 + ty * 8 + 4);
            float4 b0 = *reinterpret_cast<const float4*>(Bs + kk * 68 + tx * 4);
            float4 b1 = *reinterpret_cast<const float4*>(Bs + kk * 68 + tx * 4 + 32);
            ULL a2_0 = pack2(a0.x, a0.y), a2_1 = pack2(a0.z, a0.w);
            ULL a2_2 = pack2(a1.x, a1.y), a2_3 = pack2(a1.z, a1.w);
            ULL bb[8];
            bb[0] = dup2(b0.x); bb[1] = dup2(b0.y); bb[2] = dup2(b0.z); bb[3] = dup2(b0.w);
            bb[4] = dup2(b1.x); bb[5] = dup2(b1.y); bb[6] = dup2(b1.z); bb[7] = dup2(b1.w);
#pragma unroll
            for (int j = 0; j < 8; j++) {
                fma2(acc[0][j], a2_0, bb[j]);
                fma2(acc[1][j], a2_1, bb[j]);
                fma2(acc[2][j], a2_2, bb[j]);
                fma2(acc[3][j], a2_3, bb[j]);
            }
        }
        __syncthreads();
    }
    float* outp = g_part + (size_t)s * BATCH * NDIM;
#pragma unroll
    for (int p = 0; p < 4; p++) {
        int m0 = ty * 8 + 2 * p;
#pragma unroll
        for (int j = 0; j < 8; j++) {
            int n = nbase + tx * 4 + (j < 4 ? j : 32 + j - 4);
            float lo, hi;
            unpack2(acc[p][j], lo, hi);
            outp[m0 * NDIM + n]       = lo;
            outp[(m0 + 1) * NDIM + n] = hi;
        }
    }
}

// ---------------- kernel 4: fused per-batch pipeline -------------------------
// One block per batch; thread l (0..255) owns sequence position l.
__global__ void __launch_bounds__(256) k_fuse(
    const float* __restrict__ fc_b,
    const float* __restrict__ ln1_s, const float* __restrict__ ln1_b,
    const float* __restrict__ ln2_s, const float* __restrict__ ln2_b,
    const float* __restrict__ Wq, const float* __restrict__ Wk, const float* __restrict__ Wv,
    const float* __restrict__ Wg, const float* __restrict__ Wo,
    const float* __restrict__ gn_w, const float* __restrict__ gn_b,
    const float* __restrict__ w1, const float* __restrict__ b1,
    const float* __restrict__ w2, const float* __restrict__ b2,
    float* __restrict__ out)
{
    int b = blockIdx.x;
    int l = threadIdx.x;

    __shared__ float4 sK4[256];
    __shared__ float4 sV4[256][2];
    __shared__ float  sGPinv[256];
    __shared__ float  sRed[8][2];
    __shared__ float  swq[64], swk[64], swv[128], swg[128], swo[128];
    __shared__ float  sgnw[16], sgnb[16], sw1[64], sw2[64];
    __shared__ float  sb1[8], sb2[8], sl1s[8], sl1b[8], sl2s[8], sl2b[8];

    if (l < 64)  { swq[l] = Wq[l]; swk[l] = Wk[l]; sw1[l] = w1[l]; sw2[l] = w2[l]; }
    if (l < 128) { swv[l] = Wv[l]; swg[l] = Wg[l]; swo[l] = Wo[l]; }
    if (l < 16)  { sgnw[l] = gn_w[l]; sgnb[l] = gn_b[l]; }
    if (l < 8)   { sb1[l] = b1[l]; sb2[l] = b2[l];
                   sl1s[l] = ln1_s[l]; sl1b[l] = ln1_b[l];
                   sl2s[l] = ln2_s[l]; sl2b[l] = ln2_b[l]; }

    // reduce split-K partials + bias -> X row
    float X[8];
#pragma unroll
    for (int d = 0; d < 8; d++) {
        float h = fc_b[l * 8 + d];
#pragma unroll
        for (int s = 0; s < KSPLIT; s++)
            h += g_part[s * (BATCH * NDIM) + b * NDIM + l * 8 + d];
        X[d] = h;
    }
    __syncthreads();   // weights ready

    // LN1
    float Xn[8];
    {
        float mu = 0.f;
#pragma unroll
        for (int d = 0; d < 8; d++) mu += X[d];
        mu *= 0.125f;
        float var = 0.f;
#pragma unroll
        for (int d = 0; d < 8; d++) { float t = X[d] - mu; var += t * t; }
        var *= 0.125f;
        float inv = rsqrtf(var + 1e-5f);
#pragma unroll
        for (int d = 0; d < 8; d++) Xn[d] = (X[d] - mu) * inv * sl1s[d] + sl1b[d];
    }

    // xpos per-position factors (Dh=4: two rotary pairs)
    float fl = (float)l;
    float c0 = cosf(fl), s0 = sinf(fl);
    float c1 = cosf(fl * 0.01f), s1 = sinf(fl * 0.01f);
    // sv0 = 1.6/5.6, sv1 = 3.6/5.6 ; scale = sv^(l/512)
    float e0 = exp2f(fl * (-1.807354922f / 512.0f));
    float e1 = exp2f(fl * (-0.637429921f / 512.0f));
    float ie0 = 1.0f / e0, ie1 = 1.0f / e1;

    float yc[16];
    const float gammas[2] = { 1.0f - 1.0f / 32.0f, 1.0f - 1.0f / 512.0f };

#pragma unroll
    for (int hd = 0; hd < 2; ++hd) {
        float gamma = gammas[hd];
        const float* wq = swq + hd * 32;
        const float* wk = swk + hd * 32;
        const float* wv = swv + hd * 64;

        float q0 = 0, q1 = 0, q2 = 0, q3 = 0, k0 = 0, k1 = 0, k2 = 0, k3 = 0;
#pragma unroll
        for (int d = 0; d < 8; d++) {
            float xv = Xn[d];
            q0 += xv * wq[d * 4 + 0]; q1 += xv * wq[d * 4 + 1];
            q2 += xv * wq[d * 4 + 2]; q3 += xv * wq[d * 4 + 3];
            k0 += xv * wk[d * 4 + 0]; k1 += xv * wk[d * 4 + 1];
            k2 += xv * wk[d * 4 + 2]; k3 += xv * wk[d * 4 + 3];
        }
        // Q: scale = e ; K: downscale -> 1/e
        float Q0 = (q0 * c0 - q1 * s0) * e0;
        float Q1 = (q1 * c0 + q0 * s0) * e0;
        float Q2 = (q2 * c1 - q3 * s1) * e1;
        float Q3 = (q3 * c1 + q2 * s1) * e1;
        float K0 = (k0 * c0 - k1 * s0) * ie0;
        float K1 = (k1 * c0 + k0 * s0) * ie0;
        float K2 = (k2 * c1 - k3 * s1) * ie1;
        float K3 = (k3 * c1 + k2 * s1) * ie1;

        float V[8];
#pragma unroll
        for (int f = 0; f < 8; f++) {
            float a = 0.f;
#pragma unroll
            for (int d = 0; d < 8; d++) a += Xn[d] * wv[d * 8 + f];
            V[f] = a;
        }

        sK4[l] = make_float4(K0, K1, K2, K3);
        sV4[l][0] = make_float4(V[0], V[1], V[2], V[3]);
        sV4[l][1] = make_float4(V[4], V[5], V[6], V[7]);
        sGPinv[l] = powf(gamma, -fl);
        float gpn = powf(gamma, fl);
        __syncthreads();

        float a0 = 0, a1 = 0, a2 = 0, a3 = 0, a4 = 0, a5 = 0, a6 = 0, a7 = 0;
        for (int m = 0; m <= l; ++m) {
            float4 kv = sK4[m];
            float w = (Q0 * kv.x + Q1 * kv.y + Q2 * kv.z + Q3 * kv.w) * gpn * sGPinv[m];
            float4 v0 = sV4[m][0], v1 = sV4[m][1];
            a0 += w * v0.x; a1 += w * v0.y; a2 += w * v0.z; a3 += w * v0.w;
            a4 += w * v1.x; a5 += w * v1.y; a6 += w * v1.z; a7 += w * v1.w;
        }
        yc[hd * 8 + 0] = a0; yc[hd * 8 + 1] = a1; yc[hd * 8 + 2] = a2; yc[hd * 8 + 3] = a3;
        yc[hd * 8 + 4] = a4; yc[hd * 8 + 5] = a5; yc[hd * 8 + 6] = a6; yc[hd * 8 + 7] = a7;
        __syncthreads();   // protect sK4/sV4 before next head overwrites
    }

    // group norm (2 groups of 8) + gn_w/gn_b
    float gn[16];
#pragma unroll
    for (int g = 0; g < 2; g++) {
        float mu = 0.f;
#pragma unroll
        for (int jj = 0; jj < 8; jj++) mu += yc[g * 8 + jj];
        mu *= 0.125f;
        float var = 0.f;
#pragma unroll
        for (int jj = 0; jj < 8; jj++) { float t = yc[g * 8 + jj] - mu; var += t * t; }
        var *= 0.125f;
        float inv = rsqrtf(var + 1e-5f);
#pragma unroll
        for (int jj = 0; jj < 8; jj++)
            gn[g * 8 + jj] = (yc[g * 8 + jj] - mu) * inv * sgnw[g * 8 + jj] + sgnb[g * 8 + jj];
    }

    // gate = swish(Xn @ Wg); msr = (gate*gn) @ Wo
    float msr[8] = {0, 0, 0, 0, 0, 0, 0, 0};
#pragma unroll
    for (int j = 0; j < 16; j++) {
        float gt = 0.f;
#pragma unroll
        for (int d = 0; d < 8; d++) gt += Xn[d] * swg[d * 16 + j];
        gt = gt / (1.0f + expf(-gt));     // swish
        float val = gt * gn[j];
#pragma unroll
        for (int d = 0; d < 8; d++) msr[d] += val * swo[j * 8 + d];
    }

    float Y[8], Z[8];
#pragma unroll
    for (int d = 0; d < 8; d++) Y[d] = msr[d] + X[d];
    {
        float mu = 0.f;
#pragma unroll
        for (int d = 0; d < 8; d++) mu += Y[d];
        mu *= 0.125f;
        float var = 0.f;
#pragma unroll
        for (int d = 0; d < 8; d++) { float t = Y[d] - mu; var += t * t; }
        var *= 0.125f;
        float inv = rsqrtf(var + 1e-5f);
#pragma unroll
        for (int d = 0; d < 8; d++) Z[d] = (Y[d] - mu) * inv * sl2s[d] + sl2b[d];
    }

    float f1[8];
#pragma unroll
    for (int e = 0; e < 8; e++) {
        float a = sb1[e];
#pragma unroll
        for (int d = 0; d < 8; d++) a += Z[d] * sw1[d * 8 + e];
        f1[e] = 0.5f * a * (1.0f + erff(a * 0.70710678118654752f));   // exact gelu
    }

    float p0 = 0.f, p1 = 0.f;
#pragma unroll
    for (int d = 0; d < 8; d++) {
        float a = sb2[d];
#pragma unroll
        for (int e = 0; e < 8; e++) a += f1[e] * sw2[e * 8 + d];
        float xf = a + Y[d];
        p0 += xf * g_W12[(l * 8 + d) * 2];
        p1 += xf * g_W12[(l * 8 + d) * 2 + 1];
    }

    // deterministic block reduction -> out[b, 0..1]
#pragma unroll
    for (int off = 16; off > 0; off >>= 1) {
        p0 += __shfl_down_sync(0xffffffffu, p0, off);
        p1 += __shfl_down_sync(0xffffffffu, p1, off);
    }
    if ((l & 31) == 0) { sRed[l >> 5][0] = p0; sRed[l >> 5][1] = p1; }
    __syncthreads();
    if (l == 0) {
        float o0 = g_ob[0], o1 = g_ob[1];
#pragma unroll
        for (int w = 0; w < 8; w++) { o0 += sRed[w][0]; o1 += sRed[w][1]; }
        out[b * 2 + 0] = o0;
        out[b * 2 + 1] = o1;
    }
}

// ---------------- launch --------------------------------------------------
extern "C" void kernel_launch(void* const* d_in, const int* in_sizes, int n_in,
                              void* d_out, int out_size) {
    const float* x      = (const float*)d_in[0];
    const float* fc_w   = (const float*)d_in[1];
    const float* fc_b   = (const float*)d_in[2];
    const float* ln1_s  = (const float*)d_in[3];
    const float* ln1_b  = (const float*)d_in[4];
    const float* ln2_s  = (const float*)d_in[5];
    const float* ln2_b  = (const float*)d_in[6];
    const float* Wq     = (const float*)d_in[7];
    const float* Wk     = (const float*)d_in[8];
    const float* Wv     = (const float*)d_in[9];
    const float* Wg     = (const float*)d_in[10];
    const float* Wo     = (const float*)d_in[11];
    const float* gn_w   = (const float*)d_in[12];
    const float* gn_b   = (const float*)d_in[13];
    const float* ffn_w1 = (const float*)d_in[14];
    const float* ffn_b1 = (const float*)d_in[15];
    const float* ffn_w2 = (const float*)d_in[16];
    const float* ffn_b2 = (const float*)d_in[17];
    const float* li1_w  = (const float*)d_in[18];
    const float* li1_b  = (const float*)d_in[19];
    const float* li2_w  = (const float*)d_in[20];
    const float* li2_b  = (const float*)d_in[21];

    k_transpose<<<(BATCH * KDIM) / 256, 256>>>(x);
    k_w12<<<NDIM + 1, 256>>>(li1_w, li1_b, li2_w, li2_b);
    dim3 gg(NDIM / 64, KSPLIT);
    k_gemm<<<gg, 128>>>(fc_w);
    k_fuse<<<BATCH, 256>>>(fc_b, ln1_s, ln1_b, ln2_s, ln2_b,
                           Wq, Wk, Wv, Wg, Wo, gn_w, gn_b,
                           ffn_w1, ffn_b1, ffn_w2, ffn_b2,
                           (float*)d_out);
}

// round 3
// speedup vs baseline: 3.2610x; 3.2610x over previous
#include <cuda_runtime.h>
#include <cuda_bf16.h>
#include <math.h>
#include <stdint.h>

// ---------------- problem constants ----------------
#define BATCH   128
#define KDIM    49152      // 6144 * 8
#define NDIM    2048       // 256 * 8
#define KSPLIT  8
#define KCHUNK  (KDIM / KSPLIT)   // 6144
#define KT      64                 // K per smem stage
#define NC      (KCHUNK / KT)      // 96 chunks per CTA
#define BN      128                // N tile per CTA
#define NTILES  (KDIM / KT)        // 768 A tiles

// ---------------- scratch (device globals; no allocation allowed) ----------
// A pre-converted to bf16 hi/lo, stored as the exact swizzled 16KB smem tile
// image: tile T holds rows m=0..127, 64 bf16 per row (128B), SW128 XOR applied.
__device__ __align__(16) __nv_bfloat16 g_xA_hi[NTILES * 128 * 64];  // 12.6 MB
__device__ __align__(16) __nv_bfloat16 g_xA_lo[NTILES * 128 * 64];  // 12.6 MB
__device__ float g_part[KSPLIT * BATCH * NDIM];   // 8 MB split-K partials
__device__ float g_W12[NDIM * 2];                 // collapsed li1_w @ li2_w
__device__ float g_ob[2];                         // collapsed output bias

// ================= PTX helpers (sm_80-era ISA only: safe on compute_103) ====
__device__ __forceinline__ uint32_t smem_u32(const void* p) {
    uint32_t a;
    asm("{ .reg .u64 t; cvta.to.shared.u64 t, %1; cvt.u32.u64 %0, t; }" : "=r"(a) : "l"(p));
    return a;
}
__device__ __forceinline__ void cp_async16(uint32_t dst, const void* src) {
    asm volatile("cp.async.cg.shared.global [%0], [%1], 16;" :: "r"(dst), "l"(src) : "memory");
}
#define CP_COMMIT() asm volatile("cp.async.commit_group;" ::: "memory")
#define CP_WAIT0()  asm volatile("cp.async.wait_group 0;" ::: "memory")

__device__ __forceinline__ void ldsm4(uint32_t* r, uint32_t addr) {
    asm volatile("ldmatrix.sync.aligned.m8n8.x4.shared.b16 {%0,%1,%2,%3}, [%4];"
        : "=r"(r[0]), "=r"(r[1]), "=r"(r[2]), "=r"(r[3]) : "r"(addr));
}
__device__ __forceinline__ void mma_bf16(float* d, const uint32_t* a, const uint32_t* b) {
    asm volatile("mma.sync.aligned.m16n8k16.row.col.f32.bf16.bf16.f32 "
        "{%0,%1,%2,%3}, {%4,%5,%6,%7}, {%8,%9}, {%0,%1,%2,%3};"
        : "+f"(d[0]), "+f"(d[1]), "+f"(d[2]), "+f"(d[3])
        : "r"(a[0]), "r"(a[1]), "r"(a[2]), "r"(a[3]), "r"(b[0]), "r"(b[1]));
}
__device__ __forceinline__ uint32_t bfpair(float a, float b) {
    __nv_bfloat162 h = __floats2bfloat162_rn(a, b);
    return *reinterpret_cast<uint32_t*>(&h);
}

// ---------------- kernel 1: transpose + bf16 hi/lo split + tile-swizzle -----
// x (B=128, 8, 6144): logical xT[m][kglob] = x[m][(kglob&7)*6144 + (kglob>>3)]
// thread handles (m, i): kglob = i*8 + j, j=0..7 (one 16B octet of one tile).
__global__ void __launch_bounds__(256) k_convA(const float* __restrict__ x) {
    int m = blockIdx.x;
    int i = blockIdx.y * 256 + threadIdx.x;
    const float* xp = x + (size_t)m * KDIM + i;
    float v[8];
#pragma unroll
    for (int j = 0; j < 8; j++) v[j] = xp[j * 6144];

    uint32_t hi[4], lo[4];
#pragma unroll
    for (int j = 0; j < 4; j++) {
        float a = v[2 * j], b = v[2 * j + 1];
        float ha = __bfloat162float(__float2bfloat16_rn(a));
        float hb = __bfloat162float(__float2bfloat16_rn(b));
        hi[j] = bfpair(ha, hb);
        lo[j] = bfpair(a - ha, b - hb);
    }
    int T = i >> 3;
    uint32_t off = (uint32_t)T * 16384 + (uint32_t)m * 128
                 + ((((uint32_t)i & 7) << 4) ^ (((uint32_t)m & 7) << 4));
    *reinterpret_cast<uint4*>(reinterpret_cast<char*>(g_xA_hi) + off) =
        make_uint4(hi[0], hi[1], hi[2], hi[3]);
    *reinterpret_cast<uint4*>(reinterpret_cast<char*>(g_xA_lo) + off) =
        make_uint4(lo[0], lo[1], lo[2], lo[3]);
}

// ---------------- kernel 2: W12 = li1_w @ li2_w (2048x2), ob ----------------
__global__ void k_w12(const float* __restrict__ li1_w, const float* __restrict__ li1_b,
                      const float* __restrict__ li2_w, const float* __restrict__ li2_b) {
    int j = blockIdx.x;
    int t = threadIdx.x;
    __shared__ float red0[256];
    __shared__ float red1[256];
    const float* row = (j < NDIM) ? (li1_w + (size_t)j * 1000) : li1_b;
    float a0 = 0.f, a1 = 0.f;
    for (int p = t; p < 1000; p += 256) {
        float w = row[p];
        a0 += w * li2_w[2 * p];
        a1 += w * li2_w[2 * p + 1];
    }
    red0[t] = a0; red1[t] = a1;
    __syncthreads();
    for (int s = 128; s > 0; s >>= 1) {
        if (t < s) { red0[t] += red0[t + s]; red1[t] += red1[t + s]; }
        __syncthreads();
    }
    if (t == 0) {
        if (j < NDIM) { g_W12[2 * j] = red0[0]; g_W12[2 * j + 1] = red1[0]; }
        else          { g_ob[0] = red0[0] + li2_b[0]; g_ob[1] = red1[0] + li2_b[1]; }
    }
}

// ---------------- kernel 3: bf16x3 split-K GEMM via mma.sync ----------------
// grid (16, 8): x = N-tile (128 cols), y = K-split. 256 threads = 8 warps (2m x 4n).
// SMEM per buffer (64KB): A_hi[16K] A_lo[16K] B_hi[16K] B_lo[16K]; 2 buffers.
#define BUF_BYTES  65536
#define SMEM_BYTES (2 * BUF_BYTES)

__global__ void __launch_bounds__(256, 1) k_gemm(const float* __restrict__ fc_w) {
    extern __shared__ __align__(1024) char smem[];
    const uint32_t sb = smem_u32(smem);
    const int t   = threadIdx.x;
    const int w   = t >> 5;
    const int l   = t & 31;
    const int wm  = w >> 2;          // 0..1  (64 rows each)
    const int wn  = w & 3;           // 0..3  (32 cols each)
    const int nbase = blockIdx.x * BN;
    const int s     = blockIdx.y;

    // per-thread ldmatrix address components
    uint32_t aoff[4], amask[4];
#pragma unroll
    for (int mt = 0; mt < 4; mt++) {
        int row = wm * 64 + mt * 16 + (l & 15);
        aoff[mt]  = (uint32_t)row * 128;
        amask[mt] = ((uint32_t)row & 7) << 4;
    }
    uint32_t boff[2], bmask[2];
#pragma unroll
    for (int bt = 0; bt < 2; bt++) {
        int n = wn * 32 + bt * 16 + (l & 15);
        boff[bt]  = (uint32_t)n * 128;
        bmask[bt] = ((uint32_t)n & 7) << 4;
    }
    const uint32_t lcol = ((uint32_t)l >> 4) << 4;   // 0 or 16

    // B load/store lane mapping (conflict-free swizzled STS.64)
    int bn[2], bkq[4];
#pragma unroll
    for (int ih = 0; ih < 2; ih++) bn[ih] = (l & 7) | (w << 3) | (ih << 6);
#pragma unroll
    for (int il = 0; il < 4; il++) bkq[il] = (l >> 3) | (il << 2);

    float acc[64];
#pragma unroll
    for (int q = 0; q < 64; q++) acc[q] = 0.f;

    float bst[8][4];   // staged B fp32 for next chunk

    // ---- prologue: A(0) cp.async + B(0) load/convert/store ----
    {
        int T = s * NC + 0;
        const char* srch = reinterpret_cast<const char*>(g_xA_hi) + (size_t)T * 16384 + t * 16;
        const char* srcl = reinterpret_cast<const char*>(g_xA_lo) + (size_t)T * 16384 + t * 16;
#pragma unroll
        for (int i = 0; i < 4; i++) {
            cp_async16(sb + t * 16 + i * 4096, srch + i * 4096);
            cp_async16(sb + 16384 + t * 16 + i * 4096, srcl + i * 4096);
        }
        CP_COMMIT();
        int kb = s * KCHUNK;
#pragma unroll
        for (int i = 0; i < 8; i++) {
            int n = bn[i >> 2], kq = bkq[i & 3];
            const float* src = fc_w + (size_t)(kb + kq * 4) * NDIM + nbase + n;
#pragma unroll
            for (int e = 0; e < 4; e++) bst[i][e] = src[(size_t)e * NDIM];
        }
#pragma unroll
        for (int i = 0; i < 8; i++) {
            int n = bn[i >> 2], kq = bkq[i & 3];
            uint32_t sa = (uint32_t)n * 128 + (((uint32_t)kq * 8) ^ (((uint32_t)n & 7) << 4));
            float h0 = __bfloat162float(__float2bfloat16_rn(bst[i][0]));
            float h1 = __bfloat162float(__float2bfloat16_rn(bst[i][1]));
            float h2 = __bfloat162float(__float2bfloat16_rn(bst[i][2]));
            float h3 = __bfloat162float(__float2bfloat16_rn(bst[i][3]));
            *reinterpret_cast<uint2*>(smem + 32768 + sa) = make_uint2(bfpair(h0, h1), bfpair(h2, h3));
            *reinterpret_cast<uint2*>(smem + 49152 + sa) =
                make_uint2(bfpair(bst[i][0] - h0, bst[i][1] - h1),
                           bfpair(bst[i][2] - h2, bst[i][3] - h3));
        }
    }

    // ---- main loop ----
    for (int c = 0; c < NC; ++c) {
        const uint32_t cbuf = sb + (uint32_t)(c & 1) * BUF_BYTES;
        const uint32_t nbuf = sb + (uint32_t)((c + 1) & 1) * BUF_BYTES;

        // 1. issue B(c+1) global loads (latency hidden behind compute)
        if (c + 1 < NC) {
            int kb = s * KCHUNK + (c + 1) * KT;
#pragma unroll
            for (int i = 0; i < 8; i++) {
                int n = bn[i >> 2], kq = bkq[i & 3];
                const float* src = fc_w + (size_t)(kb + kq * 4) * NDIM + nbase + n;
#pragma unroll
                for (int e = 0; e < 4; e++) bst[i][e] = src[(size_t)e * NDIM];
            }
        }

        // 2. own A(c) cp.async done; then publish everything, retire old reads
        CP_WAIT0();
        __syncthreads();

        // 3. issue A(c+1) cp.async into the other buffer
        if (c + 1 < NC) {
            int T = s * NC + c + 1;
            const char* srch = reinterpret_cast<const char*>(g_xA_hi) + (size_t)T * 16384 + t * 16;
            const char* srcl = reinterpret_cast<const char*>(g_xA_lo) + (size_t)T * 16384 + t * 16;
            uint32_t nb = nbuf;
#pragma unroll
            for (int i = 0; i < 4; i++) {
                cp_async16(nb + t * 16 + i * 4096, srch + i * 4096);
                cp_async16(nb + 16384 + t * 16 + i * 4096, srcl + i * 4096);
            }
            CP_COMMIT();
        }

        // 4. compute chunk c: 4 k-steps x (ldmatrix + 48 mma)
        const uint32_t Ah = cbuf, Bh = cbuf + 32768;
#pragma unroll
        for (int ks = 0; ks < 4; ks++) {
            const uint32_t kcol = (uint32_t)(ks * 32) + lcol;
            uint32_t ah[4][4], al[4][4], bh[4][2], bl[4][2];
#pragma unroll
            for (int mt = 0; mt < 4; mt++) {
                uint32_t ad = Ah + aoff[mt] + (kcol ^ amask[mt]);
                ldsm4(ah[mt], ad);
                ldsm4(al[mt], ad + 16384);
            }
#pragma unroll
            for (int bt = 0; bt < 2; bt++) {
                uint32_t bd = Bh + boff[bt] + (kcol ^ bmask[bt]);
                uint32_t r[4];
                ldsm4(r, bd);
                bh[2 * bt][0] = r[0]; bh[2 * bt][1] = r[2];
                bh[2 * bt + 1][0] = r[1]; bh[2 * bt + 1][1] = r[3];
                ldsm4(r, bd + 16384);
                bl[2 * bt][0] = r[0]; bl[2 * bt][1] = r[2];
                bl[2 * bt + 1][0] = r[1]; bl[2 * bt + 1][1] = r[3];
            }
#pragma unroll
            for (int mt = 0; mt < 4; mt++)
#pragma unroll
                for (int nt = 0; nt < 4; nt++) {
                    float* d = acc + (mt * 4 + nt) * 4;
                    mma_bf16(d, ah[mt], bh[nt]);
                    mma_bf16(d, ah[mt], bl[nt]);
                    mma_bf16(d, al[mt], bh[nt]);
                }
        }

        // 5. convert + store B(c+1) into the other buffer
        if (c + 1 < NC) {
#pragma unroll
            for (int i = 0; i < 8; i++) {
                int n = bn[i >> 2], kq = bkq[i & 3];
                uint32_t sa = (uint32_t)n * 128 + (((uint32_t)kq * 8) ^ (((uint32_t)n & 7) << 4));
                float h0 = __bfloat162float(__float2bfloat16_rn(bst[i][0]));
                float h1 = __bfloat162float(__float2bfloat16_rn(bst[i][1]));
                float h2 = __bfloat162float(__float2bfloat16_rn(bst[i][2]));
                float h3 = __bfloat162float(__float2bfloat16_rn(bst[i][3]));
                char* bp = smem + (nbuf - sb);
                *reinterpret_cast<uint2*>(bp + 32768 + sa) = make_uint2(bfpair(h0, h1), bfpair(h2, h3));
                *reinterpret_cast<uint2*>(bp + 49152 + sa) =
                    make_uint2(bfpair(bst[i][0] - h0, bst[i][1] - h1),
                               bfpair(bst[i][2] - h2, bst[i][3] - h3));
            }
        }
    }

    // ---- epilogue: write partials ----
    float* op = g_part + (size_t)s * BATCH * NDIM;
#pragma unroll
    for (int mt = 0; mt < 4; mt++) {
        int m = wm * 64 + mt * 16 + (l >> 2);
#pragma unroll
        for (int nt = 0; nt < 4; nt++) {
            int n = nbase + wn * 32 + nt * 8 + (l & 3) * 2;
            const float* d = acc + (mt * 4 + nt) * 4;
            *reinterpret_cast<float2*>(op + (size_t)m * NDIM + n)       = make_float2(d[0], d[1]);
            *reinterpret_cast<float2*>(op + (size_t)(m + 8) * NDIM + n) = make_float2(d[2], d[3]);
        }
    }
}

// ---------------- kernel 4: fused per-batch pipeline -------------------------
__global__ void __launch_bounds__(256) k_fuse(
    const float* __restrict__ fc_b,
    const float* __restrict__ ln1_s, const float* __restrict__ ln1_b,
    const float* __restrict__ ln2_s, const float* __restrict__ ln2_b,
    const float* __restrict__ Wq, const float* __restrict__ Wk, const float* __restrict__ Wv,
    const float* __restrict__ Wg, const float* __restrict__ Wo,
    const float* __restrict__ gn_w, const float* __restrict__ gn_b,
    const float* __restrict__ w1, const float* __restrict__ b1,
    const float* __restrict__ w2, const float* __restrict__ b2,
    float* __restrict__ out)
{
    int b = blockIdx.x;
    int l = threadIdx.x;

    __shared__ float4 sK4[256];
    __shared__ float4 sV4[256][2];
    __shared__ float  sGPinv[256];
    __shared__ float  sRed[8][2];
    __shared__ float  swq[64], swk[64], swv[128], swg[128], swo[128];
    __shared__ float  sgnw[16], sgnb[16], sw1[64], sw2[64];
    __shared__ float  sb1[8], sb2[8], sl1s[8], sl1b[8], sl2s[8], sl2b[8];

    if (l < 64)  { swq[l] = Wq[l]; swk[l] = Wk[l]; sw1[l] = w1[l]; sw2[l] = w2[l]; }
    if (l < 128) { swv[l] = Wv[l]; swg[l] = Wg[l]; swo[l] = Wo[l]; }
    if (l < 16)  { sgnw[l] = gn_w[l]; sgnb[l] = gn_b[l]; }
    if (l < 8)   { sb1[l] = b1[l]; sb2[l] = b2[l];
                   sl1s[l] = ln1_s[l]; sl1b[l] = ln1_b[l];
                   sl2s[l] = ln2_s[l]; sl2b[l] = ln2_b[l]; }

    float X[8];
#pragma unroll
    for (int d = 0; d < 8; d++) {
        float h = fc_b[l * 8 + d];
#pragma unroll
        for (int s = 0; s < KSPLIT; s++)
            h += g_part[s * (BATCH * NDIM) + b * NDIM + l * 8 + d];
        X[d] = h;
    }
    __syncthreads();

    float Xn[8];
    {
        float mu = 0.f;
#pragma unroll
        for (int d = 0; d < 8; d++) mu += X[d];
        mu *= 0.125f;
        float var = 0.f;
#pragma unroll
        for (int d = 0; d < 8; d++) { float tt = X[d] - mu; var += tt * tt; }
        var *= 0.125f;
        float inv = rsqrtf(var + 1e-5f);
#pragma unroll
        for (int d = 0; d < 8; d++) Xn[d] = (X[d] - mu) * inv * sl1s[d] + sl1b[d];
    }

    float fl = (float)l;
    float c0 = cosf(fl), s0 = sinf(fl);
    float c1 = cosf(fl * 0.01f), s1 = sinf(fl * 0.01f);
    float e0 = exp2f(fl * (-1.807354922f / 512.0f));
    float e1 = exp2f(fl * (-0.637429921f / 512.0f));
    float ie0 = 1.0f / e0, ie1 = 1.0f / e1;

    float yc[16];
    const float gammas[2] = { 1.0f - 1.0f / 32.0f, 1.0f - 1.0f / 512.0f };

#pragma unroll
    for (int hd = 0; hd < 2; ++hd) {
        float gamma = gammas[hd];
        const float* wq = swq + hd * 32;
        const float* wk = swk + hd * 32;
        const float* wv = swv + hd * 64;

        float q0 = 0, q1 = 0, q2 = 0, q3 = 0, k0 = 0, k1 = 0, k2 = 0, k3 = 0;
#pragma unroll
        for (int d = 0; d < 8; d++) {
            float xv = Xn[d];
            q0 += xv * wq[d * 4 + 0]; q1 += xv * wq[d * 4 + 1];
            q2 += xv * wq[d * 4 + 2]; q3 += xv * wq[d * 4 + 3];
            k0 += xv * wk[d * 4 + 0]; k1 += xv * wk[d * 4 + 1];
            k2 += xv * wk[d * 4 + 2]; k3 += xv * wk[d * 4 + 3];
        }
        float Q0 = (q0 * c0 - q1 * s0) * e0;
        float Q1 = (q1 * c0 + q0 * s0) * e0;
        float Q2 = (q2 * c1 - q3 * s1) * e1;
        float Q3 = (q3 * c1 + q2 * s1) * e1;
        float K0 = (k0 * c0 - k1 * s0) * ie0;
        float K1 = (k1 * c0 + k0 * s0) * ie0;
        float K2 = (k2 * c1 - k3 * s1) * ie1;
        float K3 = (k3 * c1 + k2 * s1) * ie1;

        float V[8];
#pragma unroll
        for (int f = 0; f < 8; f++) {
            float a = 0.f;
#pragma unroll
            for (int d = 0; d < 8; d++) a += Xn[d] * wv[d * 8 + f];
            V[f] = a;
        }

        sK4[l] = make_float4(K0, K1, K2, K3);
        sV4[l][0] = make_float4(V[0], V[1], V[2], V[3]);
        sV4[l][1] = make_float4(V[4], V[5], V[6], V[7]);
        sGPinv[l] = powf(gamma, -fl);
        float gpn = powf(gamma, fl);
        __syncthreads();

        float a0 = 0, a1 = 0, a2 = 0, a3 = 0, a4 = 0, a5 = 0, a6 = 0, a7 = 0;
        for (int m = 0; m <= l; ++m) {
            float4 kv = sK4[m];
            float wgt = (Q0 * kv.x + Q1 * kv.y + Q2 * kv.z + Q3 * kv.w) * gpn * sGPinv[m];
            float4 v0 = sV4[m][0], v1 = sV4[m][1];
            a0 += wgt * v0.x; a1 += wgt * v0.y; a2 += wgt * v0.z; a3 += wgt * v0.w;
            a4 += wgt * v1.x; a5 += wgt * v1.y; a6 += wgt * v1.z; a7 += wgt * v1.w;
        }
        yc[hd * 8 + 0] = a0; yc[hd * 8 + 1] = a1; yc[hd * 8 + 2] = a2; yc[hd * 8 + 3] = a3;
        yc[hd * 8 + 4] = a4; yc[hd * 8 + 5] = a5; yc[hd * 8 + 6] = a6; yc[hd * 8 + 7] = a7;
        __syncthreads();
    }

    float gn[16];
#pragma unroll
    for (int g = 0; g < 2; g++) {
        float mu = 0.f;
#pragma unroll
        for (int jj = 0; jj < 8; jj++) mu += yc[g * 8 + jj];
        mu *= 0.125f;
        float var = 0.f;
#pragma unroll
        for (int jj = 0; jj < 8; jj++) { float tt = yc[g * 8 + jj] - mu; var += tt * tt; }
        var *= 0.125f;
        float inv = rsqrtf(var + 1e-5f);
#pragma unroll
        for (int jj = 0; jj < 8; jj++)
            gn[g * 8 + jj] = (yc[g * 8 + jj] - mu) * inv * sgnw[g * 8 + jj] + sgnb[g * 8 + jj];
    }

    float msr[8] = {0, 0, 0, 0, 0, 0, 0, 0};
#pragma unroll
    for (int j = 0; j < 16; j++) {
        float gt = 0.f;
#pragma unroll
        for (int d = 0; d < 8; d++) gt += Xn[d] * swg[d * 16 + j];
        gt = gt / (1.0f + expf(-gt));
        float val = gt * gn[j];
#pragma unroll
        for (int d = 0; d < 8; d++) msr[d] += val * swo[j * 8 + d];
    }

    float Y[8], Z[8];
#pragma unroll
    for (int d = 0; d < 8; d++) Y[d] = msr[d] + X[d];
    {
        float mu = 0.f;
#pragma unroll
        for (int d = 0; d < 8; d++) mu += Y[d];
        mu *= 0.125f;
        float var = 0.f;
#pragma unroll
        for (int d = 0; d < 8; d++) { float tt = Y[d] - mu; var += tt * tt; }
        var *= 0.125f;
        float inv = rsqrtf(var + 1e-5f);
#pragma unroll
        for (int d = 0; d < 8; d++) Z[d] = (Y[d] - mu) * inv * sl2s[d] + sl2b[d];
    }

    float f1[8];
#pragma unroll
    for (int e = 0; e < 8; e++) {
        float a = sb1[e];
#pragma unroll
        for (int d = 0; d < 8; d++) a += Z[d] * sw1[d * 8 + e];
        f1[e] = 0.5f * a * (1.0f + erff(a * 0.70710678118654752f));
    }

    float p0 = 0.f, p1 = 0.f;
#pragma unroll
    for (int d = 0; d < 8; d++) {
        float a = sb2[d];
#pragma unroll
        for (int e = 0; e < 8; e++) a += f1[e] * sw2[e * 8 + d];
        float xf = a + Y[d];
        p0 += xf * g_W12[(l * 8 + d) * 2];
        p1 += xf * g_W12[(l * 8 + d) * 2 + 1];
    }

#pragma unroll
    for (int off = 16; off > 0; off >>= 1) {
        p0 += __shfl_down_sync(0xffffffffu, p0, off);
        p1 += __shfl_down_sync(0xffffffffu, p1, off);
    }
    if ((l & 31) == 0) { sRed[l >> 5][0] = p0; sRed[l >> 5][1] = p1; }
    __syncthreads();
    if (l == 0) {
        float o0 = g_ob[0], o1 = g_ob[1];
#pragma unroll
        for (int ww = 0; ww < 8; ww++) { o0 += sRed[ww][0]; o1 += sRed[ww][1]; }
        out[b * 2 + 0] = o0;
        out[b * 2 + 1] = o1;
    }
}

// ---------------- launch --------------------------------------------------
extern "C" void kernel_launch(void* const* d_in, const int* in_sizes, int n_in,
                              void* d_out, int out_size) {
    const float* x      = (const float*)d_in[0];
    const float* fc_w   = (const float*)d_in[1];
    const float* fc_b   = (const float*)d_in[2];
    const float* ln1_s  = (const float*)d_in[3];
    const float* ln1_b  = (const float*)d_in[4];
    const float* ln2_s  = (const float*)d_in[5];
    const float* ln2_b  = (const float*)d_in[6];
    const float* Wq     = (const float*)d_in[7];
    const float* Wk     = (const float*)d_in[8];
    const float* Wv     = (const float*)d_in[9];
    const float* Wg     = (const float*)d_in[10];
    const float* Wo     = (const float*)d_in[11];
    const float* gn_w   = (const float*)d_in[12];
    const float* gn_b   = (const float*)d_in[13];
    const float* ffn_w1 = (const float*)d_in[14];
    const float* ffn_b1 = (const float*)d_in[15];
    const float* ffn_w2 = (const float*)d_in[16];
    const float* ffn_b2 = (const float*)d_in[17];
    const float* li1_w  = (const float*)d_in[18];
    const float* li1_b  = (const float*)d_in[19];
    const float* li2_w  = (const float*)d_in[20];
    const float* li2_b  = (const float*)d_in[21];

    cudaFuncSetAttribute(k_gemm, cudaFuncAttributeMaxDynamicSharedMemorySize, SMEM_BYTES);

    dim3 gA(128, 24);
    k_convA<<<gA, 256>>>(x);
    k_w12<<<NDIM + 1, 256>>>(li1_w, li1_b, li2_w, li2_b);
    dim3 gg(NDIM / BN, KSPLIT);
    k_gemm<<<gg, 256, SMEM_BYTES>>>(fc_w);
    k_fuse<<<BATCH, 256>>>(fc_b, ln1_s, ln1_b, ln2_s, ln2_b,
                           Wq, Wk, Wv, Wg, Wo, gn_w, gn_b,
                           ffn_w1, ffn_b1, ffn_w2, ffn_b2,
                           (float*)d_out);
}

// round 4
// speedup vs baseline: 4.4092x; 1.3521x over previous
#include <cuda_runtime.h>
#include <cuda_fp16.h>
#include <math.h>
#include <stdint.h>

// ---------------- problem constants ----------------
#define BATCH   128
#define KDIM    49152      // 6144 * 8
#define NDIM    2048       // 256 * 8
#define KSPLIT  8
#define KCHUNK  (KDIM / KSPLIT)   // 6144
#define KT      64                 // K per smem stage
#define NC      (KCHUNK / KT)      // 96 chunks per CTA
#define BN      128                // N tile per CTA
#define NTILES  (KDIM / KT)        // 768 A tiles

// ---------------- scratch (device globals; no allocation allowed) ----------
// A pre-converted to fp16 hi/lo, stored as the exact swizzled 16KB smem tile
// image: tile T holds rows m=0..127, 64 fp16 per row (128B), SW128 XOR applied.
__device__ __align__(16) __half g_xA_hi[NTILES * 128 * 64];  // 12.6 MB
__device__ __align__(16) __half g_xA_lo[NTILES * 128 * 64];  // 12.6 MB
__device__ float g_part[KSPLIT * BATCH * NDIM];   // 8 MB split-K partials
__device__ float g_W12[NDIM * 2];                 // collapsed li1_w @ li2_w
__device__ float g_ob[2];                         // collapsed output bias

// ================= PTX helpers (sm_80-era ISA only: safe on compute_103) ====
__device__ __forceinline__ uint32_t smem_u32(const void* p) {
    uint32_t a;
    asm("{ .reg .u64 t; cvta.to.shared.u64 t, %1; cvt.u32.u64 %0, t; }" : "=r"(a) : "l"(p));
    return a;
}
__device__ __forceinline__ void cp_async16(uint32_t dst, const void* src) {
    asm volatile("cp.async.cg.shared.global [%0], [%1], 16;" :: "r"(dst), "l"(src) : "memory");
}
#define CP_COMMIT() asm volatile("cp.async.commit_group;" ::: "memory")
#define CP_WAIT0()  asm volatile("cp.async.wait_group 0;" ::: "memory")

__device__ __forceinline__ void ldsm4(uint32_t* r, uint32_t addr) {
    asm volatile("ldmatrix.sync.aligned.m8n8.x4.shared.b16 {%0,%1,%2,%3}, [%4];"
        : "=r"(r[0]), "=r"(r[1]), "=r"(r[2]), "=r"(r[3]) : "r"(addr));
}
__device__ __forceinline__ void mma_fp16(float* d, const uint32_t* a, const uint32_t* b) {
    asm volatile("mma.sync.aligned.m16n8k16.row.col.f32.f16.f16.f32 "
        "{%0,%1,%2,%3}, {%4,%5,%6,%7}, {%8,%9}, {%0,%1,%2,%3};"
        : "+f"(d[0]), "+f"(d[1]), "+f"(d[2]), "+f"(d[3])
        : "r"(a[0]), "r"(a[1]), "r"(a[2]), "r"(a[3]), "r"(b[0]), "r"(b[1]));
}
__device__ __forceinline__ uint32_t hfpair(float a, float b) {
    __half2 h = __floats2half2_rn(a, b);
    return *reinterpret_cast<uint32_t*>(&h);
}

// ---------------- kernel 1: transpose + fp16 hi/lo split + tile-swizzle -----
// x (B=128, 8, 6144): logical xT[m][kglob] = x[m][(kglob&7)*6144 + (kglob>>3)]
__global__ void __launch_bounds__(256) k_convA(const float* __restrict__ x) {
    int m = blockIdx.x;
    int i = blockIdx.y * 256 + threadIdx.x;
    const float* xp = x + (size_t)m * KDIM + i;
    float v[8];
#pragma unroll
    for (int j = 0; j < 8; j++) v[j] = xp[j * 6144];

    uint32_t hi[4], lo[4];
#pragma unroll
    for (int j = 0; j < 4; j++) {
        float a = v[2 * j], b = v[2 * j + 1];
        float ha = __half2float(__float2half_rn(a));
        float hb = __half2float(__float2half_rn(b));
        hi[j] = hfpair(ha, hb);
        lo[j] = hfpair(a - ha, b - hb);
    }
    int T = i >> 3;
    uint32_t off = (uint32_t)T * 16384 + (uint32_t)m * 128
                 + ((((uint32_t)i & 7) << 4) ^ (((uint32_t)m & 7) << 4));
    *reinterpret_cast<uint4*>(reinterpret_cast<char*>(g_xA_hi) + off) =
        make_uint4(hi[0], hi[1], hi[2], hi[3]);
    *reinterpret_cast<uint4*>(reinterpret_cast<char*>(g_xA_lo) + off) =
        make_uint4(lo[0], lo[1], lo[2], lo[3]);
}

// ---------------- kernel 2: W12 = li1_w @ li2_w (2048x2), ob ----------------
__global__ void k_w12(const float* __restrict__ li1_w, const float* __restrict__ li1_b,
                      const float* __restrict__ li2_w, const float* __restrict__ li2_b) {
    int j = blockIdx.x;
    int t = threadIdx.x;
    __shared__ float red0[256];
    __shared__ float red1[256];
    const float* row = (j < NDIM) ? (li1_w + (size_t)j * 1000) : li1_b;
    float a0 = 0.f, a1 = 0.f;
    for (int p = t; p < 1000; p += 256) {
        float w = row[p];
        a0 += w * li2_w[2 * p];
        a1 += w * li2_w[2 * p + 1];
    }
    red0[t] = a0; red1[t] = a1;
    __syncthreads();
    for (int s = 128; s > 0; s >>= 1) {
        if (t < s) { red0[t] += red0[t + s]; red1[t] += red1[t + s]; }
        __syncthreads();
    }
    if (t == 0) {
        if (j < NDIM) { g_W12[2 * j] = red0[0]; g_W12[2 * j + 1] = red1[0]; }
        else          { g_ob[0] = red0[0] + li2_b[0]; g_ob[1] = red1[0] + li2_b[1]; }
    }
}

// ---------------- kernel 3: fp16 2-pass split-K GEMM via mma.sync ----------
// grid (16, 8): x = N-tile (128 cols), y = K-split. 256 threads = 8 warps (2m x 4n).
// SMEM per buffer (48KB): A_hi[16K] A_lo[16K] B[16K]; 2 buffers.
#define BUF_BYTES  49152
#define SMEM_BYTES (2 * BUF_BYTES)

__global__ void __launch_bounds__(256, 1) k_gemm(const float* __restrict__ fc_w) {
    extern __shared__ __align__(1024) char smem[];
    const uint32_t sb = smem_u32(smem);
    const int t   = threadIdx.x;
    const int w   = t >> 5;
    const int l   = t & 31;
    const int wm  = w >> 2;          // 0..1  (64 rows each)
    const int wn  = w & 3;           // 0..3  (32 cols each)
    const int nbase = blockIdx.x * BN;
    const int s     = blockIdx.y;

    // per-thread ldmatrix address components
    uint32_t aoff[4], amask[4];
#pragma unroll
    for (int mt = 0; mt < 4; mt++) {
        int row = wm * 64 + mt * 16 + (l & 15);
        aoff[mt]  = (uint32_t)row * 128;
        amask[mt] = ((uint32_t)row & 7) << 4;
    }
    uint32_t boff[2], bmask[2];
#pragma unroll
    for (int bt = 0; bt < 2; bt++) {
        int n = wn * 32 + bt * 16 + (l & 15);
        boff[bt]  = (uint32_t)n * 128;
        bmask[bt] = ((uint32_t)n & 7) << 4;
    }
    const uint32_t lcol = ((uint32_t)l >> 4) << 4;   // 0 or 16

    // B load/store lane mapping (conflict-free swizzled STS.64)
    int bn[2], bkq[4];
#pragma unroll
    for (int ih = 0; ih < 2; ih++) bn[ih] = (l & 7) | (w << 3) | (ih << 6);
#pragma unroll
    for (int il = 0; il < 4; il++) bkq[il] = (l >> 3) | (il << 2);

    float acc[64];
#pragma unroll
    for (int q = 0; q < 64; q++) acc[q] = 0.f;

    float bst[8][4];   // staged B fp32 for next chunk

    // ---- prologue: A(0) cp.async + B(0) load/convert/store ----
    {
        int T = s * NC + 0;
        const char* srch = reinterpret_cast<const char*>(g_xA_hi) + (size_t)T * 16384 + t * 16;
        const char* srcl = reinterpret_cast<const char*>(g_xA_lo) + (size_t)T * 16384 + t * 16;
#pragma unroll
        for (int i = 0; i < 4; i++) {
            cp_async16(sb + t * 16 + i * 4096, srch + i * 4096);
            cp_async16(sb + 16384 + t * 16 + i * 4096, srcl + i * 4096);
        }
        CP_COMMIT();
        int kb = s * KCHUNK;
#pragma unroll
        for (int i = 0; i < 8; i++) {
            int n = bn[i >> 2], kq = bkq[i & 3];
            const float* src = fc_w + (size_t)(kb + kq * 4) * NDIM + nbase + n;
#pragma unroll
            for (int e = 0; e < 4; e++) bst[i][e] = src[(size_t)e * NDIM];
        }
#pragma unroll
        for (int i = 0; i < 8; i++) {
            int n = bn[i >> 2], kq = bkq[i & 3];
            uint32_t sa = (uint32_t)n * 128 + (((uint32_t)kq * 8) ^ (((uint32_t)n & 7) << 4));
            *reinterpret_cast<uint2*>(smem + 32768 + sa) =
                make_uint2(hfpair(bst[i][0], bst[i][1]), hfpair(bst[i][2], bst[i][3]));
        }
    }

    // ---- main loop ----
    for (int c = 0; c < NC; ++c) {
        const uint32_t cbuf = sb + (uint32_t)(c & 1) * BUF_BYTES;
        const uint32_t nbuf = sb + (uint32_t)((c + 1) & 1) * BUF_BYTES;

        // 1. issue B(c+1) global loads (latency hidden behind compute)
        if (c + 1 < NC) {
            int kb = s * KCHUNK + (c + 1) * KT;
#pragma unroll
            for (int i = 0; i < 8; i++) {
                int n = bn[i >> 2], kq = bkq[i & 3];
                const float* src = fc_w + (size_t)(kb + kq * 4) * NDIM + nbase + n;
#pragma unroll
                for (int e = 0; e < 4; e++) bst[i][e] = src[(size_t)e * NDIM];
            }
        }

        // 2. own A(c) cp.async done; publish, retire old reads
        CP_WAIT0();
        __syncthreads();

        // 3. issue A(c+1) cp.async into the other buffer
        if (c + 1 < NC) {
            int T = s * NC + c + 1;
            const char* srch = reinterpret_cast<const char*>(g_xA_hi) + (size_t)T * 16384 + t * 16;
            const char* srcl = reinterpret_cast<const char*>(g_xA_lo) + (size_t)T * 16384 + t * 16;
#pragma unroll
            for (int i = 0; i < 4; i++) {
                cp_async16(nbuf + t * 16 + i * 4096, srch + i * 4096);
                cp_async16(nbuf + 16384 + t * 16 + i * 4096, srcl + i * 4096);
            }
            CP_COMMIT();
        }

        // 4. compute chunk c: 4 k-steps x (ldmatrix + 32 mma)
        const uint32_t Ah = cbuf, Bh = cbuf + 32768;
#pragma unroll
        for (int ks = 0; ks < 4; ks++) {
            const uint32_t kcol = (uint32_t)(ks * 32) + lcol;
            uint32_t ah[4][4], al[4][4], bh[4][2];
#pragma unroll
            for (int mt = 0; mt < 4; mt++) {
                uint32_t ad = Ah + aoff[mt] + (kcol ^ amask[mt]);
                ldsm4(ah[mt], ad);
                ldsm4(al[mt], ad + 16384);
            }
#pragma unroll
            for (int bt = 0; bt < 2; bt++) {
                uint32_t bd = Bh + boff[bt] + (kcol ^ bmask[bt]);
                uint32_t r[4];
                ldsm4(r, bd);
                bh[2 * bt][0] = r[0]; bh[2 * bt][1] = r[2];
                bh[2 * bt + 1][0] = r[1]; bh[2 * bt + 1][1] = r[3];
            }
#pragma unroll
            for (int mt = 0; mt < 4; mt++)
#pragma unroll
                for (int nt = 0; nt < 4; nt++) {
                    float* d = acc + (mt * 4 + nt) * 4;
                    mma_fp16(d, ah[mt], bh[nt]);
                    mma_fp16(d, al[mt], bh[nt]);
                }
        }

        // 5. convert + store B(c+1) into the other buffer
        if (c + 1 < NC) {
#pragma unroll
            for (int i = 0; i < 8; i++) {
                int n = bn[i >> 2], kq = bkq[i & 3];
                uint32_t sa = (uint32_t)n * 128 + (((uint32_t)kq * 8) ^ (((uint32_t)n & 7) << 4));
                char* bp = smem + (nbuf - sb);
                *reinterpret_cast<uint2*>(bp + 32768 + sa) =
                    make_uint2(hfpair(bst[i][0], bst[i][1]), hfpair(bst[i][2], bst[i][3]));
            }
        }
    }

    // ---- epilogue: write partials ----
    float* op = g_part + (size_t)s * BATCH * NDIM;
#pragma unroll
    for (int mt = 0; mt < 4; mt++) {
        int m = wm * 64 + mt * 16 + (l >> 2);
#pragma unroll
        for (int nt = 0; nt < 4; nt++) {
            int n = nbase + wn * 32 + nt * 8 + (l & 3) * 2;
            const float* d = acc + (mt * 4 + nt) * 4;
            *reinterpret_cast<float2*>(op + (size_t)m * NDIM + n)       = make_float2(d[0], d[1]);
            *reinterpret_cast<float2*>(op + (size_t)(m + 8) * NDIM + n) = make_float2(d[2], d[3]);
        }
    }
}

// ---------------- kernel 4: fused per-batch pipeline -------------------------
__global__ void __launch_bounds__(256) k_fuse(
    const float* __restrict__ fc_b,
    const float* __restrict__ ln1_s, const float* __restrict__ ln1_b,
    const float* __restrict__ ln2_s, const float* __restrict__ ln2_b,
    const float* __restrict__ Wq, const float* __restrict__ Wk, const float* __restrict__ Wv,
    const float* __restrict__ Wg, const float* __restrict__ Wo,
    const float* __restrict__ gn_w, const float* __restrict__ gn_b,
    const float* __restrict__ w1, const float* __restrict__ b1,
    const float* __restrict__ w2, const float* __restrict__ b2,
    float* __restrict__ out)
{
    int b = blockIdx.x;
    int l = threadIdx.x;

    __shared__ float4 sK4[256];
    __shared__ float4 sV4[256][2];
    __shared__ float  sGPinv[256];
    __shared__ float  sRed[8][2];
    __shared__ float  swq[64], swk[64], swv[128], swg[128], swo[128];
    __shared__ float  sgnw[16], sgnb[16], sw1[64], sw2[64];
    __shared__ float  sb1[8], sb2[8], sl1s[8], sl1b[8], sl2s[8], sl2b[8];

    if (l < 64)  { swq[l] = Wq[l]; swk[l] = Wk[l]; sw1[l] = w1[l]; sw2[l] = w2[l]; }
    if (l < 128) { swv[l] = Wv[l]; swg[l] = Wg[l]; swo[l] = Wo[l]; }
    if (l < 16)  { sgnw[l] = gn_w[l]; sgnb[l] = gn_b[l]; }
    if (l < 8)   { sb1[l] = b1[l]; sb2[l] = b2[l];
                   sl1s[l] = ln1_s[l]; sl1b[l] = ln1_b[l];
                   sl2s[l] = ln2_s[l]; sl2b[l] = ln2_b[l]; }

    float X[8];
#pragma unroll
    for (int d = 0; d < 8; d++) {
        float h = fc_b[l * 8 + d];
#pragma unroll
        for (int s = 0; s < KSPLIT; s++)
            h += g_part[s * (BATCH * NDIM) + b * NDIM + l * 8 + d];
        X[d] = h;
    }
    __syncthreads();

    float Xn[8];
    {
        float mu = 0.f;
#pragma unroll
        for (int d = 0; d < 8; d++) mu += X[d];
        mu *= 0.125f;
        float var = 0.f;
#pragma unroll
        for (int d = 0; d < 8; d++) { float tt = X[d] - mu; var += tt * tt; }
        var *= 0.125f;
        float inv = rsqrtf(var + 1e-5f);
#pragma unroll
        for (int d = 0; d < 8; d++) Xn[d] = (X[d] - mu) * inv * sl1s[d] + sl1b[d];
    }

    float fl = (float)l;
    float c0 = cosf(fl), s0 = sinf(fl);
    float c1 = cosf(fl * 0.01f), s1 = sinf(fl * 0.01f);
    float e0 = exp2f(fl * (-1.807354922f / 512.0f));
    float e1 = exp2f(fl * (-0.637429921f / 512.0f));
    float ie0 = 1.0f / e0, ie1 = 1.0f / e1;

    float yc[16];
    const float gammas[2] = { 1.0f - 1.0f / 32.0f, 1.0f - 1.0f / 512.0f };

#pragma unroll
    for (int hd = 0; hd < 2; ++hd) {
        float gamma = gammas[hd];
        const float* wq = swq + hd * 32;
        const float* wk = swk + hd * 32;
        const float* wv = swv + hd * 64;

        float q0 = 0, q1 = 0, q2 = 0, q3 = 0, k0 = 0, k1 = 0, k2 = 0, k3 = 0;
#pragma unroll
        for (int d = 0; d < 8; d++) {
            float xv = Xn[d];
            q0 += xv * wq[d * 4 + 0]; q1 += xv * wq[d * 4 + 1];
            q2 += xv * wq[d * 4 + 2]; q3 += xv * wq[d * 4 + 3];
            k0 += xv * wk[d * 4 + 0]; k1 += xv * wk[d * 4 + 1];
            k2 += xv * wk[d * 4 + 2]; k3 += xv * wk[d * 4 + 3];
        }
        float Q0 = (q0 * c0 - q1 * s0) * e0;
        float Q1 = (q1 * c0 + q0 * s0) * e0;
        float Q2 = (q2 * c1 - q3 * s1) * e1;
        float Q3 = (q3 * c1 + q2 * s1) * e1;
        float K0 = (k0 * c0 - k1 * s0) * ie0;
        float K1 = (k1 * c0 + k0 * s0) * ie0;
        float K2 = (k2 * c1 - k3 * s1) * ie1;
        float K3 = (k3 * c1 + k2 * s1) * ie1;

        float V[8];
#pragma unroll
        for (int f = 0; f < 8; f++) {
            float a = 0.f;
#pragma unroll
            for (int d = 0; d < 8; d++) a += Xn[d] * wv[d * 8 + f];
            V[f] = a;
        }

        sK4[l] = make_float4(K0, K1, K2, K3);
        sV4[l][0] = make_float4(V[0], V[1], V[2], V[3]);
        sV4[l][1] = make_float4(V[4], V[5], V[6], V[7]);
        sGPinv[l] = powf(gamma, -fl);
        float gpn = powf(gamma, fl);
        __syncthreads();

        float a0 = 0, a1 = 0, a2 = 0, a3 = 0, a4 = 0, a5 = 0, a6 = 0, a7 = 0;
        for (int m = 0; m <= l; ++m) {
            float4 kv = sK4[m];
            float wgt = (Q0 * kv.x + Q1 * kv.y + Q2 * kv.z + Q3 * kv.w) * gpn * sGPinv[m];
            float4 v0 = sV4[m][0], v1 = sV4[m][1];
            a0 += wgt * v0.x; a1 += wgt * v0.y; a2 += wgt * v0.z; a3 += wgt * v0.w;
            a4 += wgt * v1.x; a5 += wgt * v1.y; a6 += wgt * v1.z; a7 += wgt * v1.w;
        }
        yc[hd * 8 + 0] = a0; yc[hd * 8 + 1] = a1; yc[hd * 8 + 2] = a2; yc[hd * 8 + 3] = a3;
        yc[hd * 8 + 4] = a4; yc[hd * 8 + 5] = a5; yc[hd * 8 + 6] = a6; yc[hd * 8 + 7] = a7;
        __syncthreads();
    }

    float gn[16];
#pragma unroll
    for (int g = 0; g < 2; g++) {
        float mu = 0.f;
#pragma unroll
        for (int jj = 0; jj < 8; jj++) mu += yc[g * 8 + jj];
        mu *= 0.125f;
        float var = 0.f;
#pragma unroll
        for (int jj = 0; jj < 8; jj++) { float tt = yc[g * 8 + jj] - mu; var += tt * tt; }
        var *= 0.125f;
        float inv = rsqrtf(var + 1e-5f);
#pragma unroll
        for (int jj = 0; jj < 8; jj++)
            gn[g * 8 + jj] = (yc[g * 8 + jj] - mu) * inv * sgnw[g * 8 + jj] + sgnb[g * 8 + jj];
    }

    float msr[8] = {0, 0, 0, 0, 0, 0, 0, 0};
#pragma unroll
    for (int j = 0; j < 16; j++) {
        float gt = 0.f;
#pragma unroll
        for (int d = 0; d < 8; d++) gt += Xn[d] * swg[d * 16 + j];
        gt = gt / (1.0f + expf(-gt));
        float val = gt * gn[j];
#pragma unroll
        for (int d = 0; d < 8; d++) msr[d] += val * swo[j * 8 + d];
    }

    float Y[8], Z[8];
#pragma unroll
    for (int d = 0; d < 8; d++) Y[d] = msr[d] + X[d];
    {
        float mu = 0.f;
#pragma unroll
        for (int d = 0; d < 8; d++) mu += Y[d];
        mu *= 0.125f;
        float var = 0.f;
#pragma unroll
        for (int d = 0; d < 8; d++) { float tt = Y[d] - mu; var += tt * tt; }
        var *= 0.125f;
        float inv = rsqrtf(var + 1e-5f);
#pragma unroll
        for (int d = 0; d < 8; d++) Z[d] = (Y[d] - mu) * inv * sl2s[d] + sl2b[d];
    }

    float f1[8];
#pragma unroll
    for (int e = 0; e < 8; e++) {
        float a = sb1[e];
#pragma unroll
        for (int d = 0; d < 8; d++) a += Z[d] * sw1[d * 8 + e];
        f1[e] = 0.5f * a * (1.0f + erff(a * 0.70710678118654752f));
    }

    float p0 = 0.f, p1 = 0.f;
#pragma unroll
    for (int d = 0; d < 8; d++) {
        float a = sb2[d];
#pragma unroll
        for (int e = 0; e < 8; e++) a += f1[e] * sw2[e * 8 + d];
        float xf = a + Y[d];
        p0 += xf * g_W12[(l * 8 + d) * 2];
        p1 += xf * g_W12[(l * 8 + d) * 2 + 1];
    }

#pragma unroll
    for (int off = 16; off > 0; off >>= 1) {
        p0 += __shfl_down_sync(0xffffffffu, p0, off);
        p1 += __shfl_down_sync(0xffffffffu, p1, off);
    }
    if ((l & 31) == 0) { sRed[l >> 5][0] = p0; sRed[l >> 5][1] = p1; }
    __syncthreads();
    if (l == 0) {
        float o0 = g_ob[0], o1 = g_ob[1];
#pragma unroll
        for (int ww = 0; ww < 8; ww++) { o0 += sRed[ww][0]; o1 += sRed[ww][1]; }
        out[b * 2 + 0] = o0;
        out[b * 2 + 1] = o1;
    }
}

// ---------------- launch --------------------------------------------------
extern "C" void kernel_launch(void* const* d_in, const int* in_sizes, int n_in,
                              void* d_out, int out_size) {
    const float* x      = (const float*)d_in[0];
    const float* fc_w   = (const float*)d_in[1];
    const float* fc_b   = (const float*)d_in[2];
    const float* ln1_s  = (const float*)d_in[3];
    const float* ln1_b  = (const float*)d_in[4];
    const float* ln2_s  = (const float*)d_in[5];
    const float* ln2_b  = (const float*)d_in[6];
    const float* Wq     = (const float*)d_in[7];
    const float* Wk     = (const float*)d_in[8];
    const float* Wv     = (const float*)d_in[9];
    const float* Wg     = (const float*)d_in[10];
    const float* Wo     = (const float*)d_in[11];
    const float* gn_w   = (const float*)d_in[12];
    const float* gn_b   = (const float*)d_in[13];
    const float* ffn_w1 = (const float*)d_in[14];
    const float* ffn_b1 = (const float*)d_in[15];
    const float* ffn_w2 = (const float*)d_in[16];
    const float* ffn_b2 = (const float*)d_in[17];
    const float* li1_w  = (const float*)d_in[18];
    const float* li1_b  = (const float*)d_in[19];
    const float* li2_w  = (const float*)d_in[20];
    const float* li2_b  = (const float*)d_in[21];

    cudaFuncSetAttribute(k_gemm, cudaFuncAttributeMaxDynamicSharedMemorySize, SMEM_BYTES);

    dim3 gA(128, 24);
    k_convA<<<gA, 256>>>(x);
    k_w12<<<NDIM + 1, 256>>>(li1_w, li1_b, li2_w, li2_b);
    dim3 gg(NDIM / BN, KSPLIT);
    k_gemm<<<gg, 256, SMEM_BYTES>>>(fc_w);
    k_fuse<<<BATCH, 256>>>(fc_b, ln1_s, ln1_b, ln2_s, ln2_b,
                           Wq, Wk, Wv, Wg, Wo, gn_w, gn_b,
                           ffn_w1, ffn_b1, ffn_w2, ffn_b2,
                           (float*)d_out);
}

// round 5
// speedup vs baseline: 5.9031x; 1.3388x over previous
#include <cuda_runtime.h>
#include <cuda_fp16.h>
#include <math.h>
#include <stdint.h>

// ---------------- problem constants ----------------
#define BATCH   128
#define KDIM    49152      // 6144 * 8
#define NDIM    2048       // 256 * 8
#define KSPLIT  8
#define KCHUNK  (KDIM / KSPLIT)   // 6144
#define KT      64                 // K per smem stage
#define NC      (KCHUNK / KT)      // 96 chunks per CTA
#define BN      128                // N tile per CTA
#define NTILES  (KDIM / KT)        // 768 A tiles

// ---------------- scratch (device globals; no allocation allowed) ----------
// A pre-converted to fp16, stored as the exact swizzled 16KB smem tile image:
// tile T holds rows m=0..127, 64 fp16 per row (128B), SW128 XOR applied.
__device__ __align__(16) __half g_xA[NTILES * 128 * 64];     // 12.6 MB
__device__ float g_part[KSPLIT * BATCH * NDIM];   // 8 MB split-K partials
__device__ float g_W12[NDIM * 2];                 // collapsed li1_w @ li2_w
__device__ float g_ob[2];                         // collapsed output bias

// ================= PTX helpers (sm_80-era ISA only: safe on compute_103) ====
__device__ __forceinline__ uint32_t smem_u32(const void* p) {
    uint32_t a;
    asm("{ .reg .u64 t; cvta.to.shared.u64 t, %1; cvt.u32.u64 %0, t; }" : "=r"(a) : "l"(p));
    return a;
}
__device__ __forceinline__ void cp_async16(uint32_t dst, const void* src) {
    asm volatile("cp.async.cg.shared.global [%0], [%1], 16;" :: "r"(dst), "l"(src) : "memory");
}
#define CP_COMMIT() asm volatile("cp.async.commit_group;" ::: "memory")
#define CP_WAIT0()  asm volatile("cp.async.wait_group 0;" ::: "memory")

__device__ __forceinline__ void ldsm4(uint32_t* r, uint32_t addr) {
    asm volatile("ldmatrix.sync.aligned.m8n8.x4.shared.b16 {%0,%1,%2,%3}, [%4];"
        : "=r"(r[0]), "=r"(r[1]), "=r"(r[2]), "=r"(r[3]) : "r"(addr));
}
__device__ __forceinline__ void mma_fp16(float* d, const uint32_t* a, const uint32_t* b) {
    asm volatile("mma.sync.aligned.m16n8k16.row.col.f32.f16.f16.f32 "
        "{%0,%1,%2,%3}, {%4,%5,%6,%7}, {%8,%9}, {%0,%1,%2,%3};"
        : "+f"(d[0]), "+f"(d[1]), "+f"(d[2]), "+f"(d[3])
        : "r"(a[0]), "r"(a[1]), "r"(a[2]), "r"(a[3]), "r"(b[0]), "r"(b[1]));
}
__device__ __forceinline__ uint32_t hfpair(float a, float b) {
    __half2 h = __floats2half2_rn(a, b);
    return *reinterpret_cast<uint32_t*>(&h);
}

// ---------------- kernel 1: transpose + fp16 convert + tile-swizzle ---------
// x (B=128, 8, 6144): logical xT[m][kglob] = x[m][(kglob&7)*6144 + (kglob>>3)]
__global__ void __launch_bounds__(256) k_convA(const float* __restrict__ x) {
    int m = blockIdx.x;
    int i = blockIdx.y * 256 + threadIdx.x;
    const float* xp = x + (size_t)m * KDIM + i;
    float v[8];
#pragma unroll
    for (int j = 0; j < 8; j++) v[j] = xp[j * 6144];

    uint32_t hi[4];
#pragma unroll
    for (int j = 0; j < 4; j++) hi[j] = hfpair(v[2 * j], v[2 * j + 1]);

    int T = i >> 3;
    uint32_t off = (uint32_t)T * 16384 + (uint32_t)m * 128
                 + ((((uint32_t)i & 7) << 4) ^ (((uint32_t)m & 7) << 4));
    *reinterpret_cast<uint4*>(reinterpret_cast<char*>(g_xA) + off) =
        make_uint4(hi[0], hi[1], hi[2], hi[3]);
}

// ---------------- kernel 2: W12 = li1_w @ li2_w (2048x2), ob ----------------
__global__ void k_w12(const float* __restrict__ li1_w, const float* __restrict__ li1_b,
                      const float* __restrict__ li2_w, const float* __restrict__ li2_b) {
    int j = blockIdx.x;
    int t = threadIdx.x;
    __shared__ float red0[256];
    __shared__ float red1[256];
    const float* row = (j < NDIM) ? (li1_w + (size_t)j * 1000) : li1_b;
    float a0 = 0.f, a1 = 0.f;
    for (int p = t; p < 1000; p += 256) {
        float w = row[p];
        a0 += w * li2_w[2 * p];
        a1 += w * li2_w[2 * p + 1];
    }
    red0[t] = a0; red1[t] = a1;
    __syncthreads();
    for (int s = 128; s > 0; s >>= 1) {
        if (t < s) { red0[t] += red0[t + s]; red1[t] += red1[t + s]; }
        __syncthreads();
    }
    if (t == 0) {
        if (j < NDIM) { g_W12[2 * j] = red0[0]; g_W12[2 * j + 1] = red1[0]; }
        else          { g_ob[0] = red0[0] + li2_b[0]; g_ob[1] = red1[0] + li2_b[1]; }
    }
}

// ---------------- kernel 3: fp16 single-pass split-K GEMM via mma.sync ------
// grid (16, 8): x = N-tile (128 cols), y = K-split. 256 threads = 8 warps (2m x 4n).
// SMEM per buffer (32KB): A[16K] B[16K]; 2 buffers.
#define BUF_BYTES  32768
#define SMEM_BYTES (2 * BUF_BYTES)

__global__ void __launch_bounds__(256, 1) k_gemm(const float* __restrict__ fc_w) {
    extern __shared__ __align__(1024) char smem[];
    const uint32_t sb = smem_u32(smem);
    const int t   = threadIdx.x;
    const int w   = t >> 5;
    const int l   = t & 31;
    const int wm  = w >> 2;          // 0..1  (64 rows each)
    const int wn  = w & 3;           // 0..3  (32 cols each)
    const int nbase = blockIdx.x * BN;
    const int s     = blockIdx.y;

    // per-thread ldmatrix address components
    uint32_t aoff[4], amask[4];
#pragma unroll
    for (int mt = 0; mt < 4; mt++) {
        int row = wm * 64 + mt * 16 + (l & 15);
        aoff[mt]  = (uint32_t)row * 128;
        amask[mt] = ((uint32_t)row & 7) << 4;
    }
    uint32_t boff[2], bmask[2];
#pragma unroll
    for (int bt = 0; bt < 2; bt++) {
        int n = wn * 32 + bt * 16 + (l & 15);
        boff[bt]  = (uint32_t)n * 128;
        bmask[bt] = ((uint32_t)n & 7) << 4;
    }
    const uint32_t lcol = ((uint32_t)l >> 4) << 4;   // 0 or 16

    // B load/store lane mapping (conflict-free swizzled STS.64)
    int bn[2], bkq[4];
#pragma unroll
    for (int ih = 0; ih < 2; ih++) bn[ih] = (l & 7) | (w << 3) | (ih << 6);
#pragma unroll
    for (int il = 0; il < 4; il++) bkq[il] = (l >> 3) | (il << 2);

    float acc[64];
#pragma unroll
    for (int q = 0; q < 64; q++) acc[q] = 0.f;

    float bst[8][4];   // staged B fp32 for next chunk

    // ---- prologue: A(0) cp.async + B(0) load/convert/store ----
    {
        int T = s * NC + 0;
        const char* srch = reinterpret_cast<const char*>(g_xA) + (size_t)T * 16384 + t * 16;
#pragma unroll
        for (int i = 0; i < 4; i++)
            cp_async16(sb + t * 16 + i * 4096, srch + i * 4096);
        CP_COMMIT();
        int kb = s * KCHUNK;
#pragma unroll
        for (int i = 0; i < 8; i++) {
            int n = bn[i >> 2], kq = bkq[i & 3];
            const float* src = fc_w + (size_t)(kb + kq * 4) * NDIM + nbase + n;
#pragma unroll
            for (int e = 0; e < 4; e++) bst[i][e] = src[(size_t)e * NDIM];
        }
#pragma unroll
        for (int i = 0; i < 8; i++) {
            int n = bn[i >> 2], kq = bkq[i & 3];
            uint32_t sa = (uint32_t)n * 128 + (((uint32_t)kq * 8) ^ (((uint32_t)n & 7) << 4));
            *reinterpret_cast<uint2*>(smem + 16384 + sa) =
                make_uint2(hfpair(bst[i][0], bst[i][1]), hfpair(bst[i][2], bst[i][3]));
        }
    }

    // ---- main loop ----
    for (int c = 0; c < NC; ++c) {
        const uint32_t cbuf = sb + (uint32_t)(c & 1) * BUF_BYTES;
        const uint32_t nbuf = sb + (uint32_t)((c + 1) & 1) * BUF_BYTES;

        // 1. issue B(c+1) global loads (latency hidden behind compute)
        if (c + 1 < NC) {
            int kb = s * KCHUNK + (c + 1) * KT;
#pragma unroll
            for (int i = 0; i < 8; i++) {
                int n = bn[i >> 2], kq = bkq[i & 3];
                const float* src = fc_w + (size_t)(kb + kq * 4) * NDIM + nbase + n;
#pragma unroll
                for (int e = 0; e < 4; e++) bst[i][e] = src[(size_t)e * NDIM];
            }
        }

        // 2. own A(c) cp.async done; publish, retire old reads
        CP_WAIT0();
        __syncthreads();

        // 3. issue A(c+1) cp.async into the other buffer
        if (c + 1 < NC) {
            int T = s * NC + c + 1;
            const char* srch = reinterpret_cast<const char*>(g_xA) + (size_t)T * 16384 + t * 16;
#pragma unroll
            for (int i = 0; i < 4; i++)
                cp_async16(nbuf + t * 16 + i * 4096, srch + i * 4096);
            CP_COMMIT();
        }

        // 4. compute chunk c: 4 k-steps x (6 ldmatrix + 16 mma)
        const uint32_t Ah = cbuf, Bh = cbuf + 16384;
#pragma unroll
        for (int ks = 0; ks < 4; ks++) {
            const uint32_t kcol = (uint32_t)(ks * 32) + lcol;
            uint32_t ah[4][4], bh[4][2];
#pragma unroll
            for (int mt = 0; mt < 4; mt++)
                ldsm4(ah[mt], Ah + aoff[mt] + (kcol ^ amask[mt]));
#pragma unroll
            for (int bt = 0; bt < 2; bt++) {
                uint32_t r[4];
                ldsm4(r, Bh + boff[bt] + (kcol ^ bmask[bt]));
                bh[2 * bt][0] = r[0]; bh[2 * bt][1] = r[2];
                bh[2 * bt + 1][0] = r[1]; bh[2 * bt + 1][1] = r[3];
            }
#pragma unroll
            for (int mt = 0; mt < 4; mt++)
#pragma unroll
                for (int nt = 0; nt < 4; nt++)
                    mma_fp16(acc + (mt * 4 + nt) * 4, ah[mt], bh[nt]);
        }

        // 5. convert + store B(c+1) into the other buffer
        if (c + 1 < NC) {
#pragma unroll
            for (int i = 0; i < 8; i++) {
                int n = bn[i >> 2], kq = bkq[i & 3];
                uint32_t sa = (uint32_t)n * 128 + (((uint32_t)kq * 8) ^ (((uint32_t)n & 7) << 4));
                char* bp = smem + (nbuf - sb);
                *reinterpret_cast<uint2*>(bp + 16384 + sa) =
                    make_uint2(hfpair(bst[i][0], bst[i][1]), hfpair(bst[i][2], bst[i][3]));
            }
        }
    }

    // ---- epilogue: write partials ----
    float* op = g_part + (size_t)s * BATCH * NDIM;
#pragma unroll
    for (int mt = 0; mt < 4; mt++) {
        int m = wm * 64 + mt * 16 + (l >> 2);
#pragma unroll
        for (int nt = 0; nt < 4; nt++) {
            int n = nbase + wn * 32 + nt * 8 + (l & 3) * 2;
            const float* d = acc + (mt * 4 + nt) * 4;
            *reinterpret_cast<float2*>(op + (size_t)m * NDIM + n)       = make_float2(d[0], d[1]);
            *reinterpret_cast<float2*>(op + (size_t)(m + 8) * NDIM + n) = make_float2(d[2], d[3]);
        }
    }
}

// ---------------- kernel 4: fused per-batch pipeline -------------------------
__global__ void __launch_bounds__(256) k_fuse(
    const float* __restrict__ fc_b,
    const float* __restrict__ ln1_s, const float* __restrict__ ln1_b,
    const float* __restrict__ ln2_s, const float* __restrict__ ln2_b,
    const float* __restrict__ Wq, const float* __restrict__ Wk, const float* __restrict__ Wv,
    const float* __restrict__ Wg, const float* __restrict__ Wo,
    const float* __restrict__ gn_w, const float* __restrict__ gn_b,
    const float* __restrict__ w1, const float* __restrict__ b1,
    const float* __restrict__ w2, const float* __restrict__ b2,
    float* __restrict__ out)
{
    int b = blockIdx.x;
    int l = threadIdx.x;

    __shared__ float4 sK4[256];
    __shared__ float4 sV4[256][2];
    __shared__ float  sGPinv[256];
    __shared__ float  sRed[8][2];
    __shared__ float  swq[64], swk[64], swv[128], swg[128], swo[128];
    __shared__ float  sgnw[16], sgnb[16], sw1[64], sw2[64];
    __shared__ float  sb1[8], sb2[8], sl1s[8], sl1b[8], sl2s[8], sl2b[8];

    if (l < 64)  { swq[l] = Wq[l]; swk[l] = Wk[l]; sw1[l] = w1[l]; sw2[l] = w2[l]; }
    if (l < 128) { swv[l] = Wv[l]; swg[l] = Wg[l]; swo[l] = Wo[l]; }
    if (l < 16)  { sgnw[l] = gn_w[l]; sgnb[l] = gn_b[l]; }
    if (l < 8)   { sb1[l] = b1[l]; sb2[l] = b2[l];
                   sl1s[l] = ln1_s[l]; sl1b[l] = ln1_b[l];
                   sl2s[l] = ln2_s[l]; sl2b[l] = ln2_b[l]; }

    float X[8];
#pragma unroll
    for (int d = 0; d < 8; d++) {
        float h = fc_b[l * 8 + d];
#pragma unroll
        for (int s = 0; s < KSPLIT; s++)
            h += g_part[s * (BATCH * NDIM) + b * NDIM + l * 8 + d];
        X[d] = h;
    }
    __syncthreads();

    float Xn[8];
    {
        float mu = 0.f;
#pragma unroll
        for (int d = 0; d < 8; d++) mu += X[d];
        mu *= 0.125f;
        float var = 0.f;
#pragma unroll
        for (int d = 0; d < 8; d++) { float tt = X[d] - mu; var += tt * tt; }
        var *= 0.125f;
        float inv = rsqrtf(var + 1e-5f);
#pragma unroll
        for (int d = 0; d < 8; d++) Xn[d] = (X[d] - mu) * inv * sl1s[d] + sl1b[d];
    }

    float fl = (float)l;
    float c0 = cosf(fl), s0 = sinf(fl);
    float c1 = cosf(fl * 0.01f), s1 = sinf(fl * 0.01f);
    float e0 = exp2f(fl * (-1.807354922f / 512.0f));
    float e1 = exp2f(fl * (-0.637429921f / 512.0f));
    float ie0 = 1.0f / e0, ie1 = 1.0f / e1;

    float yc[16];
    // log2(gamma) for the two heads
    const float l2g[2] = { -0.04580368961f, -0.00281970977f };

#pragma unroll
    for (int hd = 0; hd < 2; ++hd) {
        const float* wq = swq + hd * 32;
        const float* wk = swk + hd * 32;
        const float* wv = swv + hd * 64;

        float q0 = 0, q1 = 0, q2 = 0, q3 = 0, k0 = 0, k1 = 0, k2 = 0, k3 = 0;
#pragma unroll
        for (int d = 0; d < 8; d++) {
            float xv = Xn[d];
            q0 += xv * wq[d * 4 + 0]; q1 += xv * wq[d * 4 + 1];
            q2 += xv * wq[d * 4 + 2]; q3 += xv * wq[d * 4 + 3];
            k0 += xv * wk[d * 4 + 0]; k1 += xv * wk[d * 4 + 1];
            k2 += xv * wk[d * 4 + 2]; k3 += xv * wk[d * 4 + 3];
        }
        float Q0 = (q0 * c0 - q1 * s0) * e0;
        float Q1 = (q1 * c0 + q0 * s0) * e0;
        float Q2 = (q2 * c1 - q3 * s1) * e1;
        float Q3 = (q3 * c1 + q2 * s1) * e1;
        float K0 = (k0 * c0 - k1 * s0) * ie0;
        float K1 = (k1 * c0 + k0 * s0) * ie0;
        float K2 = (k2 * c1 - k3 * s1) * ie1;
        float K3 = (k3 * c1 + k2 * s1) * ie1;

        float V[8];
#pragma unroll
        for (int f = 0; f < 8; f++) {
            float a = 0.f;
#pragma unroll
            for (int d = 0; d < 8; d++) a += Xn[d] * wv[d * 8 + f];
            V[f] = a;
        }

        sK4[l] = make_float4(K0, K1, K2, K3);
        sV4[l][0] = make_float4(V[0], V[1], V[2], V[3]);
        sV4[l][1] = make_float4(V[4], V[5], V[6], V[7]);
        sGPinv[l] = exp2f(-fl * l2g[hd]);
        float gpn = exp2f(fl * l2g[hd]);
        __syncthreads();

        float a0 = 0, a1 = 0, a2 = 0, a3 = 0, a4 = 0, a5 = 0, a6 = 0, a7 = 0;
        for (int m = 0; m <= l; ++m) {
            float4 kv = sK4[m];
            float wgt = (Q0 * kv.x + Q1 * kv.y + Q2 * kv.z + Q3 * kv.w) * gpn * sGPinv[m];
            float4 v0 = sV4[m][0], v1 = sV4[m][1];
            a0 += wgt * v0.x; a1 += wgt * v0.y; a2 += wgt * v0.z; a3 += wgt * v0.w;
            a4 += wgt * v1.x; a5 += wgt * v1.y; a6 += wgt * v1.z; a7 += wgt * v1.w;
        }
        yc[hd * 8 + 0] = a0; yc[hd * 8 + 1] = a1; yc[hd * 8 + 2] = a2; yc[hd * 8 + 3] = a3;
        yc[hd * 8 + 4] = a4; yc[hd * 8 + 5] = a5; yc[hd * 8 + 6] = a6; yc[hd * 8 + 7] = a7;
        __syncthreads();
    }

    float gn[16];
#pragma unroll
    for (int g = 0; g < 2; g++) {
        float mu = 0.f;
#pragma unroll
        for (int jj = 0; jj < 8; jj++) mu += yc[g * 8 + jj];
        mu *= 0.125f;
        float var = 0.f;
#pragma unroll
        for (int jj = 0; jj < 8; jj++) { float tt = yc[g * 8 + jj] - mu; var += tt * tt; }
        var *= 0.125f;
        float inv = rsqrtf(var + 1e-5f);
#pragma unroll
        for (int jj = 0; jj < 8; jj++)
            gn[g * 8 + jj] = (yc[g * 8 + jj] - mu) * inv * sgnw[g * 8 + jj] + sgnb[g * 8 + jj];
    }

    float msr[8] = {0, 0, 0, 0, 0, 0, 0, 0};
#pragma unroll
    for (int j = 0; j < 16; j++) {
        float gt = 0.f;
#pragma unroll
        for (int d = 0; d < 8; d++) gt += Xn[d] * swg[d * 16 + j];
        gt = gt / (1.0f + expf(-gt));
        float val = gt * gn[j];
#pragma unroll
        for (int d = 0; d < 8; d++) msr[d] += val * swo[j * 8 + d];
    }

    float Y[8], Z[8];
#pragma unroll
    for (int d = 0; d < 8; d++) Y[d] = msr[d] + X[d];
    {
        float mu = 0.f;
#pragma unroll
        for (int d = 0; d < 8; d++) mu += Y[d];
        mu *= 0.125f;
        float var = 0.f;
#pragma unroll
        for (int d = 0; d < 8; d++) { float tt = Y[d] - mu; var += tt * tt; }
        var *= 0.125f;
        float inv = rsqrtf(var + 1e-5f);
#pragma unroll
        for (int d = 0; d < 8; d++) Z[d] = (Y[d] - mu) * inv * sl2s[d] + sl2b[d];
    }

    float f1[8];
#pragma unroll
    for (int e = 0; e < 8; e++) {
        float a = sb1[e];
#pragma unroll
        for (int d = 0; d < 8; d++) a += Z[d] * sw1[d * 8 + e];
        f1[e] = 0.5f * a * (1.0f + erff(a * 0.70710678118654752f));
    }

    float p0 = 0.f, p1 = 0.f;
#pragma unroll
    for (int d = 0; d < 8; d++) {
        float a = sb2[d];
#pragma unroll
        for (int e = 0; e < 8; e++) a += f1[e] * sw2[e * 8 + d];
        float xf = a + Y[d];
        p0 += xf * g_W12[(l * 8 + d) * 2];
        p1 += xf * g_W12[(l * 8 + d) * 2 + 1];
    }

#pragma unroll
    for (int off = 16; off > 0; off >>= 1) {
        p0 += __shfl_down_sync(0xffffffffu, p0, off);
        p1 += __shfl_down_sync(0xffffffffu, p1, off);
    }
    if ((l & 31) == 0) { sRed[l >> 5][0] = p0; sRed[l >> 5][1] = p1; }
    __syncthreads();
    if (l == 0) {
        float o0 = g_ob[0], o1 = g_ob[1];
#pragma unroll
        for (int ww = 0; ww < 8; ww++) { o0 += sRed[ww][0]; o1 += sRed[ww][1]; }
        out[b * 2 + 0] = o0;
        out[b * 2 + 1] = o1;
    }
}

// ---------------- launch --------------------------------------------------
extern "C" void kernel_launch(void* const* d_in, const int* in_sizes, int n_in,
                              void* d_out, int out_size) {
    const float* x      = (const float*)d_in[0];
    const float* fc_w   = (const float*)d_in[1];
    const float* fc_b   = (const float*)d_in[2];
    const float* ln1_s  = (const float*)d_in[3];
    const float* ln1_b  = (const float*)d_in[4];
    const float* ln2_s  = (const float*)d_in[5];
    const float* ln2_b  = (const float*)d_in[6];
    const float* Wq     = (const float*)d_in[7];
    const float* Wk     = (const float*)d_in[8];
    const float* Wv     = (const float*)d_in[9];
    const float* Wg     = (const float*)d_in[10];
    const float* Wo     = (const float*)d_in[11];
    const float* gn_w   = (const float*)d_in[12];
    const float* gn_b   = (const float*)d_in[13];
    const float* ffn_w1 = (const float*)d_in[14];
    const float* ffn_b1 = (const float*)d_in[15];
    const float* ffn_w2 = (const float*)d_in[16];
    const float* ffn_b2 = (const float*)d_in[17];
    const float* li1_w  = (const float*)d_in[18];
    const float* li1_b  = (const float*)d_in[19];
    const float* li2_w  = (const float*)d_in[20];
    const float* li2_b  = (const float*)d_in[21];

    cudaFuncSetAttribute(k_gemm, cudaFuncAttributeMaxDynamicSharedMemorySize, SMEM_BYTES);

    dim3 gA(128, 24);
    k_convA<<<gA, 256>>>(x);
    k_w12<<<NDIM + 1, 256>>>(li1_w, li1_b, li2_w, li2_b);
    dim3 gg(NDIM / BN, KSPLIT);
    k_gemm<<<gg, 256, SMEM_BYTES>>>(fc_w);
    k_fuse<<<BATCH, 256>>>(fc_b, ln1_s, ln1_b, ln2_s, ln2_b,
                           Wq, Wk, Wv, Wg, Wo, gn_w, gn_b,
                           ffn_w1, ffn_b1, ffn_w2, ffn_b2,
                           (float*)d_out);
}

// round 6
// speedup vs baseline: 6.1439x; 1.0408x over previous
#include <cuda_runtime.h>
#include <cuda_fp16.h>
#include <math.h>
#include <stdint.h>

// ---------------- problem constants ----------------
#define BATCH   128
#define KDIM    49152      // 6144 * 8
#define NDIM    2048       // 256 * 8
#define KSPLIT  8
#define KCHUNK  (KDIM / KSPLIT)   // 6144
#define KT      64                 // K per smem stage
#define NC      (KCHUNK / KT)      // 96 chunks per CTA
#define BN      128                // N tile per CTA
#define NTILES  (KDIM / KT)        // 768 A tiles

// ---------------- scratch (device globals; no allocation allowed) ----------
__device__ __align__(16) __half g_xA[NTILES * 128 * 64];     // 12.6 MB
__device__ __align__(16) float g_part[KSPLIT * BATCH * NDIM];   // 8 MB
__device__ float g_W12[NDIM * 2];
__device__ float g_ob[2];

// ================= PTX helpers (sm_80-era ISA only: safe on compute_103) ====
__device__ __forceinline__ uint32_t smem_u32(const void* p) {
    uint32_t a;
    asm("{ .reg .u64 t; cvta.to.shared.u64 t, %1; cvt.u32.u64 %0, t; }" : "=r"(a) : "l"(p));
    return a;
}
__device__ __forceinline__ void cp_async16(uint32_t dst, const void* src) {
    asm volatile("cp.async.cg.shared.global [%0], [%1], 16;" :: "r"(dst), "l"(src) : "memory");
}
#define CP_COMMIT() asm volatile("cp.async.commit_group;" ::: "memory")
#define CP_WAIT0()  asm volatile("cp.async.wait_group 0;" ::: "memory")

__device__ __forceinline__ void ldsm4(uint32_t* r, uint32_t addr) {
    asm volatile("ldmatrix.sync.aligned.m8n8.x4.shared.b16 {%0,%1,%2,%3}, [%4];"
        : "=r"(r[0]), "=r"(r[1]), "=r"(r[2]), "=r"(r[3]) : "r"(addr));
}
__device__ __forceinline__ void mma_fp16(float* d, const uint32_t* a, const uint32_t* b) {
    asm volatile("mma.sync.aligned.m16n8k16.row.col.f32.f16.f16.f32 "
        "{%0,%1,%2,%3}, {%4,%5,%6,%7}, {%8,%9}, {%0,%1,%2,%3};"
        : "+f"(d[0]), "+f"(d[1]), "+f"(d[2]), "+f"(d[3])
        : "r"(a[0]), "r"(a[1]), "r"(a[2]), "r"(a[3]), "r"(b[0]), "r"(b[1]));
}
__device__ __forceinline__ uint32_t hfpair(float a, float b) {
    __half2 h = __floats2half2_rn(a, b);
    return *reinterpret_cast<uint32_t*>(&h);
}

// ---------------- kernel 1: merged prep (convA + W12 collapse) ---------------
// blocks [0, 3072): transpose + fp16 convert + tile swizzle of x
// blocks [3072, 5121): W12 = li1_w @ li2_w rows (+ bias row)
__global__ void __launch_bounds__(256) k_prep(
    const float* __restrict__ x,
    const float* __restrict__ li1_w, const float* __restrict__ li1_b,
    const float* __restrict__ li2_w, const float* __restrict__ li2_b)
{
    int bx = blockIdx.x;
    if (bx < 3072) {
        int m  = bx & 127;
        int yb = bx >> 7;            // 0..23
        int i  = yb * 256 + threadIdx.x;
        const float* xp = x + (size_t)m * KDIM + i;
        float v[8];
#pragma unroll
        for (int j = 0; j < 8; j++) v[j] = xp[j * 6144];
        uint32_t hi[4];
#pragma unroll
        for (int j = 0; j < 4; j++) hi[j] = hfpair(v[2 * j], v[2 * j + 1]);
        int T = i >> 3;
        uint32_t off = (uint32_t)T * 16384 + (uint32_t)m * 128
                     + ((((uint32_t)i & 7) << 4) ^ (((uint32_t)m & 7) << 4));
        *reinterpret_cast<uint4*>(reinterpret_cast<char*>(g_xA) + off) =
            make_uint4(hi[0], hi[1], hi[2], hi[3]);
    } else {
        int j = bx - 3072;           // 0..2048
        int t = threadIdx.x;
        __shared__ float red0[256];
        __shared__ float red1[256];
        const float* row = (j < NDIM) ? (li1_w + (size_t)j * 1000) : li1_b;
        float a0 = 0.f, a1 = 0.f;
        for (int p = t; p < 1000; p += 256) {
            float w = row[p];
            a0 += w * li2_w[2 * p];
            a1 += w * li2_w[2 * p + 1];
        }
        red0[t] = a0; red1[t] = a1;
        __syncthreads();
        for (int s = 128; s > 0; s >>= 1) {
            if (t < s) { red0[t] += red0[t + s]; red1[t] += red1[t + s]; }
            __syncthreads();
        }
        if (t == 0) {
            if (j < NDIM) { g_W12[2 * j] = red0[0]; g_W12[2 * j + 1] = red1[0]; }
            else          { g_ob[0] = red0[0] + li2_b[0]; g_ob[1] = red1[0] + li2_b[1]; }
        }
    }
}

// ---------------- kernel 2: fp16 single-pass split-K GEMM via mma.sync ------
#define BUF_BYTES  32768
#define SMEM_BYTES (2 * BUF_BYTES)

__global__ void __launch_bounds__(256, 1) k_gemm(const float* __restrict__ fc_w) {
    extern __shared__ __align__(1024) char smem[];
    const uint32_t sb = smem_u32(smem);
    const int t   = threadIdx.x;
    const int w   = t >> 5;
    const int l   = t & 31;
    const int wm  = w >> 2;
    const int wn  = w & 3;
    const int nbase = blockIdx.x * BN;
    const int s     = blockIdx.y;

    uint32_t aoff[4], amask[4];
#pragma unroll
    for (int mt = 0; mt < 4; mt++) {
        int row = wm * 64 + mt * 16 + (l & 15);
        aoff[mt]  = (uint32_t)row * 128;
        amask[mt] = ((uint32_t)row & 7) << 4;
    }
    uint32_t boff[2], bmask[2];
#pragma unroll
    for (int bt = 0; bt < 2; bt++) {
        int n = wn * 32 + bt * 16 + (l & 15);
        boff[bt]  = (uint32_t)n * 128;
        bmask[bt] = ((uint32_t)n & 7) << 4;
    }
    const uint32_t lcol = ((uint32_t)l >> 4) << 4;

    int bn[2], bkq[4];
#pragma unroll
    for (int ih = 0; ih < 2; ih++) bn[ih] = (l & 7) | (w << 3) | (ih << 6);
#pragma unroll
    for (int il = 0; il < 4; il++) bkq[il] = (l >> 3) | (il << 2);

    float acc[64];
#pragma unroll
    for (int q = 0; q < 64; q++) acc[q] = 0.f;

    float bst[8][4];

    {
        int T = s * NC + 0;
        const char* srch = reinterpret_cast<const char*>(g_xA) + (size_t)T * 16384 + t * 16;
#pragma unroll
        for (int i = 0; i < 4; i++)
            cp_async16(sb + t * 16 + i * 4096, srch + i * 4096);
        CP_COMMIT();
        int kb = s * KCHUNK;
#pragma unroll
        for (int i = 0; i < 8; i++) {
            int n = bn[i >> 2], kq = bkq[i & 3];
            const float* src = fc_w + (size_t)(kb + kq * 4) * NDIM + nbase + n;
#pragma unroll
            for (int e = 0; e < 4; e++) bst[i][e] = src[(size_t)e * NDIM];
        }
#pragma unroll
        for (int i = 0; i < 8; i++) {
            int n = bn[i >> 2], kq = bkq[i & 3];
            uint32_t sa = (uint32_t)n * 128 + (((uint32_t)kq * 8) ^ (((uint32_t)n & 7) << 4));
            *reinterpret_cast<uint2*>(smem + 16384 + sa) =
                make_uint2(hfpair(bst[i][0], bst[i][1]), hfpair(bst[i][2], bst[i][3]));
        }
    }

    for (int c = 0; c < NC; ++c) {
        const uint32_t cbuf = sb + (uint32_t)(c & 1) * BUF_BYTES;
        const uint32_t nbuf = sb + (uint32_t)((c + 1) & 1) * BUF_BYTES;

        if (c + 1 < NC) {
            int kb = s * KCHUNK + (c + 1) * KT;
#pragma unroll
            for (int i = 0; i < 8; i++) {
                int n = bn[i >> 2], kq = bkq[i & 3];
                const float* src = fc_w + (size_t)(kb + kq * 4) * NDIM + nbase + n;
#pragma unroll
                for (int e = 0; e < 4; e++) bst[i][e] = src[(size_t)e * NDIM];
            }
        }

        CP_WAIT0();
        __syncthreads();

        if (c + 1 < NC) {
            int T = s * NC + c + 1;
            const char* srch = reinterpret_cast<const char*>(g_xA) + (size_t)T * 16384 + t * 16;
#pragma unroll
            for (int i = 0; i < 4; i++)
                cp_async16(nbuf + t * 16 + i * 4096, srch + i * 4096);
            CP_COMMIT();
        }

        const uint32_t Ah = cbuf, Bh = cbuf + 16384;
#pragma unroll
        for (int ks = 0; ks < 4; ks++) {
            const uint32_t kcol = (uint32_t)(ks * 32) + lcol;
            uint32_t ah[4][4], bh[4][2];
#pragma unroll
            for (int mt = 0; mt < 4; mt++)
                ldsm4(ah[mt], Ah + aoff[mt] + (kcol ^ amask[mt]));
#pragma unroll
            for (int bt = 0; bt < 2; bt++) {
                uint32_t r[4];
                ldsm4(r, Bh + boff[bt] + (kcol ^ bmask[bt]));
                bh[2 * bt][0] = r[0]; bh[2 * bt][1] = r[2];
                bh[2 * bt + 1][0] = r[1]; bh[2 * bt + 1][1] = r[3];
            }
#pragma unroll
            for (int mt = 0; mt < 4; mt++)
#pragma unroll
                for (int nt = 0; nt < 4; nt++)
                    mma_fp16(acc + (mt * 4 + nt) * 4, ah[mt], bh[nt]);
        }

        if (c + 1 < NC) {
#pragma unroll
            for (int i = 0; i < 8; i++) {
                int n = bn[i >> 2], kq = bkq[i & 3];
                uint32_t sa = (uint32_t)n * 128 + (((uint32_t)kq * 8) ^ (((uint32_t)n & 7) << 4));
                char* bp = smem + (nbuf - sb);
                *reinterpret_cast<uint2*>(bp + 16384 + sa) =
                    make_uint2(hfpair(bst[i][0], bst[i][1]), hfpair(bst[i][2], bst[i][3]));
            }
        }
    }

    float* op = g_part + (size_t)s * BATCH * NDIM;
#pragma unroll
    for (int mt = 0; mt < 4; mt++) {
        int m = wm * 64 + mt * 16 + (l >> 2);
#pragma unroll
        for (int nt = 0; nt < 4; nt++) {
            int n = nbase + wn * 32 + nt * 8 + (l & 3) * 2;
            const float* d = acc + (mt * 4 + nt) * 4;
            *reinterpret_cast<float2*>(op + (size_t)m * NDIM + n)       = make_float2(d[0], d[1]);
            *reinterpret_cast<float2*>(op + (size_t)(m + 8) * NDIM + n) = make_float2(d[2], d[3]);
        }
    }
}

// ---------------- kernel 3: fused per-batch pipeline, 512 thr (2 head grps) --
__global__ void __launch_bounds__(512) k_fuse(
    const float* __restrict__ fc_b,
    const float* __restrict__ ln1_s, const float* __restrict__ ln1_b,
    const float* __restrict__ ln2_s, const float* __restrict__ ln2_b,
    const float* __restrict__ Wq, const float* __restrict__ Wk, const float* __restrict__ Wv,
    const float* __restrict__ Wg, const float* __restrict__ Wo,
    const float* __restrict__ gn_w, const float* __restrict__ gn_b,
    const float* __restrict__ w1, const float* __restrict__ b1,
    const float* __restrict__ w2, const float* __restrict__ b2,
    float* __restrict__ out)
{
    int b   = blockIdx.x;
    int tid = threadIdx.x;
    int l   = tid & 255;
    int hg  = tid >> 8;          // head group 0/1

    __shared__ float4 sK4[2][256];
    __shared__ float4 sV4[2][256][2];
    __shared__ float  sGP[2][256];
    __shared__ float  syc[256][17];       // padded rows
    __shared__ float  sRed[8][2];
    __shared__ float  swq[64], swk[64], swv[128], swg[128], swo[128];
    __shared__ float  sgnw[16], sgnb[16], sw1[64], sw2[64];
    __shared__ float  sb1[8], sb2[8], sl1s[8], sl1b[8], sl2s[8], sl2b[8];

    if (tid < 64)  { swq[tid] = Wq[tid]; swk[tid] = Wk[tid]; sw1[tid] = w1[tid]; sw2[tid] = w2[tid]; }
    else if (tid < 192) { int u = tid - 64; swv[u] = Wv[u]; swg[u] = Wg[u]; swo[u] = Wo[u]; }
    else if (tid < 208) { int u = tid - 192; sgnw[u] = gn_w[u]; sgnb[u] = gn_b[u]; }
    else if (tid < 216) { int u = tid - 208; sb1[u] = b1[u]; sb2[u] = b2[u];
                          sl1s[u] = ln1_s[u]; sl1b[u] = ln1_b[u];
                          sl2s[u] = ln2_s[u]; sl2b[u] = ln2_b[u]; }

    // split-K reduce + bias (both groups; redundant but L2-cheap)
    float X[8];
    {
        float4 h0 = *reinterpret_cast<const float4*>(fc_b + l * 8);
        float4 h1 = *reinterpret_cast<const float4*>(fc_b + l * 8 + 4);
        X[0] = h0.x; X[1] = h0.y; X[2] = h0.z; X[3] = h0.w;
        X[4] = h1.x; X[5] = h1.y; X[6] = h1.z; X[7] = h1.w;
#pragma unroll
        for (int s = 0; s < KSPLIT; s++) {
            const float* pp = g_part + (size_t)s * (BATCH * NDIM) + b * NDIM + l * 8;
            float4 p0 = *reinterpret_cast<const float4*>(pp);
            float4 p1 = *reinterpret_cast<const float4*>(pp + 4);
            X[0] += p0.x; X[1] += p0.y; X[2] += p0.z; X[3] += p0.w;
            X[4] += p1.x; X[5] += p1.y; X[6] += p1.z; X[7] += p1.w;
        }
    }
    __syncthreads();   // weights ready

    float Xn[8];
    {
        float mu = 0.f;
#pragma unroll
        for (int d = 0; d < 8; d++) mu += X[d];
        mu *= 0.125f;
        float var = 0.f;
#pragma unroll
        for (int d = 0; d < 8; d++) { float tt = X[d] - mu; var += tt * tt; }
        var *= 0.125f;
        float inv = rsqrtf(var + 1e-5f);
#pragma unroll
        for (int d = 0; d < 8; d++) Xn[d] = (X[d] - mu) * inv * sl1s[d] + sl1b[d];
    }

    float fl = (float)l;
    float c0 = cosf(fl), s0 = sinf(fl);
    float c1 = cosf(fl * 0.01f), s1 = sinf(fl * 0.01f);
    float e0 = exp2f(fl * (-1.807354922f / 512.0f));
    float e1 = exp2f(fl * (-0.637429921f / 512.0f));
    float ie0 = 1.0f / e0, ie1 = 1.0f / e1;

    const float l2g[2] = { -0.04580368961f, -0.00281970977f };

    // ---- this group's head: Q/K/V + retention ----
    {
        const float* wq = swq + hg * 32;
        const float* wk = swk + hg * 32;
        const float* wv = swv + hg * 64;

        float q0 = 0, q1 = 0, q2 = 0, q3 = 0, k0 = 0, k1 = 0, k2 = 0, k3 = 0;
#pragma unroll
        for (int d = 0; d < 8; d++) {
            float xv = Xn[d];
            q0 += xv * wq[d * 4 + 0]; q1 += xv * wq[d * 4 + 1];
            q2 += xv * wq[d * 4 + 2]; q3 += xv * wq[d * 4 + 3];
            k0 += xv * wk[d * 4 + 0]; k1 += xv * wk[d * 4 + 1];
            k2 += xv * wk[d * 4 + 2]; k3 += xv * wk[d * 4 + 3];
        }
        float Q0 = (q0 * c0 - q1 * s0) * e0;
        float Q1 = (q1 * c0 + q0 * s0) * e0;
        float Q2 = (q2 * c1 - q3 * s1) * e1;
        float Q3 = (q3 * c1 + q2 * s1) * e1;
        float K0 = (k0 * c0 - k1 * s0) * ie0;
        float K1 = (k1 * c0 + k0 * s0) * ie0;
        float K2 = (k2 * c1 - k3 * s1) * ie1;
        float K3 = (k3 * c1 + k2 * s1) * ie1;

        float V[8];
#pragma unroll
        for (int f = 0; f < 8; f++) {
            float a = 0.f;
#pragma unroll
            for (int d = 0; d < 8; d++) a += Xn[d] * wv[d * 8 + f];
            V[f] = a;
        }

        sK4[hg][l] = make_float4(K0, K1, K2, K3);
        sV4[hg][l][0] = make_float4(V[0], V[1], V[2], V[3]);
        sV4[hg][l][1] = make_float4(V[4], V[5], V[6], V[7]);
        sGP[hg][l] = exp2f(-fl * l2g[hg]);
        float gpn = exp2f(fl * l2g[hg]);
        __syncthreads();

        float a0 = 0, a1 = 0, a2 = 0, a3 = 0, a4 = 0, a5 = 0, a6 = 0, a7 = 0;
        const float4* kp = sK4[hg];
        const float4 (*vp)[2] = sV4[hg];
        const float* gp = sGP[hg];
        for (int m = 0; m <= l; ++m) {
            float4 kv = kp[m];
            float wgt = (Q0 * kv.x + Q1 * kv.y + Q2 * kv.z + Q3 * kv.w) * gpn * gp[m];
            float4 v0 = vp[m][0], v1 = vp[m][1];
            a0 += wgt * v0.x; a1 += wgt * v0.y; a2 += wgt * v0.z; a3 += wgt * v0.w;
            a4 += wgt * v1.x; a5 += wgt * v1.y; a6 += wgt * v1.z; a7 += wgt * v1.w;
        }
        float* yr = syc[l] + hg * 8;
        yr[0] = a0; yr[1] = a1; yr[2] = a2; yr[3] = a3;
        yr[4] = a4; yr[5] = a5; yr[6] = a6; yr[7] = a7;
    }
    __syncthreads();

    if (hg == 0) {
        float yc[16];
#pragma unroll
        for (int j = 0; j < 16; j++) yc[j] = syc[l][j];

        float gn[16];
#pragma unroll
        for (int g = 0; g < 2; g++) {
            float mu = 0.f;
#pragma unroll
            for (int jj = 0; jj < 8; jj++) mu += yc[g * 8 + jj];
            mu *= 0.125f;
            float var = 0.f;
#pragma unroll
            for (int jj = 0; jj < 8; jj++) { float tt = yc[g * 8 + jj] - mu; var += tt * tt; }
            var *= 0.125f;
            float inv = rsqrtf(var + 1e-5f);
#pragma unroll
            for (int jj = 0; jj < 8; jj++)
                gn[g * 8 + jj] = (yc[g * 8 + jj] - mu) * inv * sgnw[g * 8 + jj] + sgnb[g * 8 + jj];
        }

        float msr[8] = {0, 0, 0, 0, 0, 0, 0, 0};
#pragma unroll
        for (int j = 0; j < 16; j++) {
            float gt = 0.f;
#pragma unroll
            for (int d = 0; d < 8; d++) gt += Xn[d] * swg[d * 16 + j];
            gt = gt / (1.0f + expf(-gt));
            float val = gt * gn[j];
#pragma unroll
            for (int d = 0; d < 8; d++) msr[d] += val * swo[j * 8 + d];
        }

        float Y[8], Z[8];
#pragma unroll
        for (int d = 0; d < 8; d++) Y[d] = msr[d] + X[d];
        {
            float mu = 0.f;
#pragma unroll
            for (int d = 0; d < 8; d++) mu += Y[d];
            mu *= 0.125f;
            float var = 0.f;
#pragma unroll
            for (int d = 0; d < 8; d++) { float tt = Y[d] - mu; var += tt * tt; }
            var *= 0.125f;
            float inv = rsqrtf(var + 1e-5f);
#pragma unroll
            for (int d = 0; d < 8; d++) Z[d] = (Y[d] - mu) * inv * sl2s[d] + sl2b[d];
        }

        float f1[8];
#pragma unroll
        for (int e = 0; e < 8; e++) {
            float a = sb1[e];
#pragma unroll
            for (int d = 0; d < 8; d++) a += Z[d] * sw1[d * 8 + e];
            f1[e] = 0.5f * a * (1.0f + erff(a * 0.70710678118654752f));
        }

        float p0 = 0.f, p1 = 0.f;
#pragma unroll
        for (int d = 0; d < 8; d++) {
            float a = sb2[d];
#pragma unroll
            for (int e = 0; e < 8; e++) a += f1[e] * sw2[e * 8 + d];
            float xf = a + Y[d];
            p0 += xf * g_W12[(l * 8 + d) * 2];
            p1 += xf * g_W12[(l * 8 + d) * 2 + 1];
        }

#pragma unroll
        for (int off = 16; off > 0; off >>= 1) {
            p0 += __shfl_down_sync(0xffffffffu, p0, off);
            p1 += __shfl_down_sync(0xffffffffu, p1, off);
        }
        if ((l & 31) == 0) { sRed[l >> 5][0] = p0; sRed[l >> 5][1] = p1; }
    }
    __syncthreads();
    if (tid == 0) {
        float o0 = g_ob[0], o1 = g_ob[1];
#pragma unroll
        for (int ww = 0; ww < 8; ww++) { o0 += sRed[ww][0]; o1 += sRed[ww][1]; }
        out[b * 2 + 0] = o0;
        out[b * 2 + 1] = o1;
    }
}

// ---------------- launch --------------------------------------------------
extern "C" void kernel_launch(void* const* d_in, const int* in_sizes, int n_in,
                              void* d_out, int out_size) {
    const float* x      = (const float*)d_in[0];
    const float* fc_w   = (const float*)d_in[1];
    const float* fc_b   = (const float*)d_in[2];
    const float* ln1_s  = (const float*)d_in[3];
    const float* ln1_b  = (const float*)d_in[4];
    const float* ln2_s  = (const float*)d_in[5];
    const float* ln2_b  = (const float*)d_in[6];
    const float* Wq     = (const float*)d_in[7];
    const float* Wk     = (const float*)d_in[8];
    const float* Wv     = (const float*)d_in[9];
    const float* Wg     = (const float*)d_in[10];
    const float* Wo     = (const float*)d_in[11];
    const float* gn_w   = (const float*)d_in[12];
    const float* gn_b   = (const float*)d_in[13];
    const float* ffn_w1 = (const float*)d_in[14];
    const float* ffn_b1 = (const float*)d_in[15];
    const float* ffn_w2 = (const float*)d_in[16];
    const float* ffn_b2 = (const float*)d_in[17];
    const float* li1_w  = (const float*)d_in[18];
    const float* li1_b  = (const float*)d_in[19];
    const float* li2_w  = (const float*)d_in[20];
    const float* li2_b  = (const float*)d_in[21];

    cudaFuncSetAttribute(k_gemm, cudaFuncAttributeMaxDynamicSharedMemorySize, SMEM_BYTES);

    k_prep<<<3072 + NDIM + 1, 256>>>(x, li1_w, li1_b, li2_w, li2_b);
    dim3 gg(NDIM / BN, KSPLIT);
    k_gemm<<<gg, 256, SMEM_BYTES>>>(fc_w);
    k_fuse<<<BATCH, 512>>>(fc_b, ln1_s, ln1_b, ln2_s, ln2_b,
                           Wq, Wk, Wv, Wg, Wo, gn_w, gn_b,
                           ffn_w1, ffn_b1, ffn_w2, ffn_b2,
                           (float*)d_out);
}

// round 7
// speedup vs baseline: 6.5921x; 1.0729x over previous
#include <cuda_runtime.h>
#include <cuda_fp16.h>
#include <math.h>
#include <stdint.h>

// ---------------- problem constants ----------------
#define BATCH   128
#define KDIM    49152      // 6144 * 8
#define NDIM    2048       // 256 * 8
#define KSPLIT  9          // 16 x 9 = 144 CTAs ~ one full wave on 148 SMs
#define KT      64         // K per smem stage
#define BN      128        // N tile per CTA
#define NTILES  (KDIM / KT)   // 768 A tiles

// ---------------- scratch (device globals; no allocation allowed) ----------
__device__ __align__(16) __half g_xA[NTILES * 128 * 64];          // 12.6 MB
__device__ __align__(16) float g_part[KSPLIT * BATCH * NDIM];     // 9.4 MB
__device__ float g_W12[NDIM * 2];
__device__ float g_ob[2];

// ================= PTX helpers (sm_80-era ISA only: safe on compute_103) ====
__device__ __forceinline__ uint32_t smem_u32(const void* p) {
    uint32_t a;
    asm("{ .reg .u64 t; cvta.to.shared.u64 t, %1; cvt.u32.u64 %0, t; }" : "=r"(a) : "l"(p));
    return a;
}
__device__ __forceinline__ void cp_async16(uint32_t dst, const void* src) {
    asm volatile("cp.async.cg.shared.global [%0], [%1], 16;" :: "r"(dst), "l"(src) : "memory");
}
#define CP_COMMIT() asm volatile("cp.async.commit_group;" ::: "memory")
#define CP_WAIT0()  asm volatile("cp.async.wait_group 0;" ::: "memory")

__device__ __forceinline__ void ldsm4(uint32_t* r, uint32_t addr) {
    asm volatile("ldmatrix.sync.aligned.m8n8.x4.shared.b16 {%0,%1,%2,%3}, [%4];"
        : "=r"(r[0]), "=r"(r[1]), "=r"(r[2]), "=r"(r[3]) : "r"(addr));
}
__device__ __forceinline__ void mma_fp16(float* d, const uint32_t* a, const uint32_t* b) {
    asm volatile("mma.sync.aligned.m16n8k16.row.col.f32.f16.f16.f32 "
        "{%0,%1,%2,%3}, {%4,%5,%6,%7}, {%8,%9}, {%0,%1,%2,%3};"
        : "+f"(d[0]), "+f"(d[1]), "+f"(d[2]), "+f"(d[3])
        : "r"(a[0]), "r"(a[1]), "r"(a[2]), "r"(a[3]), "r"(b[0]), "r"(b[1]));
}
__device__ __forceinline__ uint32_t hfpair(float a, float b) {
    __half2 h = __floats2half2_rn(a, b);
    return *reinterpret_cast<uint32_t*>(&h);
}

// ---------------- kernel 1: merged prep (convA vectorized + W12) -------------
// blocks [0, 768): transpose + fp16 convert + tile swizzle; thread = 4 i's
// blocks [768, 768+2049): W12 = li1_w @ li2_w rows (+ bias row)
__global__ void __launch_bounds__(256) k_prep(
    const float* __restrict__ x,
    const float* __restrict__ li1_w, const float* __restrict__ li1_b,
    const float* __restrict__ li2_w, const float* __restrict__ li2_b)
{
    int bx = blockIdx.x;
    if (bx < 768) {
        int m  = bx & 127;
        int yb = bx >> 7;                       // 0..5
        int i0 = (yb * 256 + threadIdx.x) * 4;  // 4-aligned
        const float* xp = x + (size_t)m * KDIM;
        float4 v[8];
#pragma unroll
        for (int j = 0; j < 8; j++)
            v[j] = *reinterpret_cast<const float4*>(xp + j * 6144 + i0);
        const float* vf = reinterpret_cast<const float*>(v);

        int T = i0 >> 3;
        uint32_t base = (uint32_t)T * 16384 + (uint32_t)m * 128;
        uint32_t mask = ((uint32_t)m & 7) << 4;
        char* dst = reinterpret_cast<char*>(g_xA);
#pragma unroll
        for (int e = 0; e < 4; e++) {
            int i = i0 + e;
            uint32_t h0 = hfpair(vf[0 * 4 + e], vf[1 * 4 + e]);
            uint32_t h1 = hfpair(vf[2 * 4 + e], vf[3 * 4 + e]);
            uint32_t h2 = hfpair(vf[4 * 4 + e], vf[5 * 4 + e]);
            uint32_t h3 = hfpair(vf[6 * 4 + e], vf[7 * 4 + e]);
            uint32_t off = base + ((((uint32_t)i & 7) << 4) ^ mask);
            *reinterpret_cast<uint4*>(dst + off) = make_uint4(h0, h1, h2, h3);
        }
    } else {
        int j = bx - 768;            // 0..2048
        int t = threadIdx.x;
        __shared__ float red0[256];
        __shared__ float red1[256];
        const float* row = (j < NDIM) ? (li1_w + (size_t)j * 1000) : li1_b;
        float a0 = 0.f, a1 = 0.f;
        for (int p = t; p < 1000; p += 256) {
            float w = row[p];
            a0 += w * li2_w[2 * p];
            a1 += w * li2_w[2 * p + 1];
        }
        red0[t] = a0; red1[t] = a1;
        __syncthreads();
        for (int s = 128; s > 0; s >>= 1) {
            if (t < s) { red0[t] += red0[t + s]; red1[t] += red1[t + s]; }
            __syncthreads();
        }
        if (t == 0) {
            if (j < NDIM) { g_W12[2 * j] = red0[0]; g_W12[2 * j + 1] = red1[0]; }
            else          { g_ob[0] = red0[0] + li2_b[0]; g_ob[1] = red1[0] + li2_b[1]; }
        }
    }
}

// ---------------- kernel 2: fp16 single-pass split-K GEMM via mma.sync ------
// grid (16, 9): x = N-tile (128 cols), y = K split (uneven 85/86 chunks).
#define BUF_BYTES  32768
#define SMEM_BYTES (2 * BUF_BYTES)

__global__ void __launch_bounds__(256, 1) k_gemm(const float* __restrict__ fc_w) {
    extern __shared__ __align__(1024) char smem[];
    const uint32_t sb = smem_u32(smem);
    const int t   = threadIdx.x;
    const int w   = t >> 5;
    const int l   = t & 31;
    const int wm  = w >> 2;
    const int wn  = w & 3;
    const int nbase = blockIdx.x * BN;
    const int s     = blockIdx.y;
    const int T0 = (s * NTILES) / KSPLIT;
    const int T1 = ((s + 1) * NTILES) / KSPLIT;

    uint32_t aoff[4], amask[4];
#pragma unroll
    for (int mt = 0; mt < 4; mt++) {
        int row = wm * 64 + mt * 16 + (l & 15);
        aoff[mt]  = (uint32_t)row * 128;
        amask[mt] = ((uint32_t)row & 7) << 4;
    }
    uint32_t boff[2], bmask[2];
#pragma unroll
    for (int bt = 0; bt < 2; bt++) {
        int n = wn * 32 + bt * 16 + (l & 15);
        boff[bt]  = (uint32_t)n * 128;
        bmask[bt] = ((uint32_t)n & 7) << 4;
    }
    const uint32_t lcol = ((uint32_t)l >> 4) << 4;

    int bn[2], bkq[4];
#pragma unroll
    for (int ih = 0; ih < 2; ih++) bn[ih] = (l & 7) | (w << 3) | (ih << 6);
#pragma unroll
    for (int il = 0; il < 4; il++) bkq[il] = (l >> 3) | (il << 2);

    float acc[64];
#pragma unroll
    for (int q = 0; q < 64; q++) acc[q] = 0.f;

    float bst[8][4];

    // ---- prologue: A(T0) cp.async + B(T0) load/convert/store ----
    {
        const char* srch = reinterpret_cast<const char*>(g_xA) + (size_t)T0 * 16384 + t * 16;
#pragma unroll
        for (int i = 0; i < 4; i++)
            cp_async16(sb + t * 16 + i * 4096, srch + i * 4096);
        CP_COMMIT();
        int kb = T0 * KT;
#pragma unroll
        for (int i = 0; i < 8; i++) {
            int n = bn[i >> 2], kq = bkq[i & 3];
            const float* src = fc_w + (size_t)(kb + kq * 4) * NDIM + nbase + n;
#pragma unroll
            for (int e = 0; e < 4; e++) bst[i][e] = src[(size_t)e * NDIM];
        }
#pragma unroll
        for (int i = 0; i < 8; i++) {
            int n = bn[i >> 2], kq = bkq[i & 3];
            uint32_t sa = (uint32_t)n * 128 + (((uint32_t)kq * 8) ^ (((uint32_t)n & 7) << 4));
            *reinterpret_cast<uint2*>(smem + 16384 + sa) =
                make_uint2(hfpair(bst[i][0], bst[i][1]), hfpair(bst[i][2], bst[i][3]));
        }
    }

    // ---- main loop over this split's tiles ----
    for (int T = T0; T < T1; ++T) {
        const int cl = T - T0;
        const uint32_t cbuf = sb + (uint32_t)(cl & 1) * BUF_BYTES;
        const uint32_t nbuf = sb + (uint32_t)((cl + 1) & 1) * BUF_BYTES;

        if (T + 1 < T1) {
            int kb = (T + 1) * KT;
#pragma unroll
            for (int i = 0; i < 8; i++) {
                int n = bn[i >> 2], kq = bkq[i & 3];
                const float* src = fc_w + (size_t)(kb + kq * 4) * NDIM + nbase + n;
#pragma unroll
                for (int e = 0; e < 4; e++) bst[i][e] = src[(size_t)e * NDIM];
            }
        }

        CP_WAIT0();
        __syncthreads();

        if (T + 1 < T1) {
            const char* srch = reinterpret_cast<const char*>(g_xA) + (size_t)(T + 1) * 16384 + t * 16;
#pragma unroll
            for (int i = 0; i < 4; i++)
                cp_async16(nbuf + t * 16 + i * 4096, srch + i * 4096);
            CP_COMMIT();
        }

        const uint32_t Ah = cbuf, Bh = cbuf + 16384;
#pragma unroll
        for (int ks = 0; ks < 4; ks++) {
            const uint32_t kcol = (uint32_t)(ks * 32) + lcol;
            uint32_t ah[4][4], bh[4][2];
#pragma unroll
            for (int mt = 0; mt < 4; mt++)
                ldsm4(ah[mt], Ah + aoff[mt] + (kcol ^ amask[mt]));
#pragma unroll
            for (int bt = 0; bt < 2; bt++) {
                uint32_t r[4];
                ldsm4(r, Bh + boff[bt] + (kcol ^ bmask[bt]));
                bh[2 * bt][0] = r[0]; bh[2 * bt][1] = r[2];
                bh[2 * bt + 1][0] = r[1]; bh[2 * bt + 1][1] = r[3];
            }
#pragma unroll
            for (int mt = 0; mt < 4; mt++)
#pragma unroll
                for (int nt = 0; nt < 4; nt++)
                    mma_fp16(acc + (mt * 4 + nt) * 4, ah[mt], bh[nt]);
        }

        if (T + 1 < T1) {
#pragma unroll
            for (int i = 0; i < 8; i++) {
                int n = bn[i >> 2], kq = bkq[i & 3];
                uint32_t sa = (uint32_t)n * 128 + (((uint32_t)kq * 8) ^ (((uint32_t)n & 7) << 4));
                char* bp = smem + (nbuf - sb);
                *reinterpret_cast<uint2*>(bp + 16384 + sa) =
                    make_uint2(hfpair(bst[i][0], bst[i][1]), hfpair(bst[i][2], bst[i][3]));
            }
        }
    }

    // ---- epilogue: write partials ----
    float* op = g_part + (size_t)s * BATCH * NDIM;
#pragma unroll
    for (int mt = 0; mt < 4; mt++) {
        int m = wm * 64 + mt * 16 + (l >> 2);
#pragma unroll
        for (int nt = 0; nt < 4; nt++) {
            int n = nbase + wn * 32 + nt * 8 + (l & 3) * 2;
            const float* d = acc + (mt * 4 + nt) * 4;
            *reinterpret_cast<float2*>(op + (size_t)m * NDIM + n)       = make_float2(d[0], d[1]);
            *reinterpret_cast<float2*>(op + (size_t)(m + 8) * NDIM + n) = make_float2(d[2], d[3]);
        }
    }
}

// ---------------- kernel 3: fused per-batch pipeline, 512 thr (2 head grps) --
__global__ void __launch_bounds__(512) k_fuse(
    const float* __restrict__ fc_b,
    const float* __restrict__ ln1_s, const float* __restrict__ ln1_b,
    const float* __restrict__ ln2_s, const float* __restrict__ ln2_b,
    const float* __restrict__ Wq, const float* __restrict__ Wk, const float* __restrict__ Wv,
    const float* __restrict__ Wg, const float* __restrict__ Wo,
    const float* __restrict__ gn_w, const float* __restrict__ gn_b,
    const float* __restrict__ w1, const float* __restrict__ b1,
    const float* __restrict__ w2, const float* __restrict__ b2,
    float* __restrict__ out)
{
    int b   = blockIdx.x;
    int tid = threadIdx.x;
    int l   = tid & 255;
    int hg  = tid >> 8;

    __shared__ float4 sK4[2][256];
    __shared__ float4 sV4[2][256][2];
    __shared__ float  sGP[2][256];
    __shared__ float  syc[256][17];
    __shared__ float  sRed[8][2];
    __shared__ float  swq[64], swk[64], swv[128], swg[128], swo[128];
    __shared__ float  sgnw[16], sgnb[16], sw1[64], sw2[64];
    __shared__ float  sb1[8], sb2[8], sl1s[8], sl1b[8], sl2s[8], sl2b[8];

    if (tid < 64)  { swq[tid] = Wq[tid]; swk[tid] = Wk[tid]; sw1[tid] = w1[tid]; sw2[tid] = w2[tid]; }
    else if (tid < 192) { int u = tid - 64; swv[u] = Wv[u]; swg[u] = Wg[u]; swo[u] = Wo[u]; }
    else if (tid < 208) { int u = tid - 192; sgnw[u] = gn_w[u]; sgnb[u] = gn_b[u]; }
    else if (tid < 216) { int u = tid - 208; sb1[u] = b1[u]; sb2[u] = b2[u];
                          sl1s[u] = ln1_s[u]; sl1b[u] = ln1_b[u];
                          sl2s[u] = ln2_s[u]; sl2b[u] = ln2_b[u]; }

    float X[8];
    {
        float4 h0 = *reinterpret_cast<const float4*>(fc_b + l * 8);
        float4 h1 = *reinterpret_cast<const float4*>(fc_b + l * 8 + 4);
        X[0] = h0.x; X[1] = h0.y; X[2] = h0.z; X[3] = h0.w;
        X[4] = h1.x; X[5] = h1.y; X[6] = h1.z; X[7] = h1.w;
#pragma unroll
        for (int s = 0; s < KSPLIT; s++) {
            const float* pp = g_part + (size_t)s * (BATCH * NDIM) + b * NDIM + l * 8;
            float4 p0 = *reinterpret_cast<const float4*>(pp);
            float4 p1 = *reinterpret_cast<const float4*>(pp + 4);
            X[0] += p0.x; X[1] += p0.y; X[2] += p0.z; X[3] += p0.w;
            X[4] += p1.x; X[5] += p1.y; X[6] += p1.z; X[7] += p1.w;
        }
    }
    __syncthreads();

    float Xn[8];
    {
        float mu = 0.f;
#pragma unroll
        for (int d = 0; d < 8; d++) mu += X[d];
        mu *= 0.125f;
        float var = 0.f;
#pragma unroll
        for (int d = 0; d < 8; d++) { float tt = X[d] - mu; var += tt * tt; }
        var *= 0.125f;
        float inv = rsqrtf(var + 1e-5f);
#pragma unroll
        for (int d = 0; d < 8; d++) Xn[d] = (X[d] - mu) * inv * sl1s[d] + sl1b[d];
    }

    float fl = (float)l;
    float c0 = cosf(fl), s0 = sinf(fl);
    float c1 = cosf(fl * 0.01f), s1 = sinf(fl * 0.01f);
    float e0 = exp2f(fl * (-1.807354922f / 512.0f));
    float e1 = exp2f(fl * (-0.637429921f / 512.0f));
    float ie0 = 1.0f / e0, ie1 = 1.0f / e1;

    const float l2g[2] = { -0.04580368961f, -0.00281970977f };

    {
        const float* wq = swq + hg * 32;
        const float* wk = swk + hg * 32;
        const float* wv = swv + hg * 64;

        float q0 = 0, q1 = 0, q2 = 0, q3 = 0, k0 = 0, k1 = 0, k2 = 0, k3 = 0;
#pragma unroll
        for (int d = 0; d < 8; d++) {
            float xv = Xn[d];
            q0 += xv * wq[d * 4 + 0]; q1 += xv * wq[d * 4 + 1];
            q2 += xv * wq[d * 4 + 2]; q3 += xv * wq[d * 4 + 3];
            k0 += xv * wk[d * 4 + 0]; k1 += xv * wk[d * 4 + 1];
            k2 += xv * wk[d * 4 + 2]; k3 += xv * wk[d * 4 + 3];
        }
        float Q0 = (q0 * c0 - q1 * s0) * e0;
        float Q1 = (q1 * c0 + q0 * s0) * e0;
        float Q2 = (q2 * c1 - q3 * s1) * e1;
        float Q3 = (q3 * c1 + q2 * s1) * e1;
        float K0 = (k0 * c0 - k1 * s0) * ie0;
        float K1 = (k1 * c0 + k0 * s0) * ie0;
        float K2 = (k2 * c1 - k3 * s1) * ie1;
        float K3 = (k3 * c1 + k2 * s1) * ie1;

        float V[8];
#pragma unroll
        for (int f = 0; f < 8; f++) {
            float a = 0.f;
#pragma unroll
            for (int d = 0; d < 8; d++) a += Xn[d] * wv[d * 8 + f];
            V[f] = a;
        }

        sK4[hg][l] = make_float4(K0, K1, K2, K3);
        sV4[hg][l][0] = make_float4(V[0], V[1], V[2], V[3]);
        sV4[hg][l][1] = make_float4(V[4], V[5], V[6], V[7]);
        sGP[hg][l] = exp2f(-fl * l2g[hg]);
        float gpn = exp2f(fl * l2g[hg]);
        __syncthreads();

        float a0 = 0, a1 = 0, a2 = 0, a3 = 0, a4 = 0, a5 = 0, a6 = 0, a7 = 0;
        const float4* kp = sK4[hg];
        const float4 (*vp)[2] = sV4[hg];
        const float* gp = sGP[hg];
        for (int m = 0; m <= l; ++m) {
            float4 kv = kp[m];
            float wgt = (Q0 * kv.x + Q1 * kv.y + Q2 * kv.z + Q3 * kv.w) * gpn * gp[m];
            float4 v0 = vp[m][0], v1 = vp[m][1];
            a0 += wgt * v0.x; a1 += wgt * v0.y; a2 += wgt * v0.z; a3 += wgt * v0.w;
            a4 += wgt * v1.x; a5 += wgt * v1.y; a6 += wgt * v1.z; a7 += wgt * v1.w;
        }
        float* yr = syc[l] + hg * 8;
        yr[0] = a0; yr[1] = a1; yr[2] = a2; yr[3] = a3;
        yr[4] = a4; yr[5] = a5; yr[6] = a6; yr[7] = a7;
    }
    __syncthreads();

    if (hg == 0) {
        float yc[16];
#pragma unroll
        for (int j = 0; j < 16; j++) yc[j] = syc[l][j];

        float gn[16];
#pragma unroll
        for (int g = 0; g < 2; g++) {
            float mu = 0.f;
#pragma unroll
            for (int jj = 0; jj < 8; jj++) mu += yc[g * 8 + jj];
            mu *= 0.125f;
            float var = 0.f;
#pragma unroll
            for (int jj = 0; jj < 8; jj++) { float tt = yc[g * 8 + jj] - mu; var += tt * tt; }
            var *= 0.125f;
            float inv = rsqrtf(var + 1e-5f);
#pragma unroll
            for (int jj = 0; jj < 8; jj++)
                gn[g * 8 + jj] = (yc[g * 8 + jj] - mu) * inv * sgnw[g * 8 + jj] + sgnb[g * 8 + jj];
        }

        float msr[8] = {0, 0, 0, 0, 0, 0, 0, 0};
#pragma unroll
        for (int j = 0; j < 16; j++) {
            float gt = 0.f;
#pragma unroll
            for (int d = 0; d < 8; d++) gt += Xn[d] * swg[d * 16 + j];
            gt = gt / (1.0f + expf(-gt));
            float val = gt * gn[j];
#pragma unroll
            for (int d = 0; d < 8; d++) msr[d] += val * swo[j * 8 + d];
        }

        float Y[8], Z[8];
#pragma unroll
        for (int d = 0; d < 8; d++) Y[d] = msr[d] + X[d];
        {
            float mu = 0.f;
#pragma unroll
            for (int d = 0; d < 8; d++) mu += Y[d];
            mu *= 0.125f;
            float var = 0.f;
#pragma unroll
            for (int d = 0; d < 8; d++) { float tt = Y[d] - mu; var += tt * tt; }
            var *= 0.125f;
            float inv = rsqrtf(var + 1e-5f);
#pragma unroll
            for (int d = 0; d < 8; d++) Z[d] = (Y[d] - mu) * inv * sl2s[d] + sl2b[d];
        }

        float f1[8];
#pragma unroll
        for (int e = 0; e < 8; e++) {
            float a = sb1[e];
#pragma unroll
            for (int d = 0; d < 8; d++) a += Z[d] * sw1[d * 8 + e];
            f1[e] = 0.5f * a * (1.0f + erff(a * 0.70710678118654752f));
        }

        float p0 = 0.f, p1 = 0.f;
#pragma unroll
        for (int d = 0; d < 8; d++) {
            float a = sb2[d];
#pragma unroll
            for (int e = 0; e < 8; e++) a += f1[e] * sw2[e * 8 + d];
            float xf = a + Y[d];
            p0 += xf * g_W12[(l * 8 + d) * 2];
            p1 += xf * g_W12[(l * 8 + d) * 2 + 1];
        }

#pragma unroll
        for (int off = 16; off > 0; off >>= 1) {
            p0 += __shfl_down_sync(0xffffffffu, p0, off);
            p1 += __shfl_down_sync(0xffffffffu, p1, off);
        }
        if ((l & 31) == 0) { sRed[l >> 5][0] = p0; sRed[l >> 5][1] = p1; }
    }
    __syncthreads();
    if (tid == 0) {
        float o0 = g_ob[0], o1 = g_ob[1];
#pragma unroll
        for (int ww = 0; ww < 8; ww++) { o0 += sRed[ww][0]; o1 += sRed[ww][1]; }
        out[b * 2 + 0] = o0;
        out[b * 2 + 1] = o1;
    }
}

// ---------------- launch --------------------------------------------------
extern "C" void kernel_launch(void* const* d_in, const int* in_sizes, int n_in,
                              void* d_out, int out_size) {
    const float* x      = (const float*)d_in[0];
    const float* fc_w   = (const float*)d_in[1];
    const float* fc_b   = (const float*)d_in[2];
    const float* ln1_s  = (const float*)d_in[3];
    const float* ln1_b  = (const float*)d_in[4];
    const float* ln2_s  = (const float*)d_in[5];
    const float* ln2_b  = (const float*)d_in[6];
    const float* Wq     = (const float*)d_in[7];
    const float* Wk     = (const float*)d_in[8];
    const float* Wv     = (const float*)d_in[9];
    const float* Wg     = (const float*)d_in[10];
    const float* Wo     = (const float*)d_in[11];
    const float* gn_w   = (const float*)d_in[12];
    const float* gn_b   = (const float*)d_in[13];
    const float* ffn_w1 = (const float*)d_in[14];
    const float* ffn_b1 = (const float*)d_in[15];
    const float* ffn_w2 = (const float*)d_in[16];
    const float* ffn_b2 = (const float*)d_in[17];
    const float* li1_w  = (const float*)d_in[18];
    const float* li1_b  = (const float*)d_in[19];
    const float* li2_w  = (const float*)d_in[20];
    const float* li2_b  = (const float*)d_in[21];

    cudaFuncSetAttribute(k_gemm, cudaFuncAttributeMaxDynamicSharedMemorySize, SMEM_BYTES);

    k_prep<<<768 + NDIM + 1, 256>>>(x, li1_w, li1_b, li2_w, li2_b);
    dim3 gg(NDIM / BN, KSPLIT);
    k_gemm<<<gg, 256, SMEM_BYTES>>>(fc_w);
    k_fuse<<<BATCH, 512>>>(fc_b, ln1_s, ln1_b, ln2_s, ln2_b,
                           Wq, Wk, Wv, Wg, Wo, gn_w, gn_b,
                           ffn_w1, ffn_b1, ffn_w2, ffn_b2,
                           (float*)d_out);
}

// round 8
// speedup vs baseline: 8.2494x; 1.2514x over previous
#include <cuda_runtime.h>
#include <cuda_fp16.h>
#include <math.h>
#include <stdint.h>

// ---------------- problem constants ----------------
#define BATCH   128
#define KDIM    49152      // 6144 * 8
#define NDIM    2048       // 256 * 8
#define KSPLIT  9          // 16 x 9 = 144 CTAs ~ one full wave on 148 SMs
#define KT      64         // K per smem stage
#define BN      128        // N tile per CTA
#define NTILES  (KDIM / KT)   // 768 A tiles

// ---------------- scratch (device globals; no allocation allowed) ----------
__device__ __align__(16) __half g_xA[NTILES * 128 * 64];          // 12.6 MB
__device__ __align__(16) float g_part[KSPLIT * BATCH * NDIM];     // 9.4 MB
__device__ float g_W12[NDIM * 2];
__device__ float g_ob[2];

// ================= PTX helpers (sm_80-era ISA only: safe on compute_103) ====
__device__ __forceinline__ uint32_t smem_u32(const void* p) {
    uint32_t a;
    asm("{ .reg .u64 t; cvta.to.shared.u64 t, %1; cvt.u32.u64 %0, t; }" : "=r"(a) : "l"(p));
    return a;
}
__device__ __forceinline__ void cp_async16(uint32_t dst, const void* src) {
    asm volatile("cp.async.cg.shared.global [%0], [%1], 16;" :: "r"(dst), "l"(src) : "memory");
}
#define CP_COMMIT() asm volatile("cp.async.commit_group;" ::: "memory")
#define CP_WAIT0()  asm volatile("cp.async.wait_group 0;" ::: "memory")

__device__ __forceinline__ void ldsm4(uint32_t* r, uint32_t addr) {
    asm volatile("ldmatrix.sync.aligned.m8n8.x4.shared.b16 {%0,%1,%2,%3}, [%4];"
        : "=r"(r[0]), "=r"(r[1]), "=r"(r[2]), "=r"(r[3]) : "r"(addr));
}
__device__ __forceinline__ void ldsm4t(uint32_t* r, uint32_t addr) {
    asm volatile("ldmatrix.sync.aligned.m8n8.x4.trans.shared.b16 {%0,%1,%2,%3}, [%4];"
        : "=r"(r[0]), "=r"(r[1]), "=r"(r[2]), "=r"(r[3]) : "r"(addr));
}
__device__ __forceinline__ void mma_fp16(float* d, const uint32_t* a, const uint32_t* b) {
    asm volatile("mma.sync.aligned.m16n8k16.row.col.f32.f16.f16.f32 "
        "{%0,%1,%2,%3}, {%4,%5,%6,%7}, {%8,%9}, {%0,%1,%2,%3};"
        : "+f"(d[0]), "+f"(d[1]), "+f"(d[2]), "+f"(d[3])
        : "r"(a[0]), "r"(a[1]), "r"(a[2]), "r"(a[3]), "r"(b[0]), "r"(b[1]));
}
__device__ __forceinline__ uint32_t hfpair(float a, float b) {
    __half2 h = __floats2half2_rn(a, b);
    return *reinterpret_cast<uint32_t*>(&h);
}

// ---------------- kernel 1: merged prep (convA + warp-per-row W12) ----------
// blocks [0, 768): transpose + fp16 convert + tile swizzle; thread = 4 i's
// blocks [768, 1025): W12 rows, 8 per block (warp-per-row, shfl reduce)
__global__ void __launch_bounds__(256) k_prep(
    const float* __restrict__ x,
    const float* __restrict__ li1_w, const float* __restrict__ li1_b,
    const float* __restrict__ li2_w, const float* __restrict__ li2_b)
{
    int bx = blockIdx.x;
    if (bx < 768) {
        int m  = bx & 127;
        int yb = bx >> 7;                       // 0..5
        int i0 = (yb * 256 + threadIdx.x) * 4;  // 4-aligned
        const float* xp = x + (size_t)m * KDIM;
        float4 v[8];
#pragma unroll
        for (int j = 0; j < 8; j++)
            v[j] = *reinterpret_cast<const float4*>(xp + j * 6144 + i0);
        const float* vf = reinterpret_cast<const float*>(v);

        int T = i0 >> 3;
        uint32_t base = (uint32_t)T * 16384 + (uint32_t)m * 128;
        uint32_t mask = ((uint32_t)m & 7) << 4;
        char* dst = reinterpret_cast<char*>(g_xA);
#pragma unroll
        for (int e = 0; e < 4; e++) {
            int i = i0 + e;
            uint32_t h0 = hfpair(vf[0 * 4 + e], vf[1 * 4 + e]);
            uint32_t h1 = hfpair(vf[2 * 4 + e], vf[3 * 4 + e]);
            uint32_t h2 = hfpair(vf[4 * 4 + e], vf[5 * 4 + e]);
            uint32_t h3 = hfpair(vf[6 * 4 + e], vf[7 * 4 + e]);
            uint32_t off = base + ((((uint32_t)i & 7) << 4) ^ mask);
            *reinterpret_cast<uint4*>(dst + off) = make_uint4(h0, h1, h2, h3);
        }
    } else {
        __shared__ float s2[2000];
        int t = threadIdx.x;
        for (int p = t; p < 2000; p += 256) s2[p] = li2_w[p];
        __syncthreads();
        int wq = t >> 5, l = t & 31;
        int j = (bx - 768) * 8 + wq;            // 0..2056
        if (j <= NDIM) {
            const float* row = (j < NDIM) ? (li1_w + (size_t)j * 1000) : li1_b;
            float a0 = 0.f, a1 = 0.f;
            for (int p = l; p < 1000; p += 32) {
                float wv = row[p];
                a0 += wv * s2[2 * p];
                a1 += wv * s2[2 * p + 1];
            }
#pragma unroll
            for (int off = 16; off > 0; off >>= 1) {
                a0 += __shfl_down_sync(0xffffffffu, a0, off);
                a1 += __shfl_down_sync(0xffffffffu, a1, off);
            }
            if (l == 0) {
                if (j < NDIM) { g_W12[2 * j] = a0; g_W12[2 * j + 1] = a1; }
                else          { g_ob[0] = a0 + li2_b[0]; g_ob[1] = a1 + li2_b[1]; }
            }
        }
    }
}

// ---------------- kernel 2: fp16 split-K GEMM (float4 B loads, trans-ldsm) --
// grid (16, 9). SMEM per buffer (32KB): A[16K, n-major] B[16K, k-major]; x2.
#define BUF_BYTES  32768
#define SMEM_BYTES (2 * BUF_BYTES)

__global__ void __launch_bounds__(256, 1) k_gemm(const float* __restrict__ fc_w) {
    extern __shared__ __align__(1024) char smem[];
    const uint32_t sb = smem_u32(smem);
    const int t   = threadIdx.x;
    const int w   = t >> 5;
    const int l   = t & 31;
    const int wm  = w >> 2;
    const int wn  = w & 3;
    const int nbase = blockIdx.x * BN;
    const int s     = blockIdx.y;
    const int T0 = (s * NTILES) / KSPLIT;
    const int T1 = ((s + 1) * NTILES) / KSPLIT;

    // A ldmatrix addressing (n-major SW128, unchanged)
    uint32_t aoff[4], amask[4];
#pragma unroll
    for (int mt = 0; mt < 4; mt++) {
        int row = wm * 64 + mt * 16 + (l & 15);
        aoff[mt]  = (uint32_t)row * 128;
        amask[mt] = ((uint32_t)row & 7) << 4;
    }
    const uint32_t lcol = ((uint32_t)l >> 4) << 4;

    // B ldmatrix.trans addressing: smem [k][n], 64 rows x 256B, XOR swizzle
    //   lane l -> tile jj = l>>3, tile-row r = l&7
    //   k_local = ks*16 + r + (jj&1)*8 ; n_start = wn*32 + (jj>>1)*8 (+16 for 2nd ldsm)
    const uint32_t blane = (uint32_t)((l & 7) + ((l >> 3) & 1) * 8) * 256
                         + (((uint32_t)(64 * wn + 16 * (l >> 4))) ^ (((uint32_t)l & 7) << 4));

    // B global-load / STS mapping: thread (w,l): rows k = w+8i, cols n0 = 4l
    const uint32_t bsts = (uint32_t)w * 256 + (((uint32_t)(8 * l)) ^ ((uint32_t)w << 4));

    float acc[64];
#pragma unroll
    for (int q = 0; q < 64; q++) acc[q] = 0.f;

    float4 bst[8];

    // ---- prologue: A(T0) cp.async + B(T0) load/convert/store ----
    {
        const char* srch = reinterpret_cast<const char*>(g_xA) + (size_t)T0 * 16384 + t * 16;
#pragma unroll
        for (int i = 0; i < 4; i++)
            cp_async16(sb + t * 16 + i * 4096, srch + i * 4096);
        CP_COMMIT();
        int kb = T0 * KT;
        const float* bp = fc_w + (size_t)(kb + w) * NDIM + nbase + 4 * l;
#pragma unroll
        for (int i = 0; i < 8; i++)
            bst[i] = *reinterpret_cast<const float4*>(bp + (size_t)(8 * i) * NDIM);
#pragma unroll
        for (int i = 0; i < 8; i++)
            *reinterpret_cast<uint2*>(smem + 16384 + bsts + i * 2048) =
                make_uint2(hfpair(bst[i].x, bst[i].y), hfpair(bst[i].z, bst[i].w));
    }

    // ---- main loop over this split's tiles ----
    for (int T = T0; T < T1; ++T) {
        const int cl = T - T0;
        const uint32_t cbuf = sb + (uint32_t)(cl & 1) * BUF_BYTES;
        const uint32_t nbuf = sb + (uint32_t)((cl + 1) & 1) * BUF_BYTES;

        if (T + 1 < T1) {
            int kb = (T + 1) * KT;
            const float* bp = fc_w + (size_t)(kb + w) * NDIM + nbase + 4 * l;
#pragma unroll
            for (int i = 0; i < 8; i++)
                bst[i] = *reinterpret_cast<const float4*>(bp + (size_t)(8 * i) * NDIM);
        }

        CP_WAIT0();
        __syncthreads();

        if (T + 1 < T1) {
            const char* srch = reinterpret_cast<const char*>(g_xA) + (size_t)(T + 1) * 16384 + t * 16;
#pragma unroll
            for (int i = 0; i < 4; i++)
                cp_async16(nbuf + t * 16 + i * 4096, srch + i * 4096);
            CP_COMMIT();
        }

        const uint32_t Ah = cbuf, Bh = cbuf + 16384;
#pragma unroll
        for (int ks = 0; ks < 4; ks++) {
            const uint32_t kcol = (uint32_t)(ks * 32) + lcol;
            uint32_t ah[4][4], bh[4][2];
#pragma unroll
            for (int mt = 0; mt < 4; mt++)
                ldsm4(ah[mt], Ah + aoff[mt] + (kcol ^ amask[mt]));
            {
                const uint32_t bb = Bh + (uint32_t)ks * 4096 + blane;
                uint32_t r[4];
                ldsm4t(r, bb);           // n-groups 0,1
                bh[0][0] = r[0]; bh[0][1] = r[1];
                bh[1][0] = r[2]; bh[1][1] = r[3];
                ldsm4t(r, bb ^ 32u);     // n-groups 2,3
                bh[2][0] = r[0]; bh[2][1] = r[1];
                bh[3][0] = r[2]; bh[3][1] = r[3];
            }
#pragma unroll
            for (int mt = 0; mt < 4; mt++)
#pragma unroll
                for (int nt = 0; nt < 4; nt++)
                    mma_fp16(acc + (mt * 4 + nt) * 4, ah[mt], bh[nt]);
        }

        if (T + 1 < T1) {
            char* bp = smem + (nbuf - sb);
#pragma unroll
            for (int i = 0; i < 8; i++)
                *reinterpret_cast<uint2*>(bp + 16384 + bsts + i * 2048) =
                    make_uint2(hfpair(bst[i].x, bst[i].y), hfpair(bst[i].z, bst[i].w));
        }
    }

    // ---- epilogue: write partials ----
    float* op = g_part + (size_t)s * BATCH * NDIM;
#pragma unroll
    for (int mt = 0; mt < 4; mt++) {
        int m = wm * 64 + mt * 16 + (l >> 2);
#pragma unroll
        for (int nt = 0; nt < 4; nt++) {
            int n = nbase + wn * 32 + nt * 8 + (l & 3) * 2;
            const float* d = acc + (mt * 4 + nt) * 4;
            *reinterpret_cast<float2*>(op + (size_t)m * NDIM + n)       = make_float2(d[0], d[1]);
            *reinterpret_cast<float2*>(op + (size_t)(m + 8) * NDIM + n) = make_float2(d[2], d[3]);
        }
    }
}

// ---------------- kernel 3: fused per-batch pipeline, 512 thr (2 head grps) --
__global__ void __launch_bounds__(512) k_fuse(
    const float* __restrict__ fc_b,
    const float* __restrict__ ln1_s, const float* __restrict__ ln1_b,
    const float* __restrict__ ln2_s, const float* __restrict__ ln2_b,
    const float* __restrict__ Wq, const float* __restrict__ Wk, const float* __restrict__ Wv,
    const float* __restrict__ Wg, const float* __restrict__ Wo,
    const float* __restrict__ gn_w, const float* __restrict__ gn_b,
    const float* __restrict__ w1, const float* __restrict__ b1,
    const float* __restrict__ w2, const float* __restrict__ b2,
    float* __restrict__ out)
{
    int b   = blockIdx.x;
    int tid = threadIdx.x;
    int l   = tid & 255;
    int hg  = tid >> 8;

    __shared__ float4 sK4[2][256];
    __shared__ float4 sV4[2][256][2];
    __shared__ float  sGP[2][256];
    __shared__ float  syc[256][17];
    __shared__ float  sRed[8][2];
    __shared__ float  swq[64], swk[64], swv[128], swg[128], swo[128];
    __shared__ float  sgnw[16], sgnb[16], sw1[64], sw2[64];
    __shared__ float  sb1[8], sb2[8], sl1s[8], sl1b[8], sl2s[8], sl2b[8];

    if (tid < 64)  { swq[tid] = Wq[tid]; swk[tid] = Wk[tid]; sw1[tid] = w1[tid]; sw2[tid] = w2[tid]; }
    else if (tid < 192) { int u = tid - 64; swv[u] = Wv[u]; swg[u] = Wg[u]; swo[u] = Wo[u]; }
    else if (tid < 208) { int u = tid - 192; sgnw[u] = gn_w[u]; sgnb[u] = gn_b[u]; }
    else if (tid < 216) { int u = tid - 208; sb1[u] = b1[u]; sb2[u] = b2[u];
                          sl1s[u] = ln1_s[u]; sl1b[u] = ln1_b[u];
                          sl2s[u] = ln2_s[u]; sl2b[u] = ln2_b[u]; }

    float X[8];
    {
        float4 h0 = *reinterpret_cast<const float4*>(fc_b + l * 8);
        float4 h1 = *reinterpret_cast<const float4*>(fc_b + l * 8 + 4);
        X[0] = h0.x; X[1] = h0.y; X[2] = h0.z; X[3] = h0.w;
        X[4] = h1.x; X[5] = h1.y; X[6] = h1.z; X[7] = h1.w;
#pragma unroll
        for (int s = 0; s < KSPLIT; s++) {
            const float* pp = g_part + (size_t)s * (BATCH * NDIM) + b * NDIM + l * 8;
            float4 p0 = *reinterpret_cast<const float4*>(pp);
            float4 p1 = *reinterpret_cast<const float4*>(pp + 4);
            X[0] += p0.x; X[1] += p0.y; X[2] += p0.z; X[3] += p0.w;
            X[4] += p1.x; X[5] += p1.y; X[6] += p1.z; X[7] += p1.w;
        }
    }
    __syncthreads();

    float Xn[8];
    {
        float mu = 0.f;
#pragma unroll
        for (int d = 0; d < 8; d++) mu += X[d];
        mu *= 0.125f;
        float var = 0.f;
#pragma unroll
        for (int d = 0; d < 8; d++) { float tt = X[d] - mu; var += tt * tt; }
        var *= 0.125f;
        float inv = rsqrtf(var + 1e-5f);
#pragma unroll
        for (int d = 0; d < 8; d++) Xn[d] = (X[d] - mu) * inv * sl1s[d] + sl1b[d];
    }

    float fl = (float)l;
    float c0 = cosf(fl), s0 = sinf(fl);
    float c1 = cosf(fl * 0.01f), s1 = sinf(fl * 0.01f);
    float e0 = exp2f(fl * (-1.807354922f / 512.0f));
    float e1 = exp2f(fl * (-0.637429921f / 512.0f));
    float ie0 = 1.0f / e0, ie1 = 1.0f / e1;

    const float l2g[2] = { -0.04580368961f, -0.00281970977f };

    {
        const float* wq = swq + hg * 32;
        const float* wk = swk + hg * 32;
        const float* wv = swv + hg * 64;

        float q0 = 0, q1 = 0, q2 = 0, q3 = 0, k0 = 0, k1 = 0, k2 = 0, k3 = 0;
#pragma unroll
        for (int d = 0; d < 8; d++) {
            float xv = Xn[d];
            q0 += xv * wq[d * 4 + 0]; q1 += xv * wq[d * 4 + 1];
            q2 += xv * wq[d * 4 + 2]; q3 += xv * wq[d * 4 + 3];
            k0 += xv * wk[d * 4 + 0]; k1 += xv * wk[d * 4 + 1];
            k2 += xv * wk[d * 4 + 2]; k3 += xv * wk[d * 4 + 3];
        }
        float Q0 = (q0 * c0 - q1 * s0) * e0;
        float Q1 = (q1 * c0 + q0 * s0) * e0;
        float Q2 = (q2 * c1 - q3 * s1) * e1;
        float Q3 = (q3 * c1 + q2 * s1) * e1;
        float K0 = (k0 * c0 - k1 * s0) * ie0;
        float K1 = (k1 * c0 + k0 * s0) * ie0;
        float K2 = (k2 * c1 - k3 * s1) * ie1;
        float K3 = (k3 * c1 + k2 * s1) * ie1;

        float V[8];
#pragma unroll
        for (int f = 0; f < 8; f++) {
            float a = 0.f;
#pragma unroll
            for (int d = 0; d < 8; d++) a += Xn[d] * wv[d * 8 + f];
            V[f] = a;
        }

        sK4[hg][l] = make_float4(K0, K1, K2, K3);
        sV4[hg][l][0] = make_float4(V[0], V[1], V[2], V[3]);
        sV4[hg][l][1] = make_float4(V[4], V[5], V[6], V[7]);
        sGP[hg][l] = exp2f(-fl * l2g[hg]);
        float gpn = exp2f(fl * l2g[hg]);
        __syncthreads();

        float a0 = 0, a1 = 0, a2 = 0, a3 = 0, a4 = 0, a5 = 0, a6 = 0, a7 = 0;
        const float4* kp = sK4[hg];
        const float4 (*vp)[2] = sV4[hg];
        const float* gp = sGP[hg];
        for (int m = 0; m <= l; ++m) {
            float4 kv = kp[m];
            float wgt = (Q0 * kv.x + Q1 * kv.y + Q2 * kv.z + Q3 * kv.w) * gpn * gp[m];
            float4 v0 = vp[m][0], v1 = vp[m][1];
            a0 += wgt * v0.x; a1 += wgt * v0.y; a2 += wgt * v0.z; a3 += wgt * v0.w;
            a4 += wgt * v1.x; a5 += wgt * v1.y; a6 += wgt * v1.z; a7 += wgt * v1.w;
        }
        float* yr = syc[l] + hg * 8;
        yr[0] = a0; yr[1] = a1; yr[2] = a2; yr[3] = a3;
        yr[4] = a4; yr[5] = a5; yr[6] = a6; yr[7] = a7;
    }
    __syncthreads();

    if (hg == 0) {
        float yc[16];
#pragma unroll
        for (int j = 0; j < 16; j++) yc[j] = syc[l][j];

        float gn[16];
#pragma unroll
        for (int g = 0; g < 2; g++) {
            float mu = 0.f;
#pragma unroll
            for (int jj = 0; jj < 8; jj++) mu += yc[g * 8 + jj];
            mu *= 0.125f;
            float var = 0.f;
#pragma unroll
            for (int jj = 0; jj < 8; jj++) { float tt = yc[g * 8 + jj] - mu; var += tt * tt; }
            var *= 0.125f;
            float inv = rsqrtf(var + 1e-5f);
#pragma unroll
            for (int jj = 0; jj < 8; jj++)
                gn[g * 8 + jj] = (yc[g * 8 + jj] - mu) * inv * sgnw[g * 8 + jj] + sgnb[g * 8 + jj];
        }

        float msr[8] = {0, 0, 0, 0, 0, 0, 0, 0};
#pragma unroll
        for (int j = 0; j < 16; j++) {
            float gt = 0.f;
#pragma unroll
            for (int d = 0; d < 8; d++) gt += Xn[d] * swg[d * 16 + j];
            gt = gt / (1.0f + expf(-gt));
            float val = gt * gn[j];
#pragma unroll
            for (int d = 0; d < 8; d++) msr[d] += val * swo[j * 8 + d];
        }

        float Y[8], Z[8];
#pragma unroll
        for (int d = 0; d < 8; d++) Y[d] = msr[d] + X[d];
        {
            float mu = 0.f;
#pragma unroll
            for (int d = 0; d < 8; d++) mu += Y[d];
            mu *= 0.125f;
            float var = 0.f;
#pragma unroll
            for (int d = 0; d < 8; d++) { float tt = Y[d] - mu; var += tt * tt; }
            var *= 0.125f;
            float inv = rsqrtf(var + 1e-5f);
#pragma unroll
            for (int d = 0; d < 8; d++) Z[d] = (Y[d] - mu) * inv * sl2s[d] + sl2b[d];
        }

        float f1[8];
#pragma unroll
        for (int e = 0; e < 8; e++) {
            float a = sb1[e];
#pragma unroll
            for (int d = 0; d < 8; d++) a += Z[d] * sw1[d * 8 + e];
            f1[e] = 0.5f * a * (1.0f + erff(a * 0.70710678118654752f));
        }

        float p0 = 0.f, p1 = 0.f;
#pragma unroll
        for (int d = 0; d < 8; d++) {
            float a = sb2[d];
#pragma unroll
            for (int e = 0; e < 8; e++) a += f1[e] * sw2[e * 8 + d];
            float xf = a + Y[d];
            p0 += xf * g_W12[(l * 8 + d) * 2];
            p1 += xf * g_W12[(l * 8 + d) * 2 + 1];
        }

#pragma unroll
        for (int off = 16; off > 0; off >>= 1) {
            p0 += __shfl_down_sync(0xffffffffu, p0, off);
            p1 += __shfl_down_sync(0xffffffffu, p1, off);
        }
        if ((l & 31) == 0) { sRed[l >> 5][0] = p0; sRed[l >> 5][1] = p1; }
    }
    __syncthreads();
    if (tid == 0) {
        float o0 = g_ob[0], o1 = g_ob[1];
#pragma unroll
        for (int ww = 0; ww < 8; ww++) { o0 += sRed[ww][0]; o1 += sRed[ww][1]; }
        out[b * 2 + 0] = o0;
        out[b * 2 + 1] = o1;
    }
}

// ---------------- launch --------------------------------------------------
extern "C" void kernel_launch(void* const* d_in, const int* in_sizes, int n_in,
                              void* d_out, int out_size) {
    const float* x      = (const float*)d_in[0];
    const float* fc_w   = (const float*)d_in[1];
    const float* fc_b   = (const float*)d_in[2];
    const float* ln1_s  = (const float*)d_in[3];
    const float* ln1_b  = (const float*)d_in[4];
    const float* ln2_s  = (const float*)d_in[5];
    const float* ln2_b  = (const float*)d_in[6];
    const float* Wq     = (const float*)d_in[7];
    const float* Wk     = (const float*)d_in[8];
    const float* Wv     = (const float*)d_in[9];
    const float* Wg     = (const float*)d_in[10];
    const float* Wo     = (const float*)d_in[11];
    const float* gn_w   = (const float*)d_in[12];
    const float* gn_b   = (const float*)d_in[13];
    const float* ffn_w1 = (const float*)d_in[14];
    const float* ffn_b1 = (const float*)d_in[15];
    const float* ffn_w2 = (const float*)d_in[16];
    const float* ffn_b2 = (const float*)d_in[17];
    const float* li1_w  = (const float*)d_in[18];
    const float* li1_b  = (const float*)d_in[19];
    const float* li2_w  = (const float*)d_in[20];
    const float* li2_b  = (const float*)d_in[21];

    cudaFuncSetAttribute(k_gemm, cudaFuncAttributeMaxDynamicSharedMemorySize, SMEM_BYTES);

    k_prep<<<768 + 257, 256>>>(x, li1_w, li1_b, li2_w, li2_b);
    dim3 gg(NDIM / BN, KSPLIT);
    k_gemm<<<gg, 256, SMEM_BYTES>>>(fc_w);
    k_fuse<<<BATCH, 512>>>(fc_b, ln1_s, ln1_b, ln2_s, ln2_b,
                           Wq, Wk, Wv, Wg, Wo, gn_w, gn_b,
                           ffn_w1, ffn_b1, ffn_w2, ffn_b2,
                           (float*)d_out);
}

// round 9
// speedup vs baseline: 9.3866x; 1.1378x over previous
#include <cuda_runtime.h>
#include <cuda_fp16.h>
#include <math.h>
#include <stdint.h>

// ---------------- problem constants ----------------
#define BATCH   128
#define KDIM    49152      // 6144 * 8
#define NDIM    2048       // 256 * 8
#define KSPLIT  9          // 16 x 9 = 144 CTAs ~ one full wave on 148 SMs
#define KT      64         // K per A tile (tile granularity in g_xA)
#define BN      128        // N tile per CTA
#define NTILES  (KDIM / KT)   // 768 A tiles
#define NCHUNK  (NTILES / 2)  // 384 double-tile chunks (K=128 per chunk)

// ---------------- scratch (device globals; no allocation allowed) ----------
__device__ __align__(16) __half g_xA[NTILES * 128 * 64];          // 12.6 MB
__device__ __align__(16) float g_part[KSPLIT * BATCH * NDIM];     // 9.4 MB
__device__ float g_W12[NDIM * 2];
__device__ float g_ob[2];

// ================= PTX helpers (sm_80-era ISA only: safe on compute_103) ====
__device__ __forceinline__ uint32_t smem_u32(const void* p) {
    uint32_t a;
    asm("{ .reg .u64 t; cvta.to.shared.u64 t, %1; cvt.u32.u64 %0, t; }" : "=r"(a) : "l"(p));
    return a;
}
__device__ __forceinline__ void cp_async16(uint32_t dst, const void* src) {
    asm volatile("cp.async.cg.shared.global [%0], [%1], 16;" :: "r"(dst), "l"(src) : "memory");
}
#define CP_COMMIT() asm volatile("cp.async.commit_group;" ::: "memory")
#define CP_WAIT0()  asm volatile("cp.async.wait_group 0;" ::: "memory")

__device__ __forceinline__ void ldsm4(uint32_t* r, uint32_t addr) {
    asm volatile("ldmatrix.sync.aligned.m8n8.x4.shared.b16 {%0,%1,%2,%3}, [%4];"
        : "=r"(r[0]), "=r"(r[1]), "=r"(r[2]), "=r"(r[3]) : "r"(addr));
}
__device__ __forceinline__ void ldsm4t(uint32_t* r, uint32_t addr) {
    asm volatile("ldmatrix.sync.aligned.m8n8.x4.trans.shared.b16 {%0,%1,%2,%3}, [%4];"
        : "=r"(r[0]), "=r"(r[1]), "=r"(r[2]), "=r"(r[3]) : "r"(addr));
}
__device__ __forceinline__ void mma_fp16(float* d, const uint32_t* a, const uint32_t* b) {
    asm volatile("mma.sync.aligned.m16n8k16.row.col.f32.f16.f16.f32 "
        "{%0,%1,%2,%3}, {%4,%5,%6,%7}, {%8,%9}, {%0,%1,%2,%3};"
        : "+f"(d[0]), "+f"(d[1]), "+f"(d[2]), "+f"(d[3])
        : "r"(a[0]), "r"(a[1]), "r"(a[2]), "r"(a[3]), "r"(b[0]), "r"(b[1]));
}
__device__ __forceinline__ uint32_t hfpair(float a, float b) {
    __half2 h = __floats2half2_rn(a, b);
    return *reinterpret_cast<uint32_t*>(&h);
}

// ---------------- kernel 1: merged prep (convA MLP=16 + warp-per-row W12) ---
// blocks [0, 384): transpose + fp16 convert + tile swizzle; thread = 8 i's
// blocks [384, 641): W12 rows, 8 per block (warp-per-row, shfl reduce)
__global__ void __launch_bounds__(256) k_prep(
    const float* __restrict__ x,
    const float* __restrict__ li1_w, const float* __restrict__ li1_b,
    const float* __restrict__ li2_w, const float* __restrict__ li2_b)
{
    int bx = blockIdx.x;
    if (bx < 384) {
        int m  = bx & 127;
        int yb = bx >> 7;                       // 0..2
        const float* xp = x + (size_t)m * KDIM;
        char* dst = reinterpret_cast<char*>(g_xA);
        uint32_t mask = ((uint32_t)m & 7) << 4;

        // two independent i-groups -> 16 outstanding LDG.128
        int i0a = (yb * 256 + threadIdx.x) * 4;
        int i0b = i0a + 3072;
        float4 va[8], vb[8];
#pragma unroll
        for (int j = 0; j < 8; j++)
            va[j] = *reinterpret_cast<const float4*>(xp + j * 6144 + i0a);
#pragma unroll
        for (int j = 0; j < 8; j++)
            vb[j] = *reinterpret_cast<const float4*>(xp + j * 6144 + i0b);

#pragma unroll
        for (int g = 0; g < 2; g++) {
            const float* vf = reinterpret_cast<const float*>(g == 0 ? va : vb);
            int i0 = g == 0 ? i0a : i0b;
            uint32_t base = (uint32_t)(i0 >> 3) * 16384 + (uint32_t)m * 128;
#pragma unroll
            for (int e = 0; e < 4; e++) {
                int i = i0 + e;
                uint32_t h0 = hfpair(vf[0 * 4 + e], vf[1 * 4 + e]);
                uint32_t h1 = hfpair(vf[2 * 4 + e], vf[3 * 4 + e]);
                uint32_t h2 = hfpair(vf[4 * 4 + e], vf[5 * 4 + e]);
                uint32_t h3 = hfpair(vf[6 * 4 + e], vf[7 * 4 + e]);
                uint32_t off = base + ((((uint32_t)i & 7) << 4) ^ mask);
                *reinterpret_cast<uint4*>(dst + off) = make_uint4(h0, h1, h2, h3);
            }
        }
    } else {
        __shared__ float s2[2000];
        int t = threadIdx.x;
        for (int p = t; p < 2000; p += 256) s2[p] = li2_w[p];
        __syncthreads();
        int wq = t >> 5, l = t & 31;
        int j = (bx - 384) * 8 + wq;            // 0..2056
        if (j <= NDIM) {
            const float* row = (j < NDIM) ? (li1_w + (size_t)j * 1000) : li1_b;
            float a0 = 0.f, a1 = 0.f;
            for (int p = l; p < 1000; p += 32) {
                float wv = row[p];
                a0 += wv * s2[2 * p];
                a1 += wv * s2[2 * p + 1];
            }
#pragma unroll
            for (int off = 16; off > 0; off >>= 1) {
                a0 += __shfl_down_sync(0xffffffffu, a0, off);
                a1 += __shfl_down_sync(0xffffffffu, a1, off);
            }
            if (l == 0) {
                if (j < NDIM) { g_W12[2 * j] = a0; g_W12[2 * j + 1] = a1; }
                else          { g_ob[0] = a0 + li2_b[0]; g_ob[1] = a1 + li2_b[1]; }
            }
        }
    }
}

// ---------------- kernel 2: fp16 split-K GEMM, K=128 per stage --------------
// grid (16, 9). SMEM per buffer (64KB): A[32K = 2 tiles] B[32K, k-major]; x2.
#define BUF_BYTES  65536
#define SMEM_BYTES (2 * BUF_BYTES)

__global__ void __launch_bounds__(256, 1) k_gemm(const float* __restrict__ fc_w) {
    extern __shared__ __align__(1024) char smem[];
    const uint32_t sb = smem_u32(smem);
    const int t   = threadIdx.x;
    const int w   = t >> 5;
    const int l   = t & 31;
    const int wm  = w >> 2;
    const int wn  = w & 3;
    const int nbase = blockIdx.x * BN;
    const int s     = blockIdx.y;
    const int C0 = (s * NCHUNK) / KSPLIT;
    const int C1 = ((s + 1) * NCHUNK) / KSPLIT;

    // A ldmatrix addressing (n-major SW128 within 16KB tile)
    uint32_t aoff[4], amask[4];
#pragma unroll
    for (int mt = 0; mt < 4; mt++) {
        int row = wm * 64 + mt * 16 + (l & 15);
        aoff[mt]  = (uint32_t)row * 128;
        amask[mt] = ((uint32_t)row & 7) << 4;
    }
    const uint32_t lcol = ((uint32_t)l >> 4) << 4;

    // B ldmatrix.trans addressing: smem [k][n], 128 rows x 256B, XOR swizzle
    const uint32_t blane = (uint32_t)((l & 7) + ((l >> 3) & 1) * 8) * 256
                         + (((uint32_t)(64 * wn + 16 * (l >> 4))) ^ (((uint32_t)l & 7) << 4));

    // B global-load / STS mapping: thread (w,l): rows k = w+8i (i<16), cols 4l
    const uint32_t bsts = (uint32_t)w * 256 + (((uint32_t)(8 * l)) ^ ((uint32_t)w << 4));

    float acc[64];
#pragma unroll
    for (int q = 0; q < 64; q++) acc[q] = 0.f;

    float4 bst[16];

    // ---- prologue: A(C0) cp.async + B(C0) load/convert/store ----
    {
        const char* srch = reinterpret_cast<const char*>(g_xA) + (size_t)C0 * 32768 + t * 16;
#pragma unroll
        for (int i = 0; i < 8; i++)
            cp_async16(sb + t * 16 + i * 4096, srch + i * 4096);
        CP_COMMIT();
        int kb = C0 * 128;
        const float* bp = fc_w + (size_t)(kb + w) * NDIM + nbase + 4 * l;
#pragma unroll
        for (int i = 0; i < 16; i++)
            bst[i] = *reinterpret_cast<const float4*>(bp + (size_t)(8 * i) * NDIM);
#pragma unroll
        for (int i = 0; i < 16; i++)
            *reinterpret_cast<uint2*>(smem + 32768 + bsts + i * 2048) =
                make_uint2(hfpair(bst[i].x, bst[i].y), hfpair(bst[i].z, bst[i].w));
    }

    // ---- main loop over this split's double-tile chunks ----
    for (int C = C0; C < C1; ++C) {
        const int cl = C - C0;
        const uint32_t cbuf = sb + (uint32_t)(cl & 1) * BUF_BYTES;
        const uint32_t nbuf = sb + (uint32_t)((cl + 1) & 1) * BUF_BYTES;

        if (C + 1 < C1) {
            int kb = (C + 1) * 128;
            const float* bp = fc_w + (size_t)(kb + w) * NDIM + nbase + 4 * l;
#pragma unroll
            for (int i = 0; i < 16; i++)
                bst[i] = *reinterpret_cast<const float4*>(bp + (size_t)(8 * i) * NDIM);
        }

        CP_WAIT0();
        __syncthreads();

        if (C + 1 < C1) {
            const char* srch = reinterpret_cast<const char*>(g_xA) + (size_t)(C + 1) * 32768 + t * 16;
#pragma unroll
            for (int i = 0; i < 8; i++)
                cp_async16(nbuf + t * 16 + i * 4096, srch + i * 4096);
            CP_COMMIT();
        }

        const uint32_t Bh = cbuf + 32768;
#pragma unroll
        for (int ks = 0; ks < 8; ks++) {
            const uint32_t Ah = cbuf + ((ks & 4) ? 16384u : 0u);
            const uint32_t kcol = (uint32_t)((ks & 3) * 32) + lcol;
            uint32_t ah[4][4], bh[4][2];
#pragma unroll
            for (int mt = 0; mt < 4; mt++)
                ldsm4(ah[mt], Ah + aoff[mt] + (kcol ^ amask[mt]));
            {
                const uint32_t bb = Bh + (uint32_t)ks * 4096 + blane;
                uint32_t r[4];
                ldsm4t(r, bb);           // n-groups 0,1
                bh[0][0] = r[0]; bh[0][1] = r[1];
                bh[1][0] = r[2]; bh[1][1] = r[3];
                ldsm4t(r, bb ^ 32u);     // n-groups 2,3
                bh[2][0] = r[0]; bh[2][1] = r[1];
                bh[3][0] = r[2]; bh[3][1] = r[3];
            }
#pragma unroll
            for (int mt = 0; mt < 4; mt++)
#pragma unroll
                for (int nt = 0; nt < 4; nt++)
                    mma_fp16(acc + (mt * 4 + nt) * 4, ah[mt], bh[nt]);
        }

        if (C + 1 < C1) {
            char* bp = smem + (nbuf - sb);
#pragma unroll
            for (int i = 0; i < 16; i++)
                *reinterpret_cast<uint2*>(bp + 32768 + bsts + i * 2048) =
                    make_uint2(hfpair(bst[i].x, bst[i].y), hfpair(bst[i].z, bst[i].w));
        }
    }

    // ---- epilogue: write partials ----
    float* op = g_part + (size_t)s * BATCH * NDIM;
#pragma unroll
    for (int mt = 0; mt < 4; mt++) {
        int m = wm * 64 + mt * 16 + (l >> 2);
#pragma unroll
        for (int nt = 0; nt < 4; nt++) {
            int n = nbase + wn * 32 + nt * 8 + (l & 3) * 2;
            const float* d = acc + (mt * 4 + nt) * 4;
            *reinterpret_cast<float2*>(op + (size_t)m * NDIM + n)       = make_float2(d[0], d[1]);
            *reinterpret_cast<float2*>(op + (size_t)(m + 8) * NDIM + n) = make_float2(d[2], d[3]);
        }
    }
}

// ---------------- kernel 3: fused per-batch pipeline, 512 thr (2 head grps) --
__global__ void __launch_bounds__(512) k_fuse(
    const float* __restrict__ fc_b,
    const float* __restrict__ ln1_s, const float* __restrict__ ln1_b,
    const float* __restrict__ ln2_s, const float* __restrict__ ln2_b,
    const float* __restrict__ Wq, const float* __restrict__ Wk, const float* __restrict__ Wv,
    const float* __restrict__ Wg, const float* __restrict__ Wo,
    const float* __restrict__ gn_w, const float* __restrict__ gn_b,
    const float* __restrict__ w1, const float* __restrict__ b1,
    const float* __restrict__ w2, const float* __restrict__ b2,
    float* __restrict__ out)
{
    int b   = blockIdx.x;
    int tid = threadIdx.x;
    int l   = tid & 255;
    int hg  = tid >> 8;

    __shared__ float4 sK4[2][256];
    __shared__ float4 sV4[2][256][2];
    __shared__ float  sGP[2][256];
    __shared__ float  syc[256][17];
    __shared__ float  sRed[8][2];
    __shared__ float  swq[64], swk[64], swv[128], swg[128], swo[128];
    __shared__ float  sgnw[16], sgnb[16], sw1[64], sw2[64];
    __shared__ float  sb1[8], sb2[8], sl1s[8], sl1b[8], sl2s[8], sl2b[8];

    if (tid < 64)  { swq[tid] = Wq[tid]; swk[tid] = Wk[tid]; sw1[tid] = w1[tid]; sw2[tid] = w2[tid]; }
    else if (tid < 192) { int u = tid - 64; swv[u] = Wv[u]; swg[u] = Wg[u]; swo[u] = Wo[u]; }
    else if (tid < 208) { int u = tid - 192; sgnw[u] = gn_w[u]; sgnb[u] = gn_b[u]; }
    else if (tid < 216) { int u = tid - 208; sb1[u] = b1[u]; sb2[u] = b2[u];
                          sl1s[u] = ln1_s[u]; sl1b[u] = ln1_b[u];
                          sl2s[u] = ln2_s[u]; sl2b[u] = ln2_b[u]; }

    float X[8];
    {
        float4 h0 = *reinterpret_cast<const float4*>(fc_b + l * 8);
        float4 h1 = *reinterpret_cast<const float4*>(fc_b + l * 8 + 4);
        X[0] = h0.x; X[1] = h0.y; X[2] = h0.z; X[3] = h0.w;
        X[4] = h1.x; X[5] = h1.y; X[6] = h1.z; X[7] = h1.w;
#pragma unroll
        for (int s = 0; s < KSPLIT; s++) {
            const float* pp = g_part + (size_t)s * (BATCH * NDIM) + b * NDIM + l * 8;
            float4 p0 = *reinterpret_cast<const float4*>(pp);
            float4 p1 = *reinterpret_cast<const float4*>(pp + 4);
            X[0] += p0.x; X[1] += p0.y; X[2] += p0.z; X[3] += p0.w;
            X[4] += p1.x; X[5] += p1.y; X[6] += p1.z; X[7] += p1.w;
        }
    }
    __syncthreads();

    float Xn[8];
    {
        float mu = 0.f;
#pragma unroll
        for (int d = 0; d < 8; d++) mu += X[d];
        mu *= 0.125f;
        float var = 0.f;
#pragma unroll
        for (int d = 0; d < 8; d++) { float tt = X[d] - mu; var += tt * tt; }
        var *= 0.125f;
        float inv = rsqrtf(var + 1e-5f);
#pragma unroll
        for (int d = 0; d < 8; d++) Xn[d] = (X[d] - mu) * inv * sl1s[d] + sl1b[d];
    }

    float fl = (float)l;
    float c0 = cosf(fl), s0 = sinf(fl);
    float c1 = cosf(fl * 0.01f), s1 = sinf(fl * 0.01f);
    float e0 = exp2f(fl * (-1.807354922f / 512.0f));
    float e1 = exp2f(fl * (-0.637429921f / 512.0f));
    float ie0 = 1.0f / e0, ie1 = 1.0f / e1;

    const float l2g[2] = { -0.04580368961f, -0.00281970977f };

    {
        const float* wq = swq + hg * 32;
        const float* wk = swk + hg * 32;
        const float* wv = swv + hg * 64;

        float q0 = 0, q1 = 0, q2 = 0, q3 = 0, k0 = 0, k1 = 0, k2 = 0, k3 = 0;
#pragma unroll
        for (int d = 0; d < 8; d++) {
            float xv = Xn[d];
            q0 += xv * wq[d * 4 + 0]; q1 += xv * wq[d * 4 + 1];
            q2 += xv * wq[d * 4 + 2]; q3 += xv * wq[d * 4 + 3];
            k0 += xv * wk[d * 4 + 0]; k1 += xv * wk[d * 4 + 1];
            k2 += xv * wk[d * 4 + 2]; k3 += xv * wk[d * 4 + 3];
        }
        float Q0 = (q0 * c0 - q1 * s0) * e0;
        float Q1 = (q1 * c0 + q0 * s0) * e0;
        float Q2 = (q2 * c1 - q3 * s1) * e1;
        float Q3 = (q3 * c1 + q2 * s1) * e1;
        float K0 = (k0 * c0 - k1 * s0) * ie0;
        float K1 = (k1 * c0 + k0 * s0) * ie0;
        float K2 = (k2 * c1 - k3 * s1) * ie1;
        float K3 = (k3 * c1 + k2 * s1) * ie1;

        float V[8];
#pragma unroll
        for (int f = 0; f < 8; f++) {
            float a = 0.f;
#pragma unroll
            for (int d = 0; d < 8; d++) a += Xn[d] * wv[d * 8 + f];
            V[f] = a;
        }

        sK4[hg][l] = make_float4(K0, K1, K2, K3);
        sV4[hg][l][0] = make_float4(V[0], V[1], V[2], V[3]);
        sV4[hg][l][1] = make_float4(V[4], V[5], V[6], V[7]);
        sGP[hg][l] = exp2f(-fl * l2g[hg]);
        float gpn = exp2f(fl * l2g[hg]);
        __syncthreads();

        float a0 = 0, a1 = 0, a2 = 0, a3 = 0, a4 = 0, a5 = 0, a6 = 0, a7 = 0;
        const float4* kp = sK4[hg];
        const float4 (*vp)[2] = sV4[hg];
        const float* gp = sGP[hg];
        for (int m = 0; m <= l; ++m) {
            float4 kv = kp[m];
            float wgt = (Q0 * kv.x + Q1 * kv.y + Q2 * kv.z + Q3 * kv.w) * gpn * gp[m];
            float4 v0 = vp[m][0], v1 = vp[m][1];
            a0 += wgt * v0.x; a1 += wgt * v0.y; a2 += wgt * v0.z; a3 += wgt * v0.w;
            a4 += wgt * v1.x; a5 += wgt * v1.y; a6 += wgt * v1.z; a7 += wgt * v1.w;
        }
        float* yr = syc[l] + hg * 8;
        yr[0] = a0; yr[1] = a1; yr[2] = a2; yr[3] = a3;
        yr[4] = a4; yr[5] = a5; yr[6] = a6; yr[7] = a7;
    }
    __syncthreads();

    if (hg == 0) {
        float yc[16];
#pragma unroll
        for (int j = 0; j < 16; j++) yc[j] = syc[l][j];

        float gn[16];
#pragma unroll
        for (int g = 0; g < 2; g++) {
            float mu = 0.f;
#pragma unroll
            for (int jj = 0; jj < 8; jj++) mu += yc[g * 8 + jj];
            mu *= 0.125f;
            float var = 0.f;
#pragma unroll
            for (int jj = 0; jj < 8; jj++) { float tt = yc[g * 8 + jj] - mu; var += tt * tt; }
            var *= 0.125f;
            float inv = rsqrtf(var + 1e-5f);
#pragma unroll
            for (int jj = 0; jj < 8; jj++)
                gn[g * 8 + jj] = (yc[g * 8 + jj] - mu) * inv * sgnw[g * 8 + jj] + sgnb[g * 8 + jj];
        }

        float msr[8] = {0, 0, 0, 0, 0, 0, 0, 0};
#pragma unroll
        for (int j = 0; j < 16; j++) {
            float gt = 0.f;
#pragma unroll
            for (int d = 0; d < 8; d++) gt += Xn[d] * swg[d * 16 + j];
            gt = gt / (1.0f + expf(-gt));
            float val = gt * gn[j];
#pragma unroll
            for (int d = 0; d < 8; d++) msr[d] += val * swo[j * 8 + d];
        }

        float Y[8], Z[8];
#pragma unroll
        for (int d = 0; d < 8; d++) Y[d] = msr[d] + X[d];
        {
            float mu = 0.f;
#pragma unroll
            for (int d = 0; d < 8; d++) mu += Y[d];
            mu *= 0.125f;
            float var = 0.f;
#pragma unroll
            for (int d = 0; d < 8; d++) { float tt = Y[d] - mu; var += tt * tt; }
            var *= 0.125f;
            float inv = rsqrtf(var + 1e-5f);
#pragma unroll
            for (int d = 0; d < 8; d++) Z[d] = (Y[d] - mu) * inv * sl2s[d] + sl2b[d];
        }

        float f1[8];
#pragma unroll
        for (int e = 0; e < 8; e++) {
            float a = sb1[e];
#pragma unroll
            for (int d = 0; d < 8; d++) a += Z[d] * sw1[d * 8 + e];
            f1[e] = 0.5f * a * (1.0f + erff(a * 0.70710678118654752f));
        }

        float p0 = 0.f, p1 = 0.f;
#pragma unroll
        for (int d = 0; d < 8; d++) {
            float a = sb2[d];
#pragma unroll
            for (int e = 0; e < 8; e++) a += f1[e] * sw2[e * 8 + d];
            float xf = a + Y[d];
            p0 += xf * g_W12[(l * 8 + d) * 2];
            p1 += xf * g_W12[(l * 8 + d) * 2 + 1];
        }

#pragma unroll
        for (int off = 16; off > 0; off >>= 1) {
            p0 += __shfl_down_sync(0xffffffffu, p0, off);
            p1 += __shfl_down_sync(0xffffffffu, p1, off);
        }
        if ((l & 31) == 0) { sRed[l >> 5][0] = p0; sRed[l >> 5][1] = p1; }
    }
    __syncthreads();
    if (tid == 0) {
        float o0 = g_ob[0], o1 = g_ob[1];
#pragma unroll
        for (int ww = 0; ww < 8; ww++) { o0 += sRed[ww][0]; o1 += sRed[ww][1]; }
        out[b * 2 + 0] = o0;
        out[b * 2 + 1] = o1;
    }
}

// ---------------- launch --------------------------------------------------
extern "C" void kernel_launch(void* const* d_in, const int* in_sizes, int n_in,
                              void* d_out, int out_size) {
    const float* x      = (const float*)d_in[0];
    const float* fc_w   = (const float*)d_in[1];
    const float* fc_b   = (const float*)d_in[2];
    const float* ln1_s  = (const float*)d_in[3];
    const float* ln1_b  = (const float*)d_in[4];
    const float* ln2_s  = (const float*)d_in[5];
    const float* ln2_b  = (const float*)d_in[6];
    const float* Wq     = (const float*)d_in[7];
    const float* Wk     = (const float*)d_in[8];
    const float* Wv     = (const float*)d_in[9];
    const float* Wg     = (const float*)d_in[10];
    const float* Wo     = (const float*)d_in[11];
    const float* gn_w   = (const float*)d_in[12];
    const float* gn_b   = (const float*)d_in[13];
    const float* ffn_w1 = (const float*)d_in[14];
    const float* ffn_b1 = (const float*)d_in[15];
    const float* ffn_w2 = (const float*)d_in[16];
    const float* ffn_b2 = (const float*)d_in[17];
    const float* li1_w  = (const float*)d_in[18];
    const float* li1_b  = (const float*)d_in[19];
    const float* li2_w  = (const float*)d_in[20];
    const float* li2_b  = (const float*)d_in[21];

    cudaFuncSetAttribute(k_gemm, cudaFuncAttributeMaxDynamicSharedMemorySize, SMEM_BYTES);

    k_prep<<<384 + 257, 256>>>(x, li1_w, li1_b, li2_w, li2_b);
    dim3 gg(NDIM / BN, KSPLIT);
    k_gemm<<<gg, 256, SMEM_BYTES>>>(fc_w);
    k_fuse<<<BATCH, 512>>>(fc_b, ln1_s, ln1_b, ln2_s, ln2_b,
                           Wq, Wk, Wv, Wg, Wo, gn_w, gn_b,
                           ffn_w1, ffn_b1, ffn_w2, ffn_b2,
                           (float*)d_out);
}

// round 10
// speedup vs baseline: 9.7110x; 1.0346x over previous
#include <cuda_runtime.h>
#include <cuda_fp16.h>
#include <math.h>
#include <stdint.h>

// ---------------- problem constants ----------------
#define BATCH   128
#define KDIM    49152      // 6144 * 8
#define NDIM    2048       // 256 * 8
#define KSPLIT  9          // 16 x 9 = 144 CTAs ~ one full wave on 148 SMs
#define KT      64         // K per A tile (tile granularity in g_xA)
#define BN      128        // N tile per CTA
#define NTILES  (KDIM / KT)   // 768 A tiles
#define NCHUNK  (NTILES / 2)  // 384 double-tile chunks (K=128 per chunk)

// ---------------- scratch (device globals; no allocation allowed) ----------
__device__ __align__(16) __half g_xA[NTILES * 128 * 64];          // 12.6 MB
__device__ __align__(16) float g_part[KSPLIT * BATCH * NDIM];     // 9.4 MB
__device__ float g_W12[NDIM * 2];
__device__ float g_ob[2];

// ================= PTX helpers ===============================================
__device__ __forceinline__ uint32_t smem_u32(const void* p) {
    uint32_t a;
    asm("{ .reg .u64 t; cvta.to.shared.u64 t, %1; cvt.u32.u64 %0, t; }" : "=r"(a) : "l"(p));
    return a;
}
__device__ __forceinline__ void cp_async16(uint32_t dst, const void* src) {
    asm volatile("cp.async.cg.shared.global [%0], [%1], 16;" :: "r"(dst), "l"(src) : "memory");
}
#define CP_COMMIT() asm volatile("cp.async.commit_group;" ::: "memory")
#define CP_WAIT0()  asm volatile("cp.async.wait_group 0;" ::: "memory")

// PDL (sm_90+ griddepcontrol — legal on compute_103, unlike tcgen05)
#define GDC_WAIT()   asm volatile("griddepcontrol.wait;" ::: "memory")
#define GDC_LAUNCH() asm volatile("griddepcontrol.launch_dependents;")

__device__ __forceinline__ void ldsm4(uint32_t* r, uint32_t addr) {
    asm volatile("ldmatrix.sync.aligned.m8n8.x4.shared.b16 {%0,%1,%2,%3}, [%4];"
        : "=r"(r[0]), "=r"(r[1]), "=r"(r[2]), "=r"(r[3]) : "r"(addr));
}
__device__ __forceinline__ void ldsm4t(uint32_t* r, uint32_t addr) {
    asm volatile("ldmatrix.sync.aligned.m8n8.x4.trans.shared.b16 {%0,%1,%2,%3}, [%4];"
        : "=r"(r[0]), "=r"(r[1]), "=r"(r[2]), "=r"(r[3]) : "r"(addr));
}
__device__ __forceinline__ void mma_fp16(float* d, const uint32_t* a, const uint32_t* b) {
    asm volatile("mma.sync.aligned.m16n8k16.row.col.f32.f16.f16.f32 "
        "{%0,%1,%2,%3}, {%4,%5,%6,%7}, {%8,%9}, {%0,%1,%2,%3};"
        : "+f"(d[0]), "+f"(d[1]), "+f"(d[2]), "+f"(d[3])
        : "r"(a[0]), "r"(a[1]), "r"(a[2]), "r"(a[3]), "r"(b[0]), "r"(b[1]));
}
__device__ __forceinline__ uint32_t hfpair(float a, float b) {
    __half2 h = __floats2half2_rn(a, b);
    return *reinterpret_cast<uint32_t*>(&h);
}

// ---------------- kernel 1: merged prep (convA MLP=16 + warp-per-row W12) ---
__global__ void __launch_bounds__(256) k_prep(
    const float* __restrict__ x,
    const float* __restrict__ li1_w, const float* __restrict__ li1_b,
    const float* __restrict__ li2_w, const float* __restrict__ li2_b)
{
    int bx = blockIdx.x;
    if (bx < 384) {
        int m  = bx & 127;
        int yb = bx >> 7;                       // 0..2
        const float* xp = x + (size_t)m * KDIM;
        char* dst = reinterpret_cast<char*>(g_xA);
        uint32_t mask = ((uint32_t)m & 7) << 4;

        int i0a = (yb * 256 + threadIdx.x) * 4;
        int i0b = i0a + 3072;
        float4 va[8], vb[8];
#pragma unroll
        for (int j = 0; j < 8; j++)
            va[j] = *reinterpret_cast<const float4*>(xp + j * 6144 + i0a);
#pragma unroll
        for (int j = 0; j < 8; j++)
            vb[j] = *reinterpret_cast<const float4*>(xp + j * 6144 + i0b);

#pragma unroll
        for (int g = 0; g < 2; g++) {
            const float* vf = reinterpret_cast<const float*>(g == 0 ? va : vb);
            int i0 = g == 0 ? i0a : i0b;
            uint32_t base = (uint32_t)(i0 >> 3) * 16384 + (uint32_t)m * 128;
#pragma unroll
            for (int e = 0; e < 4; e++) {
                int i = i0 + e;
                uint32_t h0 = hfpair(vf[0 * 4 + e], vf[1 * 4 + e]);
                uint32_t h1 = hfpair(vf[2 * 4 + e], vf[3 * 4 + e]);
                uint32_t h2 = hfpair(vf[4 * 4 + e], vf[5 * 4 + e]);
                uint32_t h3 = hfpair(vf[6 * 4 + e], vf[7 * 4 + e]);
                uint32_t off = base + ((((uint32_t)i & 7) << 4) ^ mask);
                *reinterpret_cast<uint4*>(dst + off) = make_uint4(h0, h1, h2, h3);
            }
        }
    } else {
        __shared__ float s2[2000];
        int t = threadIdx.x;
        for (int p = t; p < 2000; p += 256) s2[p] = li2_w[p];
        __syncthreads();
        int wq = t >> 5, l = t & 31;
        int j = (bx - 384) * 8 + wq;            // 0..2056
        if (j <= NDIM) {
            const float* row = (j < NDIM) ? (li1_w + (size_t)j * 1000) : li1_b;
            float a0 = 0.f, a1 = 0.f;
            for (int p = l; p < 1000; p += 32) {
                float wv = row[p];
                a0 += wv * s2[2 * p];
                a1 += wv * s2[2 * p + 1];
            }
#pragma unroll
            for (int off = 16; off > 0; off >>= 1) {
                a0 += __shfl_down_sync(0xffffffffu, a0, off);
                a1 += __shfl_down_sync(0xffffffffu, a1, off);
            }
            if (l == 0) {
                if (j < NDIM) { g_W12[2 * j] = a0; g_W12[2 * j + 1] = a1; }
                else          { g_ob[0] = a0 + li2_b[0]; g_ob[1] = a1 + li2_b[1]; }
            }
        }
    }
    GDC_LAUNCH();   // writes done -> let k_gemm's post-wait section proceed
}

// ---------------- kernel 2: fp16 split-K GEMM, K=128 per stage, PDL ---------
#define BUF_BYTES  65536
#define SMEM_BYTES (2 * BUF_BYTES)

__global__ void __launch_bounds__(256, 1) k_gemm(const float* __restrict__ fc_w) {
    extern __shared__ __align__(1024) char smem[];
    const uint32_t sb = smem_u32(smem);
    const int t   = threadIdx.x;
    const int w   = t >> 5;
    const int l   = t & 31;
    const int wm  = w >> 2;
    const int wn  = w & 3;
    const int nbase = blockIdx.x * BN;
    const int s     = blockIdx.y;
    const int C0 = (s * NCHUNK) / KSPLIT;
    const int C1 = ((s + 1) * NCHUNK) / KSPLIT;

    uint32_t aoff[4], amask[4];
#pragma unroll
    for (int mt = 0; mt < 4; mt++) {
        int row = wm * 64 + mt * 16 + (l & 15);
        aoff[mt]  = (uint32_t)row * 128;
        amask[mt] = ((uint32_t)row & 7) << 4;
    }
    const uint32_t lcol = ((uint32_t)l >> 4) << 4;

    const uint32_t blane = (uint32_t)((l & 7) + ((l >> 3) & 1) * 8) * 256
                         + (((uint32_t)(64 * wn + 16 * (l >> 4))) ^ (((uint32_t)l & 7) << 4));
    const uint32_t bsts = (uint32_t)w * 256 + (((uint32_t)(8 * l)) ^ ((uint32_t)w << 4));

    float acc[64];
#pragma unroll
    for (int q = 0; q < 64; q++) acc[q] = 0.f;

    float4 bst[16];

    // ---- PRE-WAIT prologue: B(C0) from fc_w (independent of prep) ----
    {
        int kb = C0 * 128;
        const float* bp = fc_w + (size_t)(kb + w) * NDIM + nbase + 4 * l;
#pragma unroll
        for (int i = 0; i < 16; i++)
            bst[i] = *reinterpret_cast<const float4*>(bp + (size_t)(8 * i) * NDIM);
#pragma unroll
        for (int i = 0; i < 16; i++)
            *reinterpret_cast<uint2*>(smem + 32768 + bsts + i * 2048) =
                make_uint2(hfpair(bst[i].x, bst[i].y), hfpair(bst[i].z, bst[i].w));
    }

    // ---- wait for prep (g_xA ready), then A(C0) cp.async ----
    GDC_WAIT();
    {
        const char* srch = reinterpret_cast<const char*>(g_xA) + (size_t)C0 * 32768 + t * 16;
#pragma unroll
        for (int i = 0; i < 8; i++)
            cp_async16(sb + t * 16 + i * 4096, srch + i * 4096);
        CP_COMMIT();
    }

    // ---- main loop over this split's double-tile chunks ----
    for (int C = C0; C < C1; ++C) {
        const int cl = C - C0;
        const uint32_t cbuf = sb + (uint32_t)(cl & 1) * BUF_BYTES;
        const uint32_t nbuf = sb + (uint32_t)((cl + 1) & 1) * BUF_BYTES;

        if (C + 1 < C1) {
            int kb = (C + 1) * 128;
            const float* bp = fc_w + (size_t)(kb + w) * NDIM + nbase + 4 * l;
#pragma unroll
            for (int i = 0; i < 16; i++)
                bst[i] = *reinterpret_cast<const float4*>(bp + (size_t)(8 * i) * NDIM);
        }

        CP_WAIT0();
        __syncthreads();

        if (C + 1 < C1) {
            const char* srch = reinterpret_cast<const char*>(g_xA) + (size_t)(C + 1) * 32768 + t * 16;
#pragma unroll
            for (int i = 0; i < 8; i++)
                cp_async16(nbuf + t * 16 + i * 4096, srch + i * 4096);
            CP_COMMIT();
        }

        const uint32_t Bh = cbuf + 32768;
#pragma unroll
        for (int ks = 0; ks < 8; ks++) {
            const uint32_t Ah = cbuf + ((ks & 4) ? 16384u : 0u);
            const uint32_t kcol = (uint32_t)((ks & 3) * 32) + lcol;
            uint32_t ah[4][4], bh[4][2];
#pragma unroll
            for (int mt = 0; mt < 4; mt++)
                ldsm4(ah[mt], Ah + aoff[mt] + (kcol ^ amask[mt]));
            {
                const uint32_t bb = Bh + (uint32_t)ks * 4096 + blane;
                uint32_t r[4];
                ldsm4t(r, bb);
                bh[0][0] = r[0]; bh[0][1] = r[1];
                bh[1][0] = r[2]; bh[1][1] = r[3];
                ldsm4t(r, bb ^ 32u);
                bh[2][0] = r[0]; bh[2][1] = r[1];
                bh[3][0] = r[2]; bh[3][1] = r[3];
            }
#pragma unroll
            for (int mt = 0; mt < 4; mt++)
#pragma unroll
                for (int nt = 0; nt < 4; nt++)
                    mma_fp16(acc + (mt * 4 + nt) * 4, ah[mt], bh[nt]);
        }

        if (C + 1 < C1) {
            char* bp = smem + (nbuf - sb);
#pragma unroll
            for (int i = 0; i < 16; i++)
                *reinterpret_cast<uint2*>(bp + 32768 + bsts + i * 2048) =
                    make_uint2(hfpair(bst[i].x, bst[i].y), hfpair(bst[i].z, bst[i].w));
        }
    }

    // ---- epilogue: write partials, then trigger fuse ----
    float* op = g_part + (size_t)s * BATCH * NDIM;
#pragma unroll
    for (int mt = 0; mt < 4; mt++) {
        int m = wm * 64 + mt * 16 + (l >> 2);
#pragma unroll
        for (int nt = 0; nt < 4; nt++) {
            int n = nbase + wn * 32 + nt * 8 + (l & 3) * 2;
            const float* d = acc + (mt * 4 + nt) * 4;
            *reinterpret_cast<float2*>(op + (size_t)m * NDIM + n)       = make_float2(d[0], d[1]);
            *reinterpret_cast<float2*>(op + (size_t)(m + 8) * NDIM + n) = make_float2(d[2], d[3]);
        }
    }
    GDC_LAUNCH();
}

// ---------------- kernel 3: fused per-batch pipeline, 512 thr, PDL ----------
__global__ void __launch_bounds__(512) k_fuse(
    const float* __restrict__ fc_b,
    const float* __restrict__ ln1_s, const float* __restrict__ ln1_b,
    const float* __restrict__ ln2_s, const float* __restrict__ ln2_b,
    const float* __restrict__ Wq, const float* __restrict__ Wk, const float* __restrict__ Wv,
    const float* __restrict__ Wg, const float* __restrict__ Wo,
    const float* __restrict__ gn_w, const float* __restrict__ gn_b,
    const float* __restrict__ w1, const float* __restrict__ b1,
    const float* __restrict__ w2, const float* __restrict__ b2,
    float* __restrict__ out)
{
    int b   = blockIdx.x;
    int tid = threadIdx.x;
    int l   = tid & 255;
    int hg  = tid >> 8;

    __shared__ float4 sK4[2][256];
    __shared__ float4 sV4[2][256][2];
    __shared__ float  sGP[2][256];
    __shared__ float  syc[256][17];
    __shared__ float  sRed[8][2];
    __shared__ float  swq[64], swk[64], swv[128], swg[128], swo[128];
    __shared__ float  sgnw[16], sgnb[16], sw1[64], sw2[64];
    __shared__ float  sb1[8], sb2[8], sl1s[8], sl1b[8], sl2s[8], sl2b[8];

    // ---- PRE-WAIT: weights (harness inputs) + per-position constants ----
    if (tid < 64)  { swq[tid] = Wq[tid]; swk[tid] = Wk[tid]; sw1[tid] = w1[tid]; sw2[tid] = w2[tid]; }
    else if (tid < 192) { int u = tid - 64; swv[u] = Wv[u]; swg[u] = Wg[u]; swo[u] = Wo[u]; }
    else if (tid < 208) { int u = tid - 192; sgnw[u] = gn_w[u]; sgnb[u] = gn_b[u]; }
    else if (tid < 216) { int u = tid - 208; sb1[u] = b1[u]; sb2[u] = b2[u];
                          sl1s[u] = ln1_s[u]; sl1b[u] = ln1_b[u];
                          sl2s[u] = ln2_s[u]; sl2b[u] = ln2_b[u]; }

    float fl = (float)l;
    float c0 = cosf(fl), s0 = sinf(fl);
    float c1 = cosf(fl * 0.01f), s1 = sinf(fl * 0.01f);
    float e0 = exp2f(fl * (-1.807354922f / 512.0f));
    float e1 = exp2f(fl * (-0.637429921f / 512.0f));
    float ie0 = 1.0f / e0, ie1 = 1.0f / e1;
    const float l2g[2] = { -0.04580368961f, -0.00281970977f };

    float4 hb0 = *reinterpret_cast<const float4*>(fc_b + l * 8);
    float4 hb1 = *reinterpret_cast<const float4*>(fc_b + l * 8 + 4);

    // ---- wait for GEMM partials ----
    GDC_WAIT();

    float X[8];
    {
        X[0] = hb0.x; X[1] = hb0.y; X[2] = hb0.z; X[3] = hb0.w;
        X[4] = hb1.x; X[5] = hb1.y; X[6] = hb1.z; X[7] = hb1.w;
#pragma unroll
        for (int s = 0; s < KSPLIT; s++) {
            const float* pp = g_part + (size_t)s * (BATCH * NDIM) + b * NDIM + l * 8;
            float4 p0 = *reinterpret_cast<const float4*>(pp);
            float4 p1 = *reinterpret_cast<const float4*>(pp + 4);
            X[0] += p0.x; X[1] += p0.y; X[2] += p0.z; X[3] += p0.w;
            X[4] += p1.x; X[5] += p1.y; X[6] += p1.z; X[7] += p1.w;
        }
    }
    __syncthreads();

    float Xn[8];
    {
        float mu = 0.f;
#pragma unroll
        for (int d = 0; d < 8; d++) mu += X[d];
        mu *= 0.125f;
        float var = 0.f;
#pragma unroll
        for (int d = 0; d < 8; d++) { float tt = X[d] - mu; var += tt * tt; }
        var *= 0.125f;
        float inv = rsqrtf(var + 1e-5f);
#pragma unroll
        for (int d = 0; d < 8; d++) Xn[d] = (X[d] - mu) * inv * sl1s[d] + sl1b[d];
    }

    {
        const float* wq = swq + hg * 32;
        const float* wk = swk + hg * 32;
        const float* wv = swv + hg * 64;

        float q0 = 0, q1 = 0, q2 = 0, q3 = 0, k0 = 0, k1 = 0, k2 = 0, k3 = 0;
#pragma unroll
        for (int d = 0; d < 8; d++) {
            float xv = Xn[d];
            q0 += xv * wq[d * 4 + 0]; q1 += xv * wq[d * 4 + 1];
            q2 += xv * wq[d * 4 + 2]; q3 += xv * wq[d * 4 + 3];
            k0 += xv * wk[d * 4 + 0]; k1 += xv * wk[d * 4 + 1];
            k2 += xv * wk[d * 4 + 2]; k3 += xv * wk[d * 4 + 3];
        }
        float Q0 = (q0 * c0 - q1 * s0) * e0;
        float Q1 = (q1 * c0 + q0 * s0) * e0;
        float Q2 = (q2 * c1 - q3 * s1) * e1;
        float Q3 = (q3 * c1 + q2 * s1) * e1;
        float K0 = (k0 * c0 - k1 * s0) * ie0;
        float K1 = (k1 * c0 + k0 * s0) * ie0;
        float K2 = (k2 * c1 - k3 * s1) * ie1;
        float K3 = (k3 * c1 + k2 * s1) * ie1;

        float V[8];
#pragma unroll
        for (int f = 0; f < 8; f++) {
            float a = 0.f;
#pragma unroll
            for (int d = 0; d < 8; d++) a += Xn[d] * wv[d * 8 + f];
            V[f] = a;
        }

        sK4[hg][l] = make_float4(K0, K1, K2, K3);
        sV4[hg][l][0] = make_float4(V[0], V[1], V[2], V[3]);
        sV4[hg][l][1] = make_float4(V[4], V[5], V[6], V[7]);
        sGP[hg][l] = exp2f(-fl * l2g[hg]);
        float gpn = exp2f(fl * l2g[hg]);
        __syncthreads();

        float a0 = 0, a1 = 0, a2 = 0, a3 = 0, a4 = 0, a5 = 0, a6 = 0, a7 = 0;
        const float4* kp = sK4[hg];
        const float4 (*vp)[2] = sV4[hg];
        const float* gp = sGP[hg];
        for (int m = 0; m <= l; ++m) {
            float4 kv = kp[m];
            float wgt = (Q0 * kv.x + Q1 * kv.y + Q2 * kv.z + Q3 * kv.w) * gpn * gp[m];
            float4 v0 = vp[m][0], v1 = vp[m][1];
            a0 += wgt * v0.x; a1 += wgt * v0.y; a2 += wgt * v0.z; a3 += wgt * v0.w;
            a4 += wgt * v1.x; a5 += wgt * v1.y; a6 += wgt * v1.z; a7 += wgt * v1.w;
        }
        float* yr = syc[l] + hg * 8;
        yr[0] = a0; yr[1] = a1; yr[2] = a2; yr[3] = a3;
        yr[4] = a4; yr[5] = a5; yr[6] = a6; yr[7] = a7;
    }
    __syncthreads();

    if (hg == 0) {
        float yc[16];
#pragma unroll
        for (int j = 0; j < 16; j++) yc[j] = syc[l][j];

        float gn[16];
#pragma unroll
        for (int g = 0; g < 2; g++) {
            float mu = 0.f;
#pragma unroll
            for (int jj = 0; jj < 8; jj++) mu += yc[g * 8 + jj];
            mu *= 0.125f;
            float var = 0.f;
#pragma unroll
            for (int jj = 0; jj < 8; jj++) { float tt = yc[g * 8 + jj] - mu; var += tt * tt; }
            var *= 0.125f;
            float inv = rsqrtf(var + 1e-5f);
#pragma unroll
            for (int jj = 0; jj < 8; jj++)
                gn[g * 8 + jj] = (yc[g * 8 + jj] - mu) * inv * sgnw[g * 8 + jj] + sgnb[g * 8 + jj];
        }

        float msr[8] = {0, 0, 0, 0, 0, 0, 0, 0};
#pragma unroll
        for (int j = 0; j < 16; j++) {
            float gt = 0.f;
#pragma unroll
            for (int d = 0; d < 8; d++) gt += Xn[d] * swg[d * 16 + j];
            gt = gt / (1.0f + expf(-gt));
            float val = gt * gn[j];
#pragma unroll
            for (int d = 0; d < 8; d++) msr[d] += val * swo[j * 8 + d];
        }

        float Y[8], Z[8];
#pragma unroll
        for (int d = 0; d < 8; d++) Y[d] = msr[d] + X[d];
        {
            float mu = 0.f;
#pragma unroll
            for (int d = 0; d < 8; d++) mu += Y[d];
            mu *= 0.125f;
            float var = 0.f;
#pragma unroll
            for (int d = 0; d < 8; d++) { float tt = Y[d] - mu; var += tt * tt; }
            var *= 0.125f;
            float inv = rsqrtf(var + 1e-5f);
#pragma unroll
            for (int d = 0; d < 8; d++) Z[d] = (Y[d] - mu) * inv * sl2s[d] + sl2b[d];
        }

        float f1[8];
#pragma unroll
        for (int e = 0; e < 8; e++) {
            float a = sb1[e];
#pragma unroll
            for (int d = 0; d < 8; d++) a += Z[d] * sw1[d * 8 + e];
            f1[e] = 0.5f * a * (1.0f + erff(a * 0.70710678118654752f));
        }

        float p0 = 0.f, p1 = 0.f;
#pragma unroll
        for (int d = 0; d < 8; d++) {
            float a = sb2[d];
#pragma unroll
            for (int e = 0; e < 8; e++) a += f1[e] * sw2[e * 8 + d];
            float xf = a + Y[d];
            p0 += xf * g_W12[(l * 8 + d) * 2];
            p1 += xf * g_W12[(l * 8 + d) * 2 + 1];
        }

#pragma unroll
        for (int off = 16; off > 0; off >>= 1) {
            p0 += __shfl_down_sync(0xffffffffu, p0, off);
            p1 += __shfl_down_sync(0xffffffffu, p1, off);
        }
        if ((l & 31) == 0) { sRed[l >> 5][0] = p0; sRed[l >> 5][1] = p1; }
    }
    __syncthreads();
    if (tid == 0) {
        float o0 = g_ob[0], o1 = g_ob[1];
#pragma unroll
        for (int ww = 0; ww < 8; ww++) { o0 += sRed[ww][0]; o1 += sRed[ww][1]; }
        out[b * 2 + 0] = o0;
        out[b * 2 + 1] = o1;
    }
}

// ---------------- launch (PDL: programmatic stream serialization) -----------
extern "C" void kernel_launch(void* const* d_in, const int* in_sizes, int n_in,
                              void* d_out, int out_size) {
    const float* x      = (const float*)d_in[0];
    const float* fc_w   = (const float*)d_in[1];
    const float* fc_b   = (const float*)d_in[2];
    const float* ln1_s  = (const float*)d_in[3];
    const float* ln1_b  = (const float*)d_in[4];
    const float* ln2_s  = (const float*)d_in[5];
    const float* ln2_b  = (const float*)d_in[6];
    const float* Wq     = (const float*)d_in[7];
    const float* Wk     = (const float*)d_in[8];
    const float* Wv     = (const float*)d_in[9];
    const float* Wg     = (const float*)d_in[10];
    const float* Wo     = (const float*)d_in[11];
    const float* gn_w   = (const float*)d_in[12];
    const float* gn_b   = (const float*)d_in[13];
    const float* ffn_w1 = (const float*)d_in[14];
    const float* ffn_b1 = (const float*)d_in[15];
    const float* ffn_w2 = (const float*)d_in[16];
    const float* ffn_b2 = (const float*)d_in[17];
    const float* li1_w  = (const float*)d_in[18];
    const float* li1_b  = (const float*)d_in[19];
    const float* li2_w  = (const float*)d_in[20];
    const float* li2_b  = (const float*)d_in[21];

    cudaFuncSetAttribute(k_gemm, cudaFuncAttributeMaxDynamicSharedMemorySize, SMEM_BYTES);

    // prep: normal launch
    k_prep<<<384 + 257, 256>>>(x, li1_w, li1_b, li2_w, li2_b);

    // gemm: PDL (launches while prep drains; waits on griddepcontrol.wait)
    {
        cudaLaunchAttribute attr[1];
        attr[0].id = cudaLaunchAttributeProgrammaticStreamSerialization;
        attr[0].val.programmaticStreamSerializationAllowed = 1;
        cudaLaunchConfig_t cfg = {};
        cfg.gridDim = dim3(NDIM / BN, KSPLIT, 1);
        cfg.blockDim = dim3(256, 1, 1);
        cfg.dynamicSmemBytes = SMEM_BYTES;
        cfg.stream = 0;
        cfg.attrs = attr;
        cfg.numAttrs = 1;
        cudaLaunchKernelEx(&cfg, k_gemm, fc_w);
    }

    // fuse: PDL
    {
        cudaLaunchAttribute attr[1];
        attr[0].id = cudaLaunchAttributeProgrammaticStreamSerialization;
        attr[0].val.programmaticStreamSerializationAllowed = 1;
        cudaLaunchConfig_t cfg = {};
        cfg.gridDim = dim3(BATCH, 1, 1);
        cfg.blockDim = dim3(512, 1, 1);
        cfg.dynamicSmemBytes = 0;
        cfg.stream = 0;
        cfg.attrs = attr;
        cfg.numAttrs = 1;
        cudaLaunchKernelEx(&cfg, k_fuse, fc_b, ln1_s, ln1_b, ln2_s, ln2_b,
                           Wq, Wk, Wv, Wg, Wo, gn_w, gn_b,
                           ffn_w1, ffn_b1, ffn_w2, ffn_b2,
                           (float*)d_out);
    }
}